// round 7
// baseline (speedup 1.0000x reference)
#include <cuda_runtime.h>
#include <cuda_bf16.h>
#include <math.h>
#include <stdint.h>

// ---------------- problem constants ----------------
#define NB   8
#define NS   256
#define NP   16
#define ND   512
#define NH   8
#define HD   64
#define NL   6
#define NF   2048
#define NV   65536
#define NTOK (NB * NS)   // 2048

// ---------------- scratch (device globals; no allocation) ----------------
__device__ float g_x  [NTOK * ND];          // residual stream (fp32)
__device__ float g_qkv[NTOK * 3 * ND];      // qkv projection (fp32)

// split-bf16 tile buffers (hi|lo 2KB blocks of 64 rows x 16 k, swizzled)
__device__ uint8_t s_xn [NTOK * ND * 4];
__device__ uint8_t s_o  [NTOK * ND * 4];
__device__ uint8_t s_h  [NTOK * NF * 4];
__device__ uint8_t s_xf [NTOK * ND * 4];
__device__ uint8_t s_win[NL * 3 * ND * ND * 4];
__device__ uint8_t s_wo [NL * ND * ND * 4];
__device__ uint8_t s_w1 [NL * NF * ND * 4];
__device__ uint8_t s_w2 [(size_t)NL * ND * NF * 4];
__device__ uint8_t s_wv [(size_t)NV * ND * 4];

__device__ __forceinline__ uint32_t smem_u32(const void* p) {
    uint32_t a;
    asm("{ .reg .u64 t; cvta.to.shared.u64 t, %1; cvt.u32.u64 %0, t; }" : "=r"(a) : "l"(p));
    return a;
}

// ---------------- split helpers ----------------
__device__ __forceinline__ void split_pack(float a, float b, unsigned& hi, unsigned& lo) {
    __nv_bfloat16 ha = __float2bfloat16_rn(a);
    __nv_bfloat16 hb = __float2bfloat16_rn(b);
    float ra = a - __bfloat162float(ha);
    float rb = b - __bfloat162float(hb);
    __nv_bfloat162 h2 = __halves2bfloat162(ha, hb);
    __nv_bfloat162 l2 = __floats2bfloat162_rn(ra, rb);
    hi = *(unsigned*)&h2;
    lo = *(unsigned*)&l2;
}
__device__ __forceinline__ void pack8(float4 v0, float4 v1, uint4& hi, uint4& lo) {
    split_pack(v0.x, v0.y, hi.x, lo.x);
    split_pack(v0.z, v0.w, hi.y, lo.y);
    split_pack(v1.x, v1.y, hi.z, lo.z);
    split_pack(v1.z, v1.w, hi.w, lo.w);
}
__device__ __forceinline__ void store_split2(uint8_t* base, int K, int row, int col,
                                             float a, float b) {
    unsigned hi, lo;
    split_pack(a, b, hi, lo);
    size_t blk = (size_t)(row >> 6) * (K >> 4) + (col >> 4);
    uint32_t off = (uint32_t)((row & 63) * 32 +
                   ((((col >> 3) & 1) ^ ((row >> 2) & 1)) << 4) + (col & 7) * 2);
    *(unsigned*)(base + blk * 4096 + off) = hi;
    *(unsigned*)(base + blk * 4096 + 2048 + off) = lo;
}

// ---------------- weight conversion (fp32 [R,K] -> split tiles) ----------------
__global__ void convert_w(const float* __restrict__ src, uint8_t* __restrict__ dst,
                          int K, int nChunks) {
    int ct = blockIdx.x * 256 + threadIdx.x;
    if (ct >= nChunks) return;
    int within = ct & 127;
    int blk = ct >> 7;
    int r = within >> 1, kc = within & 1;
    int stages = K >> 4;
    int rt = blk / stages, s = blk - rt * stages;
    const float* p = src + (size_t)(rt * 64 + r) * K + s * 16 + kc * 8;
    float4 v0 = *(const float4*)p, v1 = *(const float4*)(p + 4);
    uint4 hi, lo;
    pack8(v0, v1, hi, lo);
    uint32_t off = (uint32_t)(r * 32 + ((kc ^ ((r >> 2) & 1)) << 4));
    *(uint4*)(dst + (size_t)blk * 4096 + off) = hi;
    *(uint4*)(dst + (size_t)blk * 4096 + 2048 + off) = lo;
}

__global__ void convert_x_kernel(const float* __restrict__ src, uint8_t* __restrict__ dst) {
    const int row = blockIdx.x;
    const int d = threadIdx.x * 2;
    float2 v = ((const float2*)(src + (size_t)row * ND))[threadIdx.x];
    store_split2(dst, ND, row, d, v.x, v.y);
}

// ---------------- tokenize + embed ----------------
__global__ void tokenize_embed_kernel(const float* __restrict__ patches,
                                      const float* __restrict__ masked_token,
                                      const float* __restrict__ partial_params,
                                      const float* __restrict__ emb_w,
                                      const float* __restrict__ emb_b) {
    const int tok = blockIdx.x;
    const int tid = threadIdx.x;   // 128 threads
    __shared__ float proc[NP];

    if (tid == 0) {
        const float* f = patches + (size_t)tok * NP;
        bool anyMask = false, anyBin = false;
        int firstBin = -1;
        float fp[NP];
        #pragma unroll
        for (int p = 0; p < NP; p++) {
            float v = f[p];
            fp[p] = v;
            bool m = fabsf(v - 0.5f) < 0.1f;
            if (m) anyMask = true;
            else { anyBin = true; if (firstBin < 0) firstBin = p; }
        }
        if (!anyBin) {
            #pragma unroll
            for (int p = 0; p < NP; p++) proc[p] = masked_token[p];
        } else if (anyMask) {
            int ptok = firstBin * 2 + (int)rintf(fp[firstBin]);
            const float* pp = partial_params + ptok * NP;
            #pragma unroll
            for (int p = 0; p < NP; p++) proc[p] = pp[p];
        } else {
            #pragma unroll
            for (int p = 0; p < NP; p++) proc[p] = fp[p];
        }
    }
    __syncthreads();

    for (int d = tid; d < ND; d += blockDim.x) {
        const float* w = emb_w + d * NP;
        float s = emb_b[d];
        #pragma unroll
        for (int p = 0; p < NP; p++) s += proc[p] * w[p];
        g_x[(size_t)tok * ND + d] = s;
    }
}

// ---------------- layernorm (fp32 in -> split-bf16 tile out) ----------------
__global__ void ln_kernel(const float* __restrict__ in, uint8_t* __restrict__ out,
                          const float* __restrict__ gamma, const float* __restrict__ beta) {
    const int tok = blockIdx.x;
    const int tid = threadIdx.x;   // 256
    const float2 v = ((const float2*)(in + (size_t)tok * ND))[tid];

    float s  = v.x + v.y;
    float sq = v.x * v.x + v.y * v.y;
    #pragma unroll
    for (int off = 16; off; off >>= 1) {
        s  += __shfl_xor_sync(0xffffffffu, s,  off);
        sq += __shfl_xor_sync(0xffffffffu, sq, off);
    }
    __shared__ float rs[8], rq[8], stats[2];
    if ((tid & 31) == 0) { rs[tid >> 5] = s; rq[tid >> 5] = sq; }
    __syncthreads();
    if (tid == 0) {
        float S = 0.f, Q = 0.f;
        #pragma unroll
        for (int i = 0; i < 8; i++) { S += rs[i]; Q += rq[i]; }
        float mean = S * (1.0f / ND);
        float var  = Q * (1.0f / ND) - mean * mean;
        stats[0] = mean;
        stats[1] = rsqrtf(var + 1e-5f);
    }
    __syncthreads();
    const float mean = stats[0], inv = stats[1];
    float2 g2 = ((const float2*)gamma)[tid];
    float2 b2 = ((const float2*)beta)[tid];
    float ox = (v.x - mean) * inv * g2.x + b2.x;
    float oy = (v.y - mean) * inv * g2.y + b2.y;
    store_split2(out, ND, tok, tid * 2, ox, oy);
}

// ---------------- fused attention (smem K/V, split output) ----------------
#define ATTN_SMEM (192 * 1024)

__global__ __launch_bounds__(256) void attn_kernel(const float* __restrict__ rel) {
    extern __shared__ float sm[];
    float* Ks = sm;            // [256][64] rotated rows
    float* Vs = sm + 16384;    // [256][64]
    float* Qs = sm + 32768;    // [128][64]
    float* Wb = sm + 40960;    // [8 warps][256][4]

    const int idx = blockIdx.x;
    const int qc = idx & 1;
    const int h  = (idx >> 1) & (NH - 1);
    const int b  = idx >> 4;
    const int tid = threadIdx.x, wid = tid >> 5, L = tid & 31;

    const size_t base = (size_t)(b * NS) * (3 * ND) + h * HD;

    {
        const int dc = (tid & 15) * 4;
        int t = tid >> 4;
        #pragma unroll 4
        for (int pass = 0; pass < 16; pass++, t += 16) {
            const float* kR = g_qkv + base + ND + (size_t)t * (3 * ND);
            float4 kv = *(const float4*)(kR + dc);
            const int p = (dc + 4 * (t & 15)) & 63;
            *(float4*)(Ks + t * 64 + p) = kv;
            const float* vR = g_qkv + base + 2 * ND + (size_t)t * (3 * ND);
            *(float4*)(Vs + t * 64 + dc) = *(const float4*)(vR + dc);
        }
        int q = tid >> 4;
        #pragma unroll 4
        for (int pass = 0; pass < 8; pass++, q += 16) {
            const float* qR = g_qkv + base + (size_t)(qc * 128 + q) * (3 * ND);
            *(float4*)(Qs + q * 64 + dc) = *(const float4*)(qR + dc);
        }
    }
    __syncthreads();

    float* wb = Wb + wid * 1024;
    const int rot = 4 * (L & 15);

    for (int g4 = 0; g4 < 4; g4++) {
        const int q0 = wid * 16 + g4 * 4;
        const int sRow = qc * 128 + q0;

        float sc[4][8];
        #pragma unroll
        for (int qi = 0; qi < 4; qi++)
            #pragma unroll
            for (int j = 0; j < 8; j++) sc[qi][j] = 0.f;

        #pragma unroll
        for (int dd = 0; dd < 16; dd++) {
            const int d = dd * 4;
            float4 qv[4];
            #pragma unroll
            for (int qi = 0; qi < 4; qi++)
                qv[qi] = *(const float4*)(Qs + (q0 + qi) * 64 + d);
            const int p = (d + rot) & 63;
            #pragma unroll
            for (int j = 0; j < 8; j++) {
                float4 k4 = *(const float4*)(Ks + (L + 32 * j) * 64 + p);
                #pragma unroll
                for (int qi = 0; qi < 4; qi++)
                    sc[qi][j] += qv[qi].x * k4.x + qv[qi].y * k4.y +
                                 qv[qi].z * k4.z + qv[qi].w * k4.w;
            }
        }

        #pragma unroll
        for (int qi = 0; qi < 4; qi++) {
            const float* rrow = rel + (size_t)(sRow + qi) * NS;
            float m = -1e30f;
            #pragma unroll
            for (int j = 0; j < 8; j++) {
                float v = sc[qi][j] * 0.125f + rrow[L + 32 * j];
                sc[qi][j] = v;
                m = fmaxf(m, v);
            }
            #pragma unroll
            for (int off = 16; off; off >>= 1)
                m = fmaxf(m, __shfl_xor_sync(0xffffffffu, m, off));
            float ssum = 0.f;
            #pragma unroll
            for (int j = 0; j < 8; j++) { sc[qi][j] = expf(sc[qi][j] - m); ssum += sc[qi][j]; }
            #pragma unroll
            for (int off = 16; off; off >>= 1)
                ssum += __shfl_xor_sync(0xffffffffu, ssum, off);
            const float inv = 1.0f / ssum;
            #pragma unroll
            for (int j = 0; j < 8; j++) sc[qi][j] *= inv;
        }

        #pragma unroll
        for (int j = 0; j < 8; j++)
            *(float4*)(wb + (L + 32 * j) * 4) =
                make_float4(sc[0][j], sc[1][j], sc[2][j], sc[3][j]);
        __syncwarp();

        float2 acc[4];
        #pragma unroll
        for (int qi = 0; qi < 4; qi++) acc[qi] = make_float2(0.f, 0.f);
        #pragma unroll 4
        for (int t = 0; t < NS; t++) {
            float2 v2 = *(const float2*)(Vs + t * 64 + 2 * L);
            float4 w4 = *(const float4*)(wb + t * 4);
            acc[0].x += w4.x * v2.x; acc[0].y += w4.x * v2.y;
            acc[1].x += w4.y * v2.x; acc[1].y += w4.y * v2.y;
            acc[2].x += w4.z * v2.x; acc[2].y += w4.z * v2.y;
            acc[3].x += w4.w * v2.x; acc[3].y += w4.w * v2.y;
        }
        #pragma unroll
        for (int qi = 0; qi < 4; qi++)
            store_split2(s_o, ND, b * NS + sRow + qi, h * HD + 2 * L,
                         acc[qi].x, acc[qi].y);
        __syncwarp();
    }
}

// ---------------- split-bf16 GEMM: cp.async pipeline + ldmatrix + mma ----------
// Tile (TM x TN), warp tile (TM/2 x TN/4). 3-term split, fp32 accum.
// EPI: 0 = fp32+bias, 1 = fp32+bias+res, 2 = split-gelu output.

#define MMA_BF16(d, a0,a1,a2,a3, b0,b1)                                         \
    asm volatile("mma.sync.aligned.m16n8k16.row.col.f32.bf16.bf16.f32 "         \
                 "{%0,%1,%2,%3}, {%4,%5,%6,%7}, {%8,%9}, {%0,%1,%2,%3};"        \
                 : "+f"(d[0]), "+f"(d[1]), "+f"(d[2]), "+f"(d[3])               \
                 : "r"(a0), "r"(a1), "r"(a2), "r"(a3), "r"(b0), "r"(b1))

#define LDSM4(r, addr)                                                          \
    asm volatile("ldmatrix.sync.aligned.m8n8.x4.shared.b16 {%0,%1,%2,%3}, [%4];"\
                 : "=r"((r)[0]), "=r"((r)[1]), "=r"((r)[2]), "=r"((r)[3])       \
                 : "r"(addr))

#define CP16(dst, src)                                                          \
    asm volatile("cp.async.cg.shared.global [%0], [%1], 16;" :: "r"(dst), "l"(src))
#define CP_COMMIT() asm volatile("cp.async.commit_group;" ::: "memory")
#define CP_WAIT2()  asm volatile("cp.async.wait_group 2;" ::: "memory")

__device__ __forceinline__ uint32_t tile_off(int m, int kc) {
    return (uint32_t)((m >> 6) * 4096 + (m & 63) * 32 +
                      ((kc ^ ((m >> 2) & 1)) << 4));
}

template <int TM, int TN, int EPI>
__global__ __launch_bounds__(256, 1)
void gemm_split(const uint8_t* __restrict__ A, const uint8_t* __restrict__ W,
                const float* __restrict__ bias, const float* __restrict__ res,
                void* __restrict__ Cout, int M, int N, int K) {
    constexpr int ABLK  = TM / 64;
    constexpr int WBLK  = TN / 64;
    constexpr int NREG  = ABLK + WBLK;
    constexpr int ST    = NREG * 4096;
    constexpr int AWOFF = ABLK * 4096;
    constexpr int MF    = TM / 32;              // A 16-row frags per warp
    constexpr int NFR   = TN / 32;              // W 8-col frags per warp
    constexpr int WP    = TN / 64;              // W LDSM groups per warp
    constexpr int NSTG  = 4;

    extern __shared__ uint8_t smem[];
    const uint32_t sb = smem_u32(smem);

    const int tid = threadIdx.x;
    const int bm = blockIdx.x * TM;
    const int bn = blockIdx.y * TN;
    const int wid = tid >> 5, lane = tid & 31;
    const int g = lane >> 2, t4 = lane & 3;
    const int wm = (wid >> 2) * (TM / 2);
    const int wn = (wid & 3) * (TN / 4);

    const int S = K >> 4;

    const uint8_t* ps[NREG];
    {
        const int mt0 = blockIdx.x * ABLK;
        const int nt0 = blockIdx.y * WBLK;
        #pragma unroll
        for (int i = 0; i < ABLK; i++)
            ps[i] = A + (size_t)(mt0 + i) * S * 4096;
        #pragma unroll
        for (int i = 0; i < WBLK; i++)
            ps[ABLK + i] = W + (size_t)(nt0 + i) * S * 4096;
    }

    const int sel = lane >> 3, ri = lane & 7;
    uint32_t aOffH[MF], bOffH[WP];
    #pragma unroll
    for (int mf = 0; mf < MF; mf++) {
        const int m = wm + mf * 16 + (sel & 1) * 8 + ri;
        aOffH[mf] = tile_off(m, sel >> 1);
    }
    #pragma unroll
    for (int p = 0; p < WP; p++) {
        const int n = wn + p * 16 + (sel >> 1) * 8 + ri;
        bOffH[p] = AWOFF + tile_off(n, sel & 1);
    }

    float acc[MF][NFR][4];
    #pragma unroll
    for (int i = 0; i < MF; i++)
        #pragma unroll
        for (int j = 0; j < NFR; j++)
            #pragma unroll
            for (int c = 0; c < 4; c++) acc[i][j][c] = 0.f;

    #pragma unroll
    for (int s = 0; s < NSTG - 1; s++) {
        const uint32_t dst = sb + s * ST + tid * 16;
        #pragma unroll
        for (int c = 0; c < NREG; c++)
            CP16(dst + c * 4096, ps[c] + tid * 16);
        #pragma unroll
        for (int c = 0; c < NREG; c++) ps[c] += 4096;
        CP_COMMIT();
    }

    for (int s = 0; s < S; s++) {
        CP_WAIT2();
        __syncthreads();

        const uint32_t stg = sb + (uint32_t)((s & 3) * ST);
        uint32_t aH[MF][4], aL[MF][4], bH[WP][4], bL[WP][4];
        #pragma unroll
        for (int mf = 0; mf < MF; mf++) {
            LDSM4(aH[mf], stg + aOffH[mf]);
            LDSM4(aL[mf], stg + aOffH[mf] + 2048);
        }
        #pragma unroll
        for (int p = 0; p < WP; p++) {
            LDSM4(bH[p], stg + bOffH[p]);
            LDSM4(bL[p], stg + bOffH[p] + 2048);
        }
        #pragma unroll
        for (int mf = 0; mf < MF; mf++)
            #pragma unroll
            for (int nf = 0; nf < NFR; nf++) {
                const int p = nf >> 1, q = (nf & 1) * 2;
                MMA_BF16(acc[mf][nf], aH[mf][0], aH[mf][1], aH[mf][2], aH[mf][3],
                         bH[p][q], bH[p][q + 1]);
                MMA_BF16(acc[mf][nf], aH[mf][0], aH[mf][1], aH[mf][2], aH[mf][3],
                         bL[p][q], bL[p][q + 1]);
                MMA_BF16(acc[mf][nf], aL[mf][0], aL[mf][1], aL[mf][2], aL[mf][3],
                         bH[p][q], bH[p][q + 1]);
            }

        if (s + NSTG - 1 < S) {
            const uint32_t dst = sb + (uint32_t)(((s + NSTG - 1) & 3) * ST) + tid * 16;
            #pragma unroll
            for (int c = 0; c < NREG; c++)
                CP16(dst + c * 4096, ps[c] + tid * 16);
            #pragma unroll
            for (int c = 0; c < NREG; c++) ps[c] += 4096;
        }
        CP_COMMIT();
    }

    // ---- epilogue ----
    #pragma unroll
    for (int mf = 0; mf < MF; mf++) {
        const int r0 = bm + wm + mf * 16 + g;
        #pragma unroll
        for (int nf = 0; nf < NFR; nf++) {
            const int c0 = bn + wn + nf * 8 + 2 * t4;
            const float2 bv = *(const float2*)(bias + c0);
            float v00 = acc[mf][nf][0] + bv.x;
            float v01 = acc[mf][nf][1] + bv.y;
            float v10 = acc[mf][nf][2] + bv.x;
            float v11 = acc[mf][nf][3] + bv.y;
            if (EPI == 2) {
                v00 = v00 * 0.5f * (1.0f + erff(v00 * 0.70710678118654752f));
                v01 = v01 * 0.5f * (1.0f + erff(v01 * 0.70710678118654752f));
                v10 = v10 * 0.5f * (1.0f + erff(v10 * 0.70710678118654752f));
                v11 = v11 * 0.5f * (1.0f + erff(v11 * 0.70710678118654752f));
                uint8_t* C = (uint8_t*)Cout;
                store_split2(C, N, r0,     c0, v00, v01);
                store_split2(C, N, r0 + 8, c0, v10, v11);
            } else {
                float* C = (float*)Cout;
                const size_t i0 = (size_t)r0 * N + c0;
                const size_t i1 = (size_t)(r0 + 8) * N + c0;
                if (EPI == 1) {
                    const float2 r0v = *(const float2*)(res + i0);
                    const float2 r1v = *(const float2*)(res + i1);
                    v00 += r0v.x; v01 += r0v.y; v10 += r1v.x; v11 += r1v.y;
                }
                *(float2*)(C + i0) = make_float2(v00, v01);
                *(float2*)(C + i1) = make_float2(v10, v11);
            }
        }
    }
}

// ---------------- launch ----------------
extern "C" void kernel_launch(void* const* d_in, const int* in_sizes, int n_in,
                              void* d_out, int out_size) {
    const float* patches        = (const float*)d_in[0];
    const float* masked_token   = (const float*)d_in[3];
    const float* partial_params = (const float*)d_in[4];
    const float* emb_w          = (const float*)d_in[5];
    const float* emb_b          = (const float*)d_in[6];
    const float* ln1_g          = (const float*)d_in[7];
    const float* ln1_b          = (const float*)d_in[8];
    const float* in_proj_w      = (const float*)d_in[9];
    const float* in_proj_b      = (const float*)d_in[10];
    const float* out_proj_w     = (const float*)d_in[11];
    const float* out_proj_b     = (const float*)d_in[12];
    const float* rel_pos        = (const float*)d_in[13];
    const float* ln2_g          = (const float*)d_in[14];
    const float* ln2_b          = (const float*)d_in[15];
    const float* ffn_w1         = (const float*)d_in[16];
    const float* ffn_b1         = (const float*)d_in[17];
    const float* ffn_w2         = (const float*)d_in[18];
    const float* ffn_b2         = (const float*)d_in[19];
    const float* outp_w         = (const float*)d_in[20];
    const float* outp_b         = (const float*)d_in[21];
    float* out = (float*)d_out;

    float *x, *qkv;
    uint8_t *xn, *o, *h, *xf, *win, *wo, *w1, *w2, *wv;
    cudaGetSymbolAddress((void**)&x,   g_x);
    cudaGetSymbolAddress((void**)&qkv, g_qkv);
    cudaGetSymbolAddress((void**)&xn,  s_xn);
    cudaGetSymbolAddress((void**)&o,   s_o);
    cudaGetSymbolAddress((void**)&h,   s_h);
    cudaGetSymbolAddress((void**)&xf,  s_xf);
    cudaGetSymbolAddress((void**)&win, s_win);
    cudaGetSymbolAddress((void**)&wo,  s_wo);
    cudaGetSymbolAddress((void**)&w1,  s_w1);
    cudaGetSymbolAddress((void**)&w2,  s_w2);
    cudaGetSymbolAddress((void**)&wv,  s_wv);

    cudaFuncSetAttribute(attn_kernel, cudaFuncAttributeMaxDynamicSharedMemorySize, ATTN_SMEM);
    cudaFuncSetAttribute(gemm_split<64, 256, 0>, cudaFuncAttributeMaxDynamicSharedMemorySize, 81920);
    cudaFuncSetAttribute(gemm_split<64, 256, 2>, cudaFuncAttributeMaxDynamicSharedMemorySize, 81920);
    cudaFuncSetAttribute(gemm_split<64, 128, 1>, cudaFuncAttributeMaxDynamicSharedMemorySize, 49152);
    cudaFuncSetAttribute(gemm_split<128, 256, 0>, cudaFuncAttributeMaxDynamicSharedMemorySize, 98304);

    // ---- convert all weights to split tile format ----
    {
        int nc;
        nc = NL * 3 * ND * ND / 8;  convert_w<<<(nc + 255) / 256, 256>>>(in_proj_w,  win, ND, nc);
        nc = NL * ND * ND / 8;      convert_w<<<(nc + 255) / 256, 256>>>(out_proj_w, wo,  ND, nc);
        nc = NL * NF * ND / 8;      convert_w<<<(nc + 255) / 256, 256>>>(ffn_w1,     w1,  ND, nc);
        nc = NL * ND * NF / 8;      convert_w<<<(nc + 255) / 256, 256>>>(ffn_w2,     w2,  NF, nc);
        nc = (int)((size_t)NV * ND / 8);
        convert_w<<<(nc + 255) / 256, 256>>>(outp_w, wv, ND, nc);
    }

    tokenize_embed_kernel<<<NTOK, 128>>>(patches, masked_token, partial_params, emb_w, emb_b);

    for (int l = 0; l < NL; l++) {
        ln_kernel<<<NTOK, 256>>>(x, xn, ln1_g + l * ND, ln1_b + l * ND);

        gemm_split<64, 256, 0><<<dim3(NTOK / 64, 3 * ND / 256), 256, 81920>>>(
            xn, win + (size_t)l * 3 * ND * ND * 4, in_proj_b + l * 3 * ND,
            nullptr, qkv, NTOK, 3 * ND, ND);

        attn_kernel<<<NB * NH * 2, 256, ATTN_SMEM>>>(rel_pos + (size_t)l * NS * NS);

        gemm_split<64, 128, 1><<<dim3(NTOK / 64, ND / 128), 256, 49152>>>(
            o, wo + (size_t)l * ND * ND * 4, out_proj_b + l * ND,
            x, x, NTOK, ND, ND);

        ln_kernel<<<NTOK, 256>>>(x, xn, ln2_g + l * ND, ln2_b + l * ND);

        gemm_split<64, 256, 2><<<dim3(NTOK / 64, NF / 256), 256, 81920>>>(
            xn, w1 + (size_t)l * NF * ND * 4, ffn_b1 + l * NF,
            nullptr, h, NTOK, NF, ND);

        gemm_split<64, 128, 1><<<dim3(NTOK / 64, ND / 128), 256, 49152>>>(
            h, w2 + (size_t)l * ND * NF * 4, ffn_b2 + l * ND,
            x, x, NTOK, ND, NF);
    }

    convert_x_kernel<<<NTOK, 256>>>(x, xf);

    gemm_split<128, 256, 0><<<dim3(NTOK / 128, NV / 256), 256, 98304>>>(
        xf, wv, outp_b, nullptr, out, NTOK, NV, ND);
}

// round 8
// speedup vs baseline: 1.0385x; 1.0385x over previous
#include <cuda_runtime.h>
#include <cuda_bf16.h>
#include <math.h>
#include <stdint.h>

// ---------------- problem constants ----------------
#define NB   8
#define NS   256
#define NP   16
#define ND   512
#define NH   8
#define HD   64
#define NL   6
#define NF   2048
#define NV   65536
#define NTOK (NB * NS)   // 2048

// ---------------- scratch (device globals; no allocation) ----------------
__device__ float g_x  [NTOK * ND];          // residual stream (fp32)
__device__ float g_qkv[NTOK * 3 * ND];      // qkv projection (fp32)

// split-bf16 tile buffers (hi|lo 2KB blocks of 64 rows x 16 k, swizzled)
__device__ uint8_t s_xn [NTOK * ND * 4];
__device__ uint8_t s_o  [NTOK * ND * 4];
__device__ uint8_t s_h  [NTOK * NF * 4];
__device__ uint8_t s_xf [NTOK * ND * 4];
__device__ uint8_t s_win[NL * 3 * ND * ND * 4];
__device__ uint8_t s_wo [NL * ND * ND * 4];
__device__ uint8_t s_w1 [NL * NF * ND * 4];
__device__ uint8_t s_w2 [(size_t)NL * ND * NF * 4];
__device__ uint8_t s_wv [(size_t)NV * ND * 4];

__device__ __forceinline__ uint32_t smem_u32(const void* p) {
    uint32_t a;
    asm("{ .reg .u64 t; cvta.to.shared.u64 t, %1; cvt.u32.u64 %0, t; }" : "=r"(a) : "l"(p));
    return a;
}

// ---------------- split helpers ----------------
__device__ __forceinline__ void split_pack(float a, float b, unsigned& hi, unsigned& lo) {
    __nv_bfloat16 ha = __float2bfloat16_rn(a);
    __nv_bfloat16 hb = __float2bfloat16_rn(b);
    float ra = a - __bfloat162float(ha);
    float rb = b - __bfloat162float(hb);
    __nv_bfloat162 h2 = __halves2bfloat162(ha, hb);
    __nv_bfloat162 l2 = __floats2bfloat162_rn(ra, rb);
    hi = *(unsigned*)&h2;
    lo = *(unsigned*)&l2;
}
__device__ __forceinline__ void pack8(float4 v0, float4 v1, uint4& hi, uint4& lo) {
    split_pack(v0.x, v0.y, hi.x, lo.x);
    split_pack(v0.z, v0.w, hi.y, lo.y);
    split_pack(v1.x, v1.y, hi.z, lo.z);
    split_pack(v1.z, v1.w, hi.w, lo.w);
}
__device__ __forceinline__ void store_split2(uint8_t* base, int K, int row, int col,
                                             float a, float b) {
    unsigned hi, lo;
    split_pack(a, b, hi, lo);
    size_t blk = (size_t)(row >> 6) * (K >> 4) + (col >> 4);
    uint32_t off = (uint32_t)((row & 63) * 32 +
                   ((((col >> 3) & 1) ^ ((row >> 2) & 1)) << 4) + (col & 7) * 2);
    *(unsigned*)(base + blk * 4096 + off) = hi;
    *(unsigned*)(base + blk * 4096 + 2048 + off) = lo;
}

// ---------------- weight conversion (fp32 [R,K] -> split tiles) ----------------
__global__ void convert_w(const float* __restrict__ src, uint8_t* __restrict__ dst,
                          int K, int nChunks) {
    int ct = blockIdx.x * 256 + threadIdx.x;
    if (ct >= nChunks) return;
    int within = ct & 127;
    int blk = ct >> 7;
    int r = within >> 1, kc = within & 1;
    int stages = K >> 4;
    int rt = blk / stages, s = blk - rt * stages;
    const float* p = src + (size_t)(rt * 64 + r) * K + s * 16 + kc * 8;
    float4 v0 = *(const float4*)p, v1 = *(const float4*)(p + 4);
    uint4 hi, lo;
    pack8(v0, v1, hi, lo);
    uint32_t off = (uint32_t)(r * 32 + ((kc ^ ((r >> 2) & 1)) << 4));
    *(uint4*)(dst + (size_t)blk * 4096 + off) = hi;
    *(uint4*)(dst + (size_t)blk * 4096 + 2048 + off) = lo;
}

__global__ void convert_x_kernel(const float* __restrict__ src, uint8_t* __restrict__ dst) {
    const int row = blockIdx.x;
    const int d = threadIdx.x * 2;
    float2 v = ((const float2*)(src + (size_t)row * ND))[threadIdx.x];
    store_split2(dst, ND, row, d, v.x, v.y);
}

// ---------------- tokenize + embed ----------------
__global__ void tokenize_embed_kernel(const float* __restrict__ patches,
                                      const float* __restrict__ masked_token,
                                      const float* __restrict__ partial_params,
                                      const float* __restrict__ emb_w,
                                      const float* __restrict__ emb_b) {
    const int tok = blockIdx.x;
    const int tid = threadIdx.x;   // 128 threads
    __shared__ float proc[NP];

    if (tid == 0) {
        const float* f = patches + (size_t)tok * NP;
        bool anyMask = false, anyBin = false;
        int firstBin = -1;
        float fp[NP];
        #pragma unroll
        for (int p = 0; p < NP; p++) {
            float v = f[p];
            fp[p] = v;
            bool m = fabsf(v - 0.5f) < 0.1f;
            if (m) anyMask = true;
            else { anyBin = true; if (firstBin < 0) firstBin = p; }
        }
        if (!anyBin) {
            #pragma unroll
            for (int p = 0; p < NP; p++) proc[p] = masked_token[p];
        } else if (anyMask) {
            int ptok = firstBin * 2 + (int)rintf(fp[firstBin]);
            const float* pp = partial_params + ptok * NP;
            #pragma unroll
            for (int p = 0; p < NP; p++) proc[p] = pp[p];
        } else {
            #pragma unroll
            for (int p = 0; p < NP; p++) proc[p] = fp[p];
        }
    }
    __syncthreads();

    for (int d = tid; d < ND; d += blockDim.x) {
        const float* w = emb_w + d * NP;
        float s = emb_b[d];
        #pragma unroll
        for (int p = 0; p < NP; p++) s += proc[p] * w[p];
        g_x[(size_t)tok * ND + d] = s;
    }
}

// ---------------- layernorm (fp32 in -> split-bf16 tile out) ----------------
__global__ void ln_kernel(const float* __restrict__ in, uint8_t* __restrict__ out,
                          const float* __restrict__ gamma, const float* __restrict__ beta) {
    const int tok = blockIdx.x;
    const int tid = threadIdx.x;   // 256
    const float2 v = ((const float2*)(in + (size_t)tok * ND))[tid];

    float s  = v.x + v.y;
    float sq = v.x * v.x + v.y * v.y;
    #pragma unroll
    for (int off = 16; off; off >>= 1) {
        s  += __shfl_xor_sync(0xffffffffu, s,  off);
        sq += __shfl_xor_sync(0xffffffffu, sq, off);
    }
    __shared__ float rs[8], rq[8], stats[2];
    if ((tid & 31) == 0) { rs[tid >> 5] = s; rq[tid >> 5] = sq; }
    __syncthreads();
    if (tid == 0) {
        float S = 0.f, Q = 0.f;
        #pragma unroll
        for (int i = 0; i < 8; i++) { S += rs[i]; Q += rq[i]; }
        float mean = S * (1.0f / ND);
        float var  = Q * (1.0f / ND) - mean * mean;
        stats[0] = mean;
        stats[1] = rsqrtf(var + 1e-5f);
    }
    __syncthreads();
    const float mean = stats[0], inv = stats[1];
    float2 g2 = ((const float2*)gamma)[tid];
    float2 b2 = ((const float2*)beta)[tid];
    float ox = (v.x - mean) * inv * g2.x + b2.x;
    float oy = (v.y - mean) * inv * g2.y + b2.y;
    store_split2(out, ND, tok, tid * 2, ox, oy);
}

// ---------------- fused attention (smem K/V, split output) ----------------
#define ATTN_SMEM (192 * 1024)

__global__ __launch_bounds__(256) void attn_kernel(const float* __restrict__ rel) {
    extern __shared__ float sm[];
    float* Ks = sm;            // [256][64] rotated rows
    float* Vs = sm + 16384;    // [256][64]
    float* Qs = sm + 32768;    // [128][64]
    float* Wb = sm + 40960;    // [8 warps][256][4]

    const int idx = blockIdx.x;
    const int qc = idx & 1;
    const int h  = (idx >> 1) & (NH - 1);
    const int b  = idx >> 4;
    const int tid = threadIdx.x, wid = tid >> 5, L = tid & 31;

    const size_t base = (size_t)(b * NS) * (3 * ND) + h * HD;

    {
        const int dc = (tid & 15) * 4;
        int t = tid >> 4;
        #pragma unroll 4
        for (int pass = 0; pass < 16; pass++, t += 16) {
            const float* kR = g_qkv + base + ND + (size_t)t * (3 * ND);
            float4 kv = *(const float4*)(kR + dc);
            const int p = (dc + 4 * (t & 15)) & 63;
            *(float4*)(Ks + t * 64 + p) = kv;
            const float* vR = g_qkv + base + 2 * ND + (size_t)t * (3 * ND);
            *(float4*)(Vs + t * 64 + dc) = *(const float4*)(vR + dc);
        }
        int q = tid >> 4;
        #pragma unroll 4
        for (int pass = 0; pass < 8; pass++, q += 16) {
            const float* qR = g_qkv + base + (size_t)(qc * 128 + q) * (3 * ND);
            *(float4*)(Qs + q * 64 + dc) = *(const float4*)(qR + dc);
        }
    }
    __syncthreads();

    float* wb = Wb + wid * 1024;
    const int rot = 4 * (L & 15);

    for (int g4 = 0; g4 < 4; g4++) {
        const int q0 = wid * 16 + g4 * 4;
        const int sRow = qc * 128 + q0;

        float sc[4][8];
        #pragma unroll
        for (int qi = 0; qi < 4; qi++)
            #pragma unroll
            for (int j = 0; j < 8; j++) sc[qi][j] = 0.f;

        #pragma unroll
        for (int dd = 0; dd < 16; dd++) {
            const int d = dd * 4;
            float4 qv[4];
            #pragma unroll
            for (int qi = 0; qi < 4; qi++)
                qv[qi] = *(const float4*)(Qs + (q0 + qi) * 64 + d);
            const int p = (d + rot) & 63;
            #pragma unroll
            for (int j = 0; j < 8; j++) {
                float4 k4 = *(const float4*)(Ks + (L + 32 * j) * 64 + p);
                #pragma unroll
                for (int qi = 0; qi < 4; qi++)
                    sc[qi][j] += qv[qi].x * k4.x + qv[qi].y * k4.y +
                                 qv[qi].z * k4.z + qv[qi].w * k4.w;
            }
        }

        #pragma unroll
        for (int qi = 0; qi < 4; qi++) {
            const float* rrow = rel + (size_t)(sRow + qi) * NS;
            float m = -1e30f;
            #pragma unroll
            for (int j = 0; j < 8; j++) {
                float v = sc[qi][j] * 0.125f + rrow[L + 32 * j];
                sc[qi][j] = v;
                m = fmaxf(m, v);
            }
            #pragma unroll
            for (int off = 16; off; off >>= 1)
                m = fmaxf(m, __shfl_xor_sync(0xffffffffu, m, off));
            float ssum = 0.f;
            #pragma unroll
            for (int j = 0; j < 8; j++) { sc[qi][j] = expf(sc[qi][j] - m); ssum += sc[qi][j]; }
            #pragma unroll
            for (int off = 16; off; off >>= 1)
                ssum += __shfl_xor_sync(0xffffffffu, ssum, off);
            const float inv = 1.0f / ssum;
            #pragma unroll
            for (int j = 0; j < 8; j++) sc[qi][j] *= inv;
        }

        #pragma unroll
        for (int j = 0; j < 8; j++)
            *(float4*)(wb + (L + 32 * j) * 4) =
                make_float4(sc[0][j], sc[1][j], sc[2][j], sc[3][j]);
        __syncwarp();

        float2 acc[4];
        #pragma unroll
        for (int qi = 0; qi < 4; qi++) acc[qi] = make_float2(0.f, 0.f);
        #pragma unroll 4
        for (int t = 0; t < NS; t++) {
            float2 v2 = *(const float2*)(Vs + t * 64 + 2 * L);
            float4 w4 = *(const float4*)(wb + t * 4);
            acc[0].x += w4.x * v2.x; acc[0].y += w4.x * v2.y;
            acc[1].x += w4.y * v2.x; acc[1].y += w4.y * v2.y;
            acc[2].x += w4.z * v2.x; acc[2].y += w4.z * v2.y;
            acc[3].x += w4.w * v2.x; acc[3].y += w4.w * v2.y;
        }
        #pragma unroll
        for (int qi = 0; qi < 4; qi++)
            store_split2(s_o, ND, b * NS + sRow + qi, h * HD + 2 * L,
                         acc[qi].x, acc[qi].y);
        __syncwarp();
    }
}

// ---------------- split-bf16 GEMM: cp.async pipeline + ldmatrix + mma ----------
// Tile (TM x 128), warp tile (TM/2 x 32). KCH = k16 chunks per pipeline stage.
// 3-term split: AhWh + AhWl + AlWh, fp32 accum.
// EPI: 0 = fp32+bias, 1 = fp32+bias+res, 2 = split-gelu output.

#define MMA_BF16(d, a0,a1,a2,a3, b0,b1)                                         \
    asm volatile("mma.sync.aligned.m16n8k16.row.col.f32.bf16.bf16.f32 "         \
                 "{%0,%1,%2,%3}, {%4,%5,%6,%7}, {%8,%9}, {%0,%1,%2,%3};"        \
                 : "+f"(d[0]), "+f"(d[1]), "+f"(d[2]), "+f"(d[3])               \
                 : "r"(a0), "r"(a1), "r"(a2), "r"(a3), "r"(b0), "r"(b1))

#define LDSM4(r, addr)                                                          \
    asm volatile("ldmatrix.sync.aligned.m8n8.x4.shared.b16 {%0,%1,%2,%3}, [%4];"\
                 : "=r"((r)[0]), "=r"((r)[1]), "=r"((r)[2]), "=r"((r)[3])       \
                 : "r"(addr))

#define CP16(dst, src)                                                          \
    asm volatile("cp.async.cg.shared.global [%0], [%1], 16;" :: "r"(dst), "l"(src))
#define CP_COMMIT() asm volatile("cp.async.commit_group;" ::: "memory")
#define CP_WAIT2()  asm volatile("cp.async.wait_group 2;" ::: "memory")

template <int KCH>
__device__ __forceinline__ uint32_t tile_off_k(int m, int kc) {
    // region stride per 64-row block is KCH*4096; chunk j added by caller.
    return (uint32_t)((m >> 6) * KCH * 4096 + (m & 63) * 32 +
                      ((kc ^ ((m >> 2) & 1)) << 4));
}

template <int TM, int KCH, int EPI>
__global__ __launch_bounds__(256)
void gemm_split(const uint8_t* __restrict__ A, const uint8_t* __restrict__ W,
                const float* __restrict__ bias, const float* __restrict__ res,
                void* __restrict__ Cout, int M, int N, int K) {
    constexpr int ABLK  = TM / 64;
    constexpr int NREG  = ABLK + 2;              // 64-row blocks per stage
    constexpr int ST    = NREG * KCH * 4096;     // stage bytes
    constexpr int AWOFF = ABLK * KCH * 4096;     // W offset within stage
    constexpr int MF    = TM / 32;
    constexpr int NSTG  = 4;

    extern __shared__ uint8_t smem[];
    const uint32_t sb = smem_u32(smem);

    const int tid = threadIdx.x;
    const int bm = blockIdx.x * TM;
    const int bn = blockIdx.y * 128;
    const int wid = tid >> 5, lane = tid & 31;
    const int g = lane >> 2, t4 = lane & 3;
    const int wm = (wid >> 2) * (TM / 2);
    const int wn = (wid & 3) * 32;

    const int S = K >> 4;              // k16 chunks total
    const int SP = S / KCH;            // pipeline stages

    const uint8_t* ps[NREG];
    {
        const int mt0 = blockIdx.x * ABLK;
        const int nt0 = blockIdx.y * 2;
        #pragma unroll
        for (int i = 0; i < ABLK; i++)
            ps[i] = A + (size_t)(mt0 + i) * S * 4096;
        ps[ABLK]     = W + (size_t)nt0 * S * 4096;
        ps[ABLK + 1] = W + (size_t)(nt0 + 1) * S * 4096;
    }

    const int sel = lane >> 3, ri = lane & 7;
    uint32_t aOffH[MF], bOffH[2];
    #pragma unroll
    for (int mf = 0; mf < MF; mf++) {
        const int m = wm + mf * 16 + (sel & 1) * 8 + ri;
        aOffH[mf] = tile_off_k<KCH>(m, sel >> 1);
    }
    #pragma unroll
    for (int p = 0; p < 2; p++) {
        const int n = wn + p * 16 + (sel >> 1) * 8 + ri;
        bOffH[p] = AWOFF + tile_off_k<KCH>(n, sel & 1);
    }

    float acc[MF][4][4];
    #pragma unroll
    for (int i = 0; i < MF; i++)
        #pragma unroll
        for (int j = 0; j < 4; j++)
            #pragma unroll
            for (int c = 0; c < 4; c++) acc[i][j][c] = 0.f;

    #pragma unroll
    for (int s = 0; s < NSTG - 1; s++) {
        const uint32_t dst = sb + s * ST + tid * 16;
        #pragma unroll
        for (int c = 0; c < NREG; c++)
            #pragma unroll
            for (int j = 0; j < KCH; j++)
                CP16(dst + (c * KCH + j) * 4096, ps[c] + j * 4096 + tid * 16);
        #pragma unroll
        for (int c = 0; c < NREG; c++) ps[c] += KCH * 4096;
        CP_COMMIT();
    }

    for (int s = 0; s < SP; s++) {
        CP_WAIT2();
        __syncthreads();

        const uint32_t stg = sb + (uint32_t)((s & 3) * ST);
        #pragma unroll
        for (int j = 0; j < KCH; j++) {
            const uint32_t cofs = stg + j * 4096;
            uint32_t aH[MF][4], aL[MF][4], bH[2][4], bL[2][4];
            #pragma unroll
            for (int mf = 0; mf < MF; mf++) {
                LDSM4(aH[mf], cofs + aOffH[mf]);
                LDSM4(aL[mf], cofs + aOffH[mf] + 2048);
            }
            #pragma unroll
            for (int p = 0; p < 2; p++) {
                LDSM4(bH[p], cofs + bOffH[p]);
                LDSM4(bL[p], cofs + bOffH[p] + 2048);
            }
            #pragma unroll
            for (int mf = 0; mf < MF; mf++)
                #pragma unroll
                for (int nf = 0; nf < 4; nf++) {
                    const int p = nf >> 1, q = (nf & 1) * 2;
                    MMA_BF16(acc[mf][nf], aH[mf][0], aH[mf][1], aH[mf][2], aH[mf][3],
                             bH[p][q], bH[p][q + 1]);
                    MMA_BF16(acc[mf][nf], aH[mf][0], aH[mf][1], aH[mf][2], aH[mf][3],
                             bL[p][q], bL[p][q + 1]);
                    MMA_BF16(acc[mf][nf], aL[mf][0], aL[mf][1], aL[mf][2], aL[mf][3],
                             bH[p][q], bH[p][q + 1]);
                }
        }

        if (s + NSTG - 1 < SP) {
            const uint32_t dst = sb + (uint32_t)(((s + NSTG - 1) & 3) * ST) + tid * 16;
            #pragma unroll
            for (int c = 0; c < NREG; c++)
                #pragma unroll
                for (int j = 0; j < KCH; j++)
                    CP16(dst + (c * KCH + j) * 4096, ps[c] + j * 4096 + tid * 16);
            #pragma unroll
            for (int c = 0; c < NREG; c++) ps[c] += KCH * 4096;
        }
        CP_COMMIT();
    }

    // ---- epilogue ----
    #pragma unroll
    for (int mf = 0; mf < MF; mf++) {
        const int r0 = bm + wm + mf * 16 + g;
        #pragma unroll
        for (int nf = 0; nf < 4; nf++) {
            const int c0 = bn + wn + nf * 8 + 2 * t4;
            const float2 bv = *(const float2*)(bias + c0);
            float v00 = acc[mf][nf][0] + bv.x;
            float v01 = acc[mf][nf][1] + bv.y;
            float v10 = acc[mf][nf][2] + bv.x;
            float v11 = acc[mf][nf][3] + bv.y;
            if (EPI == 2) {
                v00 = v00 * 0.5f * (1.0f + erff(v00 * 0.70710678118654752f));
                v01 = v01 * 0.5f * (1.0f + erff(v01 * 0.70710678118654752f));
                v10 = v10 * 0.5f * (1.0f + erff(v10 * 0.70710678118654752f));
                v11 = v11 * 0.5f * (1.0f + erff(v11 * 0.70710678118654752f));
                uint8_t* C = (uint8_t*)Cout;
                store_split2(C, N, r0,     c0, v00, v01);
                store_split2(C, N, r0 + 8, c0, v10, v11);
            } else {
                float* C = (float*)Cout;
                const size_t i0 = (size_t)r0 * N + c0;
                const size_t i1 = (size_t)(r0 + 8) * N + c0;
                if (EPI == 1) {
                    const float2 r0v = *(const float2*)(res + i0);
                    const float2 r1v = *(const float2*)(res + i1);
                    v00 += r0v.x; v01 += r0v.y; v10 += r1v.x; v11 += r1v.y;
                }
                *(float2*)(C + i0) = make_float2(v00, v01);
                *(float2*)(C + i1) = make_float2(v10, v11);
            }
        }
    }
}

// ---------------- launch ----------------
extern "C" void kernel_launch(void* const* d_in, const int* in_sizes, int n_in,
                              void* d_out, int out_size) {
    const float* patches        = (const float*)d_in[0];
    const float* masked_token   = (const float*)d_in[3];
    const float* partial_params = (const float*)d_in[4];
    const float* emb_w          = (const float*)d_in[5];
    const float* emb_b          = (const float*)d_in[6];
    const float* ln1_g          = (const float*)d_in[7];
    const float* ln1_b          = (const float*)d_in[8];
    const float* in_proj_w      = (const float*)d_in[9];
    const float* in_proj_b      = (const float*)d_in[10];
    const float* out_proj_w     = (const float*)d_in[11];
    const float* out_proj_b     = (const float*)d_in[12];
    const float* rel_pos        = (const float*)d_in[13];
    const float* ln2_g          = (const float*)d_in[14];
    const float* ln2_b          = (const float*)d_in[15];
    const float* ffn_w1         = (const float*)d_in[16];
    const float* ffn_b1         = (const float*)d_in[17];
    const float* ffn_w2         = (const float*)d_in[18];
    const float* ffn_b2         = (const float*)d_in[19];
    const float* outp_w         = (const float*)d_in[20];
    const float* outp_b         = (const float*)d_in[21];
    float* out = (float*)d_out;

    float *x, *qkv;
    uint8_t *xn, *o, *h, *xf, *win, *wo, *w1, *w2, *wv;
    cudaGetSymbolAddress((void**)&x,   g_x);
    cudaGetSymbolAddress((void**)&qkv, g_qkv);
    cudaGetSymbolAddress((void**)&xn,  s_xn);
    cudaGetSymbolAddress((void**)&o,   s_o);
    cudaGetSymbolAddress((void**)&h,   s_h);
    cudaGetSymbolAddress((void**)&xf,  s_xf);
    cudaGetSymbolAddress((void**)&win, s_win);
    cudaGetSymbolAddress((void**)&wo,  s_wo);
    cudaGetSymbolAddress((void**)&w1,  s_w1);
    cudaGetSymbolAddress((void**)&w2,  s_w2);
    cudaGetSymbolAddress((void**)&wv,  s_wv);

    cudaFuncSetAttribute(attn_kernel, cudaFuncAttributeMaxDynamicSharedMemorySize, ATTN_SMEM);
    cudaFuncSetAttribute(gemm_split<64, 1, 0>, cudaFuncAttributeMaxDynamicSharedMemorySize, 49152);
    cudaFuncSetAttribute(gemm_split<64, 1, 1>, cudaFuncAttributeMaxDynamicSharedMemorySize, 49152);
    cudaFuncSetAttribute(gemm_split<128, 1, 2>, cudaFuncAttributeMaxDynamicSharedMemorySize, 65536);
    cudaFuncSetAttribute(gemm_split<128, 2, 0>, cudaFuncAttributeMaxDynamicSharedMemorySize, 131072);

    // ---- convert all weights to split tile format ----
    {
        int nc;
        nc = NL * 3 * ND * ND / 8;  convert_w<<<(nc + 255) / 256, 256>>>(in_proj_w,  win, ND, nc);
        nc = NL * ND * ND / 8;      convert_w<<<(nc + 255) / 256, 256>>>(out_proj_w, wo,  ND, nc);
        nc = NL * NF * ND / 8;      convert_w<<<(nc + 255) / 256, 256>>>(ffn_w1,     w1,  ND, nc);
        nc = NL * ND * NF / 8;      convert_w<<<(nc + 255) / 256, 256>>>(ffn_w2,     w2,  NF, nc);
        nc = (int)((size_t)NV * ND / 8);
        convert_w<<<(nc + 255) / 256, 256>>>(outp_w, wv, ND, nc);
    }

    tokenize_embed_kernel<<<NTOK, 128>>>(patches, masked_token, partial_params, emb_w, emb_b);

    for (int l = 0; l < NL; l++) {
        ln_kernel<<<NTOK, 256>>>(x, xn, ln1_g + l * ND, ln1_b + l * ND);

        gemm_split<64, 1, 0><<<dim3(NTOK / 64, 3 * ND / 128), 256, 49152>>>(
            xn, win + (size_t)l * 3 * ND * ND * 4, in_proj_b + l * 3 * ND,
            nullptr, qkv, NTOK, 3 * ND, ND);

        attn_kernel<<<NB * NH * 2, 256, ATTN_SMEM>>>(rel_pos + (size_t)l * NS * NS);

        gemm_split<64, 1, 1><<<dim3(NTOK / 64, ND / 128), 256, 49152>>>(
            o, wo + (size_t)l * ND * ND * 4, out_proj_b + l * ND,
            x, x, NTOK, ND, ND);

        ln_kernel<<<NTOK, 256>>>(x, xn, ln2_g + l * ND, ln2_b + l * ND);

        gemm_split<128, 1, 2><<<dim3(NTOK / 128, NF / 128), 256, 65536>>>(
            xn, w1 + (size_t)l * NF * ND * 4, ffn_b1 + l * NF,
            nullptr, h, NTOK, NF, ND);

        gemm_split<64, 1, 1><<<dim3(NTOK / 64, ND / 128), 256, 49152>>>(
            h, w2 + (size_t)l * ND * NF * 4, ffn_b2 + l * ND,
            x, x, NTOK, ND, NF);
    }

    convert_x_kernel<<<NTOK, 256>>>(x, xf);

    gemm_split<128, 2, 0><<<dim3(NTOK / 128, NV / 128), 256, 131072>>>(
        xf, wv, outp_b, nullptr, out, NTOK, NV, ND);
}

// round 9
// speedup vs baseline: 1.2565x; 1.2099x over previous
#include <cuda_runtime.h>
#include <cuda_bf16.h>
#include <cuda_fp16.h>
#include <math.h>
#include <stdint.h>

// ---------------- problem constants ----------------
#define NB   8
#define NS   256
#define NP   16
#define ND   512
#define NH   8
#define HD   64
#define NL   6
#define NF   2048
#define NV   65536
#define NTOK (NB * NS)   // 2048

// ---------------- scratch (device globals; no allocation) ----------------
__device__ float g_x  [NTOK * ND];          // residual stream (fp32)
__device__ float g_qkv[NTOK * 3 * ND];      // qkv projection (fp32)

// split-bf16 tile buffers (hi|lo 2KB blocks of 64 rows x 16 k, swizzled)
__device__ uint8_t s_xn [NTOK * ND * 4];
__device__ uint8_t s_o  [NTOK * ND * 4];
__device__ uint8_t s_h  [NTOK * NF * 4];
__device__ uint8_t s_win[NL * 3 * ND * ND * 4];
__device__ uint8_t s_wo [NL * ND * ND * 4];
__device__ uint8_t s_w1 [NL * NF * ND * 4];
__device__ uint8_t s_w2 [(size_t)NL * ND * NF * 4];
// fp16 single tiles (2KB blocks of 64 rows x 16 k, swizzled) for vocab GEMM
__device__ uint8_t s_xf [NTOK * ND * 2];
__device__ uint8_t s_wv [(size_t)NV * ND * 2];

__device__ __forceinline__ uint32_t smem_u32(const void* p) {
    uint32_t a;
    asm("{ .reg .u64 t; cvta.to.shared.u64 t, %1; cvt.u32.u64 %0, t; }" : "=r"(a) : "l"(p));
    return a;
}

// ---------------- split helpers ----------------
__device__ __forceinline__ void split_pack(float a, float b, unsigned& hi, unsigned& lo) {
    __nv_bfloat16 ha = __float2bfloat16_rn(a);
    __nv_bfloat16 hb = __float2bfloat16_rn(b);
    float ra = a - __bfloat162float(ha);
    float rb = b - __bfloat162float(hb);
    __nv_bfloat162 h2 = __halves2bfloat162(ha, hb);
    __nv_bfloat162 l2 = __floats2bfloat162_rn(ra, rb);
    hi = *(unsigned*)&h2;
    lo = *(unsigned*)&l2;
}
__device__ __forceinline__ void pack8(float4 v0, float4 v1, uint4& hi, uint4& lo) {
    split_pack(v0.x, v0.y, hi.x, lo.x);
    split_pack(v0.z, v0.w, hi.y, lo.y);
    split_pack(v1.x, v1.y, hi.z, lo.z);
    split_pack(v1.z, v1.w, hi.w, lo.w);
}
__device__ __forceinline__ void store_split2(uint8_t* base, int K, int row, int col,
                                             float a, float b) {
    unsigned hi, lo;
    split_pack(a, b, hi, lo);
    size_t blk = (size_t)(row >> 6) * (K >> 4) + (col >> 4);
    uint32_t off = (uint32_t)((row & 63) * 32 +
                   ((((col >> 3) & 1) ^ ((row >> 2) & 1)) << 4) + (col & 7) * 2);
    *(unsigned*)(base + blk * 4096 + off) = hi;
    *(unsigned*)(base + blk * 4096 + 2048 + off) = lo;
}
// fp16 single-tile store of 2 adjacent elements
__device__ __forceinline__ void store_h2(uint8_t* base, int K, int row, int col,
                                         float a, float b) {
    __half2 h = __floats2half2_rn(a, b);
    size_t blk = (size_t)(row >> 6) * (K >> 4) + (col >> 4);
    uint32_t off = (uint32_t)((row & 63) * 32 +
                   ((((col >> 3) & 1) ^ ((row >> 2) & 1)) << 4) + (col & 7) * 2);
    *(__half2*)(base + blk * 2048 + off) = h;
}

// ---------------- weight conversion (fp32 [R,K] -> split tiles) ----------------
__global__ void convert_w(const float* __restrict__ src, uint8_t* __restrict__ dst,
                          int K, int nChunks) {
    int ct = blockIdx.x * 256 + threadIdx.x;
    if (ct >= nChunks) return;
    int within = ct & 127;
    int blk = ct >> 7;
    int r = within >> 1, kc = within & 1;
    int stages = K >> 4;
    int rt = blk / stages, s = blk - rt * stages;
    const float* p = src + (size_t)(rt * 64 + r) * K + s * 16 + kc * 8;
    float4 v0 = *(const float4*)p, v1 = *(const float4*)(p + 4);
    uint4 hi, lo;
    pack8(v0, v1, hi, lo);
    uint32_t off = (uint32_t)(r * 32 + ((kc ^ ((r >> 2) & 1)) << 4));
    *(uint4*)(dst + (size_t)blk * 4096 + off) = hi;
    *(uint4*)(dst + (size_t)blk * 4096 + 2048 + off) = lo;
}

// weight conversion (fp32 [R,K] -> fp16 single tiles)
__global__ void convert_w_h(const float* __restrict__ src, uint8_t* __restrict__ dst,
                            int K, int nChunks) {
    int ct = blockIdx.x * 256 + threadIdx.x;
    if (ct >= nChunks) return;
    int within = ct & 127;
    int blk = ct >> 7;
    int r = within >> 1, kc = within & 1;
    int stages = K >> 4;
    int rt = blk / stages, s = blk - rt * stages;
    const float* p = src + (size_t)(rt * 64 + r) * K + s * 16 + kc * 8;
    float4 v0 = *(const float4*)p, v1 = *(const float4*)(p + 4);
    __half2 h0 = __floats2half2_rn(v0.x, v0.y);
    __half2 h1 = __floats2half2_rn(v0.z, v0.w);
    __half2 h2 = __floats2half2_rn(v1.x, v1.y);
    __half2 h3 = __floats2half2_rn(v1.z, v1.w);
    uint4 hv;
    hv.x = *(unsigned*)&h0; hv.y = *(unsigned*)&h1;
    hv.z = *(unsigned*)&h2; hv.w = *(unsigned*)&h3;
    uint32_t off = (uint32_t)(r * 32 + ((kc ^ ((r >> 2) & 1)) << 4));
    *(uint4*)(dst + (size_t)blk * 2048 + off) = hv;
}

__global__ void convert_x_kernel(const float* __restrict__ src, uint8_t* __restrict__ dst) {
    const int row = blockIdx.x;
    float2 v = ((const float2*)(src + (size_t)row * ND))[threadIdx.x];
    store_h2(dst, ND, row, threadIdx.x * 2, v.x, v.y);
}

// ---------------- tokenize + embed ----------------
__global__ void tokenize_embed_kernel(const float* __restrict__ patches,
                                      const float* __restrict__ masked_token,
                                      const float* __restrict__ partial_params,
                                      const float* __restrict__ emb_w,
                                      const float* __restrict__ emb_b) {
    const int tok = blockIdx.x;
    const int tid = threadIdx.x;   // 128 threads
    __shared__ float proc[NP];

    if (tid == 0) {
        const float* f = patches + (size_t)tok * NP;
        bool anyMask = false, anyBin = false;
        int firstBin = -1;
        float fp[NP];
        #pragma unroll
        for (int p = 0; p < NP; p++) {
            float v = f[p];
            fp[p] = v;
            bool m = fabsf(v - 0.5f) < 0.1f;
            if (m) anyMask = true;
            else { anyBin = true; if (firstBin < 0) firstBin = p; }
        }
        if (!anyBin) {
            #pragma unroll
            for (int p = 0; p < NP; p++) proc[p] = masked_token[p];
        } else if (anyMask) {
            int ptok = firstBin * 2 + (int)rintf(fp[firstBin]);
            const float* pp = partial_params + ptok * NP;
            #pragma unroll
            for (int p = 0; p < NP; p++) proc[p] = pp[p];
        } else {
            #pragma unroll
            for (int p = 0; p < NP; p++) proc[p] = fp[p];
        }
    }
    __syncthreads();

    for (int d = tid; d < ND; d += blockDim.x) {
        const float* w = emb_w + d * NP;
        float s = emb_b[d];
        #pragma unroll
        for (int p = 0; p < NP; p++) s += proc[p] * w[p];
        g_x[(size_t)tok * ND + d] = s;
    }
}

// ---------------- layernorm (fp32 in -> split-bf16 tile out) ----------------
__global__ void ln_kernel(const float* __restrict__ in, uint8_t* __restrict__ out,
                          const float* __restrict__ gamma, const float* __restrict__ beta) {
    const int tok = blockIdx.x;
    const int tid = threadIdx.x;   // 256
    const float2 v = ((const float2*)(in + (size_t)tok * ND))[tid];

    float s  = v.x + v.y;
    float sq = v.x * v.x + v.y * v.y;
    #pragma unroll
    for (int off = 16; off; off >>= 1) {
        s  += __shfl_xor_sync(0xffffffffu, s,  off);
        sq += __shfl_xor_sync(0xffffffffu, sq, off);
    }
    __shared__ float rs[8], rq[8], stats[2];
    if ((tid & 31) == 0) { rs[tid >> 5] = s; rq[tid >> 5] = sq; }
    __syncthreads();
    if (tid == 0) {
        float S = 0.f, Q = 0.f;
        #pragma unroll
        for (int i = 0; i < 8; i++) { S += rs[i]; Q += rq[i]; }
        float mean = S * (1.0f / ND);
        float var  = Q * (1.0f / ND) - mean * mean;
        stats[0] = mean;
        stats[1] = rsqrtf(var + 1e-5f);
    }
    __syncthreads();
    const float mean = stats[0], inv = stats[1];
    float2 g2 = ((const float2*)gamma)[tid];
    float2 b2 = ((const float2*)beta)[tid];
    float ox = (v.x - mean) * inv * g2.x + b2.x;
    float oy = (v.y - mean) * inv * g2.y + b2.y;
    store_split2(out, ND, tok, tid * 2, ox, oy);
}

// ---------------- fused attention (smem K/V, split output) ----------------
#define ATTN_SMEM (192 * 1024)

__global__ __launch_bounds__(256) void attn_kernel(const float* __restrict__ rel) {
    extern __shared__ float sm[];
    float* Ks = sm;            // [256][64] rotated rows
    float* Vs = sm + 16384;    // [256][64]
    float* Qs = sm + 32768;    // [128][64]
    float* Wb = sm + 40960;    // [8 warps][256][4]

    const int idx = blockIdx.x;
    const int qc = idx & 1;
    const int h  = (idx >> 1) & (NH - 1);
    const int b  = idx >> 4;
    const int tid = threadIdx.x, wid = tid >> 5, L = tid & 31;

    const size_t base = (size_t)(b * NS) * (3 * ND) + h * HD;

    {
        const int dc = (tid & 15) * 4;
        int t = tid >> 4;
        #pragma unroll 4
        for (int pass = 0; pass < 16; pass++, t += 16) {
            const float* kR = g_qkv + base + ND + (size_t)t * (3 * ND);
            float4 kv = *(const float4*)(kR + dc);
            const int p = (dc + 4 * (t & 15)) & 63;
            *(float4*)(Ks + t * 64 + p) = kv;
            const float* vR = g_qkv + base + 2 * ND + (size_t)t * (3 * ND);
            *(float4*)(Vs + t * 64 + dc) = *(const float4*)(vR + dc);
        }
        int q = tid >> 4;
        #pragma unroll 4
        for (int pass = 0; pass < 8; pass++, q += 16) {
            const float* qR = g_qkv + base + (size_t)(qc * 128 + q) * (3 * ND);
            *(float4*)(Qs + q * 64 + dc) = *(const float4*)(qR + dc);
        }
    }
    __syncthreads();

    float* wb = Wb + wid * 1024;
    const int rot = 4 * (L & 15);

    for (int g4 = 0; g4 < 4; g4++) {
        const int q0 = wid * 16 + g4 * 4;
        const int sRow = qc * 128 + q0;

        float sc[4][8];
        #pragma unroll
        for (int qi = 0; qi < 4; qi++)
            #pragma unroll
            for (int j = 0; j < 8; j++) sc[qi][j] = 0.f;

        #pragma unroll
        for (int dd = 0; dd < 16; dd++) {
            const int d = dd * 4;
            float4 qv[4];
            #pragma unroll
            for (int qi = 0; qi < 4; qi++)
                qv[qi] = *(const float4*)(Qs + (q0 + qi) * 64 + d);
            const int p = (d + rot) & 63;
            #pragma unroll
            for (int j = 0; j < 8; j++) {
                float4 k4 = *(const float4*)(Ks + (L + 32 * j) * 64 + p);
                #pragma unroll
                for (int qi = 0; qi < 4; qi++)
                    sc[qi][j] += qv[qi].x * k4.x + qv[qi].y * k4.y +
                                 qv[qi].z * k4.z + qv[qi].w * k4.w;
            }
        }

        #pragma unroll
        for (int qi = 0; qi < 4; qi++) {
            const float* rrow = rel + (size_t)(sRow + qi) * NS;
            float m = -1e30f;
            #pragma unroll
            for (int j = 0; j < 8; j++) {
                float v = sc[qi][j] * 0.125f + rrow[L + 32 * j];
                sc[qi][j] = v;
                m = fmaxf(m, v);
            }
            #pragma unroll
            for (int off = 16; off; off >>= 1)
                m = fmaxf(m, __shfl_xor_sync(0xffffffffu, m, off));
            float ssum = 0.f;
            #pragma unroll
            for (int j = 0; j < 8; j++) { sc[qi][j] = expf(sc[qi][j] - m); ssum += sc[qi][j]; }
            #pragma unroll
            for (int off = 16; off; off >>= 1)
                ssum += __shfl_xor_sync(0xffffffffu, ssum, off);
            const float inv = 1.0f / ssum;
            #pragma unroll
            for (int j = 0; j < 8; j++) sc[qi][j] *= inv;
        }

        #pragma unroll
        for (int j = 0; j < 8; j++)
            *(float4*)(wb + (L + 32 * j) * 4) =
                make_float4(sc[0][j], sc[1][j], sc[2][j], sc[3][j]);
        __syncwarp();

        float2 acc[4];
        #pragma unroll
        for (int qi = 0; qi < 4; qi++) acc[qi] = make_float2(0.f, 0.f);
        #pragma unroll 4
        for (int t = 0; t < NS; t++) {
            float2 v2 = *(const float2*)(Vs + t * 64 + 2 * L);
            float4 w4 = *(const float4*)(wb + t * 4);
            acc[0].x += w4.x * v2.x; acc[0].y += w4.x * v2.y;
            acc[1].x += w4.y * v2.x; acc[1].y += w4.y * v2.y;
            acc[2].x += w4.z * v2.x; acc[2].y += w4.z * v2.y;
            acc[3].x += w4.w * v2.x; acc[3].y += w4.w * v2.y;
        }
        #pragma unroll
        for (int qi = 0; qi < 4; qi++)
            store_split2(s_o, ND, b * NS + sRow + qi, h * HD + 2 * L,
                         acc[qi].x, acc[qi].y);
        __syncwarp();
    }
}

// ---------------- GEMM common macros ----------------
#define MMA_BF16(d, a0,a1,a2,a3, b0,b1)                                         \
    asm volatile("mma.sync.aligned.m16n8k16.row.col.f32.bf16.bf16.f32 "         \
                 "{%0,%1,%2,%3}, {%4,%5,%6,%7}, {%8,%9}, {%0,%1,%2,%3};"        \
                 : "+f"(d[0]), "+f"(d[1]), "+f"(d[2]), "+f"(d[3])               \
                 : "r"(a0), "r"(a1), "r"(a2), "r"(a3), "r"(b0), "r"(b1))

#define MMA_FP16(d, a0,a1,a2,a3, b0,b1)                                         \
    asm volatile("mma.sync.aligned.m16n8k16.row.col.f32.f16.f16.f32 "           \
                 "{%0,%1,%2,%3}, {%4,%5,%6,%7}, {%8,%9}, {%0,%1,%2,%3};"        \
                 : "+f"(d[0]), "+f"(d[1]), "+f"(d[2]), "+f"(d[3])               \
                 : "r"(a0), "r"(a1), "r"(a2), "r"(a3), "r"(b0), "r"(b1))

#define LDSM4(r, addr)                                                          \
    asm volatile("ldmatrix.sync.aligned.m8n8.x4.shared.b16 {%0,%1,%2,%3}, [%4];"\
                 : "=r"((r)[0]), "=r"((r)[1]), "=r"((r)[2]), "=r"((r)[3])       \
                 : "r"(addr))

#define CP16(dst, src)                                                          \
    asm volatile("cp.async.cg.shared.global [%0], [%1], 16;" :: "r"(dst), "l"(src))
#define CP_COMMIT() asm volatile("cp.async.commit_group;" ::: "memory")
#define CP_WAIT2()  asm volatile("cp.async.wait_group 2;" ::: "memory")

__device__ __forceinline__ uint32_t tile_off(int m, int kc) {
    return (uint32_t)((m >> 6) * 4096 + (m & 63) * 32 +
                      ((kc ^ ((m >> 2) & 1)) << 4));
}
__device__ __forceinline__ uint32_t tile_off_h(int m, int kc) {
    return (uint32_t)((m >> 6) * 2048 + (m & 63) * 32 +
                      ((kc ^ ((m >> 2) & 1)) << 4));
}

// ---------------- split-bf16 GEMM (round-6 verified config) ----------------
template <int TM, int EPI>
__global__ __launch_bounds__(256, 1)
void gemm_split(const uint8_t* __restrict__ A, const uint8_t* __restrict__ W,
                const float* __restrict__ bias, const float* __restrict__ res,
                void* __restrict__ Cout, int M, int N, int K) {
    constexpr int ABLK  = TM / 64;
    constexpr int NREG  = ABLK + 2;
    constexpr int ST    = NREG * 4096;
    constexpr int AWOFF = ABLK * 4096;
    constexpr int MF    = TM / 32;
    constexpr int NSTG  = 4;

    extern __shared__ uint8_t smem[];
    const uint32_t sb = smem_u32(smem);

    const int tid = threadIdx.x;
    const int bm = blockIdx.x * TM;
    const int bn = blockIdx.y * 128;
    const int wid = tid >> 5, lane = tid & 31;
    const int g = lane >> 2, t4 = lane & 3;
    const int wm = (wid >> 2) * (TM / 2);
    const int wn = (wid & 3) * 32;

    const int S = K >> 4;

    const uint8_t* ps[NREG];
    {
        const int mt0 = blockIdx.x * ABLK;
        const int nt0 = blockIdx.y * 2;
        #pragma unroll
        for (int i = 0; i < ABLK; i++)
            ps[i] = A + (size_t)(mt0 + i) * S * 4096;
        ps[ABLK]     = W + (size_t)nt0 * S * 4096;
        ps[ABLK + 1] = W + (size_t)(nt0 + 1) * S * 4096;
    }

    const int sel = lane >> 3, ri = lane & 7;
    uint32_t aOffH[MF], bOffH[2];
    #pragma unroll
    for (int mf = 0; mf < MF; mf++) {
        const int m = wm + mf * 16 + (sel & 1) * 8 + ri;
        aOffH[mf] = tile_off(m, sel >> 1);
    }
    #pragma unroll
    for (int p = 0; p < 2; p++) {
        const int n = wn + p * 16 + (sel >> 1) * 8 + ri;
        bOffH[p] = AWOFF + tile_off(n, sel & 1);
    }

    float acc[MF][4][4];
    #pragma unroll
    for (int i = 0; i < MF; i++)
        #pragma unroll
        for (int j = 0; j < 4; j++)
            #pragma unroll
            for (int c = 0; c < 4; c++) acc[i][j][c] = 0.f;

    #pragma unroll
    for (int s = 0; s < NSTG - 1; s++) {
        const uint32_t dst = sb + s * ST + tid * 16;
        #pragma unroll
        for (int c = 0; c < NREG; c++)
            CP16(dst + c * 4096, ps[c] + tid * 16);
        #pragma unroll
        for (int c = 0; c < NREG; c++) ps[c] += 4096;
        CP_COMMIT();
    }

    for (int s = 0; s < S; s++) {
        CP_WAIT2();
        __syncthreads();

        const uint32_t stg = sb + (uint32_t)((s & 3) * ST);
        uint32_t aH[MF][4], aL[MF][4], bH[2][4], bL[2][4];
        #pragma unroll
        for (int mf = 0; mf < MF; mf++) {
            LDSM4(aH[mf], stg + aOffH[mf]);
            LDSM4(aL[mf], stg + aOffH[mf] + 2048);
        }
        #pragma unroll
        for (int p = 0; p < 2; p++) {
            LDSM4(bH[p], stg + bOffH[p]);
            LDSM4(bL[p], stg + bOffH[p] + 2048);
        }
        #pragma unroll
        for (int mf = 0; mf < MF; mf++)
            #pragma unroll
            for (int nf = 0; nf < 4; nf++) {
                const int p = nf >> 1, q = (nf & 1) * 2;
                MMA_BF16(acc[mf][nf], aH[mf][0], aH[mf][1], aH[mf][2], aH[mf][3],
                         bH[p][q], bH[p][q + 1]);
                MMA_BF16(acc[mf][nf], aH[mf][0], aH[mf][1], aH[mf][2], aH[mf][3],
                         bL[p][q], bL[p][q + 1]);
                MMA_BF16(acc[mf][nf], aL[mf][0], aL[mf][1], aL[mf][2], aL[mf][3],
                         bH[p][q], bH[p][q + 1]);
            }

        if (s + NSTG - 1 < S) {
            const uint32_t dst = sb + (uint32_t)(((s + NSTG - 1) & 3) * ST) + tid * 16;
            #pragma unroll
            for (int c = 0; c < NREG; c++)
                CP16(dst + c * 4096, ps[c] + tid * 16);
            #pragma unroll
            for (int c = 0; c < NREG; c++) ps[c] += 4096;
        }
        CP_COMMIT();
    }

    // ---- epilogue ----
    #pragma unroll
    for (int mf = 0; mf < MF; mf++) {
        const int r0 = bm + wm + mf * 16 + g;
        #pragma unroll
        for (int nf = 0; nf < 4; nf++) {
            const int c0 = bn + wn + nf * 8 + 2 * t4;
            const float2 bv = *(const float2*)(bias + c0);
            float v00 = acc[mf][nf][0] + bv.x;
            float v01 = acc[mf][nf][1] + bv.y;
            float v10 = acc[mf][nf][2] + bv.x;
            float v11 = acc[mf][nf][3] + bv.y;
            if (EPI == 2) {
                v00 = v00 * 0.5f * (1.0f + erff(v00 * 0.70710678118654752f));
                v01 = v01 * 0.5f * (1.0f + erff(v01 * 0.70710678118654752f));
                v10 = v10 * 0.5f * (1.0f + erff(v10 * 0.70710678118654752f));
                v11 = v11 * 0.5f * (1.0f + erff(v11 * 0.70710678118654752f));
                uint8_t* C = (uint8_t*)Cout;
                store_split2(C, N, r0,     c0, v00, v01);
                store_split2(C, N, r0 + 8, c0, v10, v11);
            } else {
                float* C = (float*)Cout;
                const size_t i0 = (size_t)r0 * N + c0;
                const size_t i1 = (size_t)(r0 + 8) * N + c0;
                if (EPI == 1) {
                    const float2 r0v = *(const float2*)(res + i0);
                    const float2 r1v = *(const float2*)(res + i1);
                    v00 += r0v.x; v01 += r0v.y; v10 += r1v.x; v11 += r1v.y;
                }
                *(float2*)(C + i0) = make_float2(v00, v01);
                *(float2*)(C + i1) = make_float2(v10, v11);
            }
        }
    }
}

// ---------------- fp16 single-term GEMM (terminal vocab projection) ----------
// TM=128 x 128, 8 KB/stage (4 blocks of 2 KB), 4 stages, 16 MMA/stage.
__global__ __launch_bounds__(256, 1)
void gemm_h(const uint8_t* __restrict__ A, const uint8_t* __restrict__ W,
            const float* __restrict__ bias, float* __restrict__ C,
            int M, int N, int K) {
    constexpr int ST   = 8192;
    constexpr int NSTG = 4;

    extern __shared__ uint8_t smem[];
    const uint32_t sb = smem_u32(smem);

    const int tid = threadIdx.x;
    const int bm = blockIdx.x * 128;
    const int bn = blockIdx.y * 128;
    const int wid = tid >> 5, lane = tid & 31;
    const int g = lane >> 2, t4 = lane & 3;
    const int wm = (wid >> 2) * 64;
    const int wn = (wid & 3) * 32;

    const int S = K >> 4;   // 32 stages

    // each thread copies two 16B lines per stage; precompute their block ptrs
    const int o0 = tid * 16;          // [0, 4096): blocks 0-1 (A)
    const int o1 = 4096 + tid * 16;   // [4096, 8192): blocks 2-3 (W)
    const uint8_t* src0;
    const uint8_t* src1;
    {
        const int mt0 = blockIdx.x * 2;
        const int nt0 = blockIdx.y * 2;
        const uint8_t* blkp[4];
        blkp[0] = A + (size_t)(mt0 + 0) * S * 2048;
        blkp[1] = A + (size_t)(mt0 + 1) * S * 2048;
        blkp[2] = W + (size_t)(nt0 + 0) * S * 2048;
        blkp[3] = W + (size_t)(nt0 + 1) * S * 2048;
        src0 = blkp[o0 >> 11] + (o0 & 2047);
        src1 = blkp[o1 >> 11] + (o1 & 2047);
    }

    const int sel = lane >> 3, ri = lane & 7;
    uint32_t aOff[4], bOff[2];
    #pragma unroll
    for (int mf = 0; mf < 4; mf++) {
        const int m = wm + mf * 16 + (sel & 1) * 8 + ri;
        aOff[mf] = tile_off_h(m, sel >> 1);
    }
    #pragma unroll
    for (int p = 0; p < 2; p++) {
        const int n = wn + p * 16 + (sel >> 1) * 8 + ri;
        bOff[p] = 4096 + tile_off_h(n, sel & 1);
    }

    float acc[4][4][4];
    #pragma unroll
    for (int i = 0; i < 4; i++)
        #pragma unroll
        for (int j = 0; j < 4; j++)
            #pragma unroll
            for (int c = 0; c < 4; c++) acc[i][j][c] = 0.f;

    #pragma unroll
    for (int s = 0; s < NSTG - 1; s++) {
        const uint32_t dst = sb + s * ST;
        CP16(dst + o0, src0);
        CP16(dst + o1, src1);
        src0 += 2048; src1 += 2048;
        CP_COMMIT();
    }

    for (int s = 0; s < S; s++) {
        CP_WAIT2();
        __syncthreads();

        const uint32_t stg = sb + (uint32_t)((s & 3) * ST);
        uint32_t aF[4][4], bF[2][4];
        #pragma unroll
        for (int mf = 0; mf < 4; mf++) LDSM4(aF[mf], stg + aOff[mf]);
        #pragma unroll
        for (int p = 0; p < 2; p++)    LDSM4(bF[p], stg + bOff[p]);

        #pragma unroll
        for (int mf = 0; mf < 4; mf++)
            #pragma unroll
            for (int nf = 0; nf < 4; nf++) {
                const int p = nf >> 1, q = (nf & 1) * 2;
                MMA_FP16(acc[mf][nf], aF[mf][0], aF[mf][1], aF[mf][2], aF[mf][3],
                         bF[p][q], bF[p][q + 1]);
            }

        if (s + NSTG - 1 < S) {
            const uint32_t dst = sb + (uint32_t)(((s + NSTG - 1) & 3) * ST);
            CP16(dst + o0, src0);
            CP16(dst + o1, src1);
            src0 += 2048; src1 += 2048;
        }
        CP_COMMIT();
    }

    #pragma unroll
    for (int mf = 0; mf < 4; mf++) {
        const int r0 = bm + wm + mf * 16 + g;
        #pragma unroll
        for (int nf = 0; nf < 4; nf++) {
            const int c0 = bn + wn + nf * 8 + 2 * t4;
            const float2 bv = *(const float2*)(bias + c0);
            const size_t i0 = (size_t)r0 * N + c0;
            const size_t i1 = (size_t)(r0 + 8) * N + c0;
            *(float2*)(C + i0) = make_float2(acc[mf][nf][0] + bv.x, acc[mf][nf][1] + bv.y);
            *(float2*)(C + i1) = make_float2(acc[mf][nf][2] + bv.x, acc[mf][nf][3] + bv.y);
        }
    }
}

// ---------------- launch ----------------
extern "C" void kernel_launch(void* const* d_in, const int* in_sizes, int n_in,
                              void* d_out, int out_size) {
    const float* patches        = (const float*)d_in[0];
    const float* masked_token   = (const float*)d_in[3];
    const float* partial_params = (const float*)d_in[4];
    const float* emb_w          = (const float*)d_in[5];
    const float* emb_b          = (const float*)d_in[6];
    const float* ln1_g          = (const float*)d_in[7];
    const float* ln1_b          = (const float*)d_in[8];
    const float* in_proj_w      = (const float*)d_in[9];
    const float* in_proj_b      = (const float*)d_in[10];
    const float* out_proj_w     = (const float*)d_in[11];
    const float* out_proj_b     = (const float*)d_in[12];
    const float* rel_pos        = (const float*)d_in[13];
    const float* ln2_g          = (const float*)d_in[14];
    const float* ln2_b          = (const float*)d_in[15];
    const float* ffn_w1         = (const float*)d_in[16];
    const float* ffn_b1         = (const float*)d_in[17];
    const float* ffn_w2         = (const float*)d_in[18];
    const float* ffn_b2         = (const float*)d_in[19];
    const float* outp_w         = (const float*)d_in[20];
    const float* outp_b         = (const float*)d_in[21];
    float* out = (float*)d_out;

    float *x, *qkv;
    uint8_t *xn, *o, *h, *xf, *win, *wo, *w1, *w2, *wv;
    cudaGetSymbolAddress((void**)&x,   g_x);
    cudaGetSymbolAddress((void**)&qkv, g_qkv);
    cudaGetSymbolAddress((void**)&xn,  s_xn);
    cudaGetSymbolAddress((void**)&o,   s_o);
    cudaGetSymbolAddress((void**)&h,   s_h);
    cudaGetSymbolAddress((void**)&xf,  s_xf);
    cudaGetSymbolAddress((void**)&win, s_win);
    cudaGetSymbolAddress((void**)&wo,  s_wo);
    cudaGetSymbolAddress((void**)&w1,  s_w1);
    cudaGetSymbolAddress((void**)&w2,  s_w2);
    cudaGetSymbolAddress((void**)&wv,  s_wv);

    cudaFuncSetAttribute(attn_kernel, cudaFuncAttributeMaxDynamicSharedMemorySize, ATTN_SMEM);
    cudaFuncSetAttribute(gemm_split<64, 0>, cudaFuncAttributeMaxDynamicSharedMemorySize, 49152);
    cudaFuncSetAttribute(gemm_split<64, 1>, cudaFuncAttributeMaxDynamicSharedMemorySize, 49152);
    cudaFuncSetAttribute(gemm_split<128, 2>, cudaFuncAttributeMaxDynamicSharedMemorySize, 65536);
    cudaFuncSetAttribute(gemm_h, cudaFuncAttributeMaxDynamicSharedMemorySize, 32768);

    // ---- convert all weights ----
    {
        int nc;
        nc = NL * 3 * ND * ND / 8;  convert_w<<<(nc + 255) / 256, 256>>>(in_proj_w,  win, ND, nc);
        nc = NL * ND * ND / 8;      convert_w<<<(nc + 255) / 256, 256>>>(out_proj_w, wo,  ND, nc);
        nc = NL * NF * ND / 8;      convert_w<<<(nc + 255) / 256, 256>>>(ffn_w1,     w1,  ND, nc);
        nc = NL * ND * NF / 8;      convert_w<<<(nc + 255) / 256, 256>>>(ffn_w2,     w2,  NF, nc);
        nc = (int)((size_t)NV * ND / 8);
        convert_w_h<<<(nc + 255) / 256, 256>>>(outp_w, wv, ND, nc);
    }

    tokenize_embed_kernel<<<NTOK, 128>>>(patches, masked_token, partial_params, emb_w, emb_b);

    for (int l = 0; l < NL; l++) {
        ln_kernel<<<NTOK, 256>>>(x, xn, ln1_g + l * ND, ln1_b + l * ND);

        gemm_split<64, 0><<<dim3(NTOK / 64, 3 * ND / 128), 256, 49152>>>(
            xn, win + (size_t)l * 3 * ND * ND * 4, in_proj_b + l * 3 * ND,
            nullptr, qkv, NTOK, 3 * ND, ND);

        attn_kernel<<<NB * NH * 2, 256, ATTN_SMEM>>>(rel_pos + (size_t)l * NS * NS);

        gemm_split<64, 1><<<dim3(NTOK / 64, ND / 128), 256, 49152>>>(
            o, wo + (size_t)l * ND * ND * 4, out_proj_b + l * ND,
            x, x, NTOK, ND, ND);

        ln_kernel<<<NTOK, 256>>>(x, xn, ln2_g + l * ND, ln2_b + l * ND);

        gemm_split<128, 2><<<dim3(NTOK / 128, NF / 128), 256, 65536>>>(
            xn, w1 + (size_t)l * NF * ND * 4, ffn_b1 + l * NF,
            nullptr, h, NTOK, NF, ND);

        gemm_split<64, 1><<<dim3(NTOK / 64, ND / 128), 256, 49152>>>(
            h, w2 + (size_t)l * ND * NF * 4, ffn_b2 + l * ND,
            x, x, NTOK, ND, NF);
    }

    convert_x_kernel<<<NTOK, 256>>>(x, xf);

    gemm_h<<<dim3(NTOK / 128, NV / 128), 256, 32768>>>(
        xf, wv, outp_b, out, NTOK, NV, ND);
}

// round 10
// speedup vs baseline: 1.3922x; 1.1080x over previous
#include <cuda_runtime.h>
#include <cuda_bf16.h>
#include <cuda_fp16.h>
#include <math.h>
#include <stdint.h>

// ---------------- problem constants ----------------
#define NB   8
#define NS   256
#define NP   16
#define ND   512
#define NH   8
#define HD   64
#define NL   6
#define NF   2048
#define NV   65536
#define NTOK (NB * NS)   // 2048

// ---------------- scratch (device globals; no allocation) ----------------
__device__ float g_x  [NTOK * ND];          // residual stream (fp32)
__device__ float g_qkv[NTOK * 3 * ND];      // qkv projection (fp32)

// split-bf16 tile buffers (hi|lo 2KB blocks of 64 rows x 16 k, swizzled)
__device__ uint8_t s_xn [NTOK * ND * 4];
__device__ uint8_t s_o  [NTOK * ND * 4];
__device__ uint8_t s_h  [NTOK * NF * 4];
__device__ uint8_t s_win[NL * 3 * ND * ND * 4];
__device__ uint8_t s_wo [NL * ND * ND * 4];
__device__ uint8_t s_w1 [NL * NF * ND * 4];
__device__ uint8_t s_w2 [(size_t)NL * ND * NF * 4];
// fp16 single tiles (2KB blocks of 64 rows x 16 k, swizzled) for vocab GEMM
__device__ uint8_t s_xf [NTOK * ND * 2];
__device__ uint8_t s_wv [(size_t)NV * ND * 2];

__device__ __forceinline__ uint32_t smem_u32(const void* p) {
    uint32_t a;
    asm("{ .reg .u64 t; cvta.to.shared.u64 t, %1; cvt.u32.u64 %0, t; }" : "=r"(a) : "l"(p));
    return a;
}

// ---------------- split helpers ----------------
__device__ __forceinline__ void split_pack(float a, float b, unsigned& hi, unsigned& lo) {
    __nv_bfloat16 ha = __float2bfloat16_rn(a);
    __nv_bfloat16 hb = __float2bfloat16_rn(b);
    float ra = a - __bfloat162float(ha);
    float rb = b - __bfloat162float(hb);
    __nv_bfloat162 h2 = __halves2bfloat162(ha, hb);
    __nv_bfloat162 l2 = __floats2bfloat162_rn(ra, rb);
    hi = *(unsigned*)&h2;
    lo = *(unsigned*)&l2;
}
__device__ __forceinline__ void pack8(float4 v0, float4 v1, uint4& hi, uint4& lo) {
    split_pack(v0.x, v0.y, hi.x, lo.x);
    split_pack(v0.z, v0.w, hi.y, lo.y);
    split_pack(v1.x, v1.y, hi.z, lo.z);
    split_pack(v1.z, v1.w, hi.w, lo.w);
}
__device__ __forceinline__ void store_split2(uint8_t* base, int K, int row, int col,
                                             float a, float b) {
    unsigned hi, lo;
    split_pack(a, b, hi, lo);
    size_t blk = (size_t)(row >> 6) * (K >> 4) + (col >> 4);
    uint32_t off = (uint32_t)((row & 63) * 32 +
                   ((((col >> 3) & 1) ^ ((row >> 2) & 1)) << 4) + (col & 7) * 2);
    *(unsigned*)(base + blk * 4096 + off) = hi;
    *(unsigned*)(base + blk * 4096 + 2048 + off) = lo;
}
// fp16 single-tile store of 2 adjacent elements
__device__ __forceinline__ void store_h2(uint8_t* base, int K, int row, int col,
                                         float a, float b) {
    __half2 h = __floats2half2_rn(a, b);
    size_t blk = (size_t)(row >> 6) * (K >> 4) + (col >> 4);
    uint32_t off = (uint32_t)((row & 63) * 32 +
                   ((((col >> 3) & 1) ^ ((row >> 2) & 1)) << 4) + (col & 7) * 2);
    *(__half2*)(base + blk * 2048 + off) = h;
}

// ---------------- weight conversion (fp32 [R,K] -> split tiles) ----------------
__global__ void convert_w(const float* __restrict__ src, uint8_t* __restrict__ dst,
                          int K, int nChunks) {
    int ct = blockIdx.x * 256 + threadIdx.x;
    if (ct >= nChunks) return;
    int within = ct & 127;
    int blk = ct >> 7;
    int r = within >> 1, kc = within & 1;
    int stages = K >> 4;
    int rt = blk / stages, s = blk - rt * stages;
    const float* p = src + (size_t)(rt * 64 + r) * K + s * 16 + kc * 8;
    float4 v0 = *(const float4*)p, v1 = *(const float4*)(p + 4);
    uint4 hi, lo;
    pack8(v0, v1, hi, lo);
    uint32_t off = (uint32_t)(r * 32 + ((kc ^ ((r >> 2) & 1)) << 4));
    *(uint4*)(dst + (size_t)blk * 4096 + off) = hi;
    *(uint4*)(dst + (size_t)blk * 4096 + 2048 + off) = lo;
}

// weight conversion (fp32 [R,K] -> fp16 single tiles)
__global__ void convert_w_h(const float* __restrict__ src, uint8_t* __restrict__ dst,
                            int K, int nChunks) {
    int ct = blockIdx.x * 256 + threadIdx.x;
    if (ct >= nChunks) return;
    int within = ct & 127;
    int blk = ct >> 7;
    int r = within >> 1, kc = within & 1;
    int stages = K >> 4;
    int rt = blk / stages, s = blk - rt * stages;
    const float* p = src + (size_t)(rt * 64 + r) * K + s * 16 + kc * 8;
    float4 v0 = *(const float4*)p, v1 = *(const float4*)(p + 4);
    __half2 h0 = __floats2half2_rn(v0.x, v0.y);
    __half2 h1 = __floats2half2_rn(v0.z, v0.w);
    __half2 h2 = __floats2half2_rn(v1.x, v1.y);
    __half2 h3 = __floats2half2_rn(v1.z, v1.w);
    uint4 hv;
    hv.x = *(unsigned*)&h0; hv.y = *(unsigned*)&h1;
    hv.z = *(unsigned*)&h2; hv.w = *(unsigned*)&h3;
    uint32_t off = (uint32_t)(r * 32 + ((kc ^ ((r >> 2) & 1)) << 4));
    *(uint4*)(dst + (size_t)blk * 2048 + off) = hv;
}

__global__ void convert_x_kernel(const float* __restrict__ src, uint8_t* __restrict__ dst) {
    const int row = blockIdx.x;
    float2 v = ((const float2*)(src + (size_t)row * ND))[threadIdx.x];
    store_h2(dst, ND, row, threadIdx.x * 2, v.x, v.y);
}

// ---------------- tokenize + embed ----------------
__global__ void tokenize_embed_kernel(const float* __restrict__ patches,
                                      const float* __restrict__ masked_token,
                                      const float* __restrict__ partial_params,
                                      const float* __restrict__ emb_w,
                                      const float* __restrict__ emb_b) {
    const int tok = blockIdx.x;
    const int tid = threadIdx.x;   // 128 threads
    __shared__ float proc[NP];

    if (tid == 0) {
        const float* f = patches + (size_t)tok * NP;
        bool anyMask = false, anyBin = false;
        int firstBin = -1;
        float fp[NP];
        #pragma unroll
        for (int p = 0; p < NP; p++) {
            float v = f[p];
            fp[p] = v;
            bool m = fabsf(v - 0.5f) < 0.1f;
            if (m) anyMask = true;
            else { anyBin = true; if (firstBin < 0) firstBin = p; }
        }
        if (!anyBin) {
            #pragma unroll
            for (int p = 0; p < NP; p++) proc[p] = masked_token[p];
        } else if (anyMask) {
            int ptok = firstBin * 2 + (int)rintf(fp[firstBin]);
            const float* pp = partial_params + ptok * NP;
            #pragma unroll
            for (int p = 0; p < NP; p++) proc[p] = pp[p];
        } else {
            #pragma unroll
            for (int p = 0; p < NP; p++) proc[p] = fp[p];
        }
    }
    __syncthreads();

    for (int d = tid; d < ND; d += blockDim.x) {
        const float* w = emb_w + d * NP;
        float s = emb_b[d];
        #pragma unroll
        for (int p = 0; p < NP; p++) s += proc[p] * w[p];
        g_x[(size_t)tok * ND + d] = s;
    }
}

// ---------------- layernorm (fp32 in -> split-bf16 tile out) ----------------
__global__ void ln_kernel(const float* __restrict__ in, uint8_t* __restrict__ out,
                          const float* __restrict__ gamma, const float* __restrict__ beta) {
    const int tok = blockIdx.x;
    const int tid = threadIdx.x;   // 256
    const float2 v = ((const float2*)(in + (size_t)tok * ND))[tid];

    float s  = v.x + v.y;
    float sq = v.x * v.x + v.y * v.y;
    #pragma unroll
    for (int off = 16; off; off >>= 1) {
        s  += __shfl_xor_sync(0xffffffffu, s,  off);
        sq += __shfl_xor_sync(0xffffffffu, sq, off);
    }
    __shared__ float rs[8], rq[8], stats[2];
    if ((tid & 31) == 0) { rs[tid >> 5] = s; rq[tid >> 5] = sq; }
    __syncthreads();
    if (tid == 0) {
        float S = 0.f, Q = 0.f;
        #pragma unroll
        for (int i = 0; i < 8; i++) { S += rs[i]; Q += rq[i]; }
        float mean = S * (1.0f / ND);
        float var  = Q * (1.0f / ND) - mean * mean;
        stats[0] = mean;
        stats[1] = rsqrtf(var + 1e-5f);
    }
    __syncthreads();
    const float mean = stats[0], inv = stats[1];
    float2 g2 = ((const float2*)gamma)[tid];
    float2 b2 = ((const float2*)beta)[tid];
    float ox = (v.x - mean) * inv * g2.x + b2.x;
    float oy = (v.y - mean) * inv * g2.y + b2.y;
    store_split2(out, ND, tok, tid * 2, ox, oy);
}

// ---------------- fused attention (smem K/V, split output) ----------------
#define ATTN_SMEM (192 * 1024)

__global__ __launch_bounds__(256) void attn_kernel(const float* __restrict__ rel) {
    extern __shared__ float sm[];
    float* Ks = sm;            // [256][64] rotated rows
    float* Vs = sm + 16384;    // [256][64]
    float* Qs = sm + 32768;    // [128][64]
    float* Wb = sm + 40960;    // [8 warps][256][4]

    const int idx = blockIdx.x;
    const int qc = idx & 1;
    const int h  = (idx >> 1) & (NH - 1);
    const int b  = idx >> 4;
    const int tid = threadIdx.x, wid = tid >> 5, L = tid & 31;

    const size_t base = (size_t)(b * NS) * (3 * ND) + h * HD;

    {
        const int dc = (tid & 15) * 4;
        int t = tid >> 4;
        #pragma unroll 4
        for (int pass = 0; pass < 16; pass++, t += 16) {
            const float* kR = g_qkv + base + ND + (size_t)t * (3 * ND);
            float4 kv = *(const float4*)(kR + dc);
            const int p = (dc + 4 * (t & 15)) & 63;
            *(float4*)(Ks + t * 64 + p) = kv;
            const float* vR = g_qkv + base + 2 * ND + (size_t)t * (3 * ND);
            *(float4*)(Vs + t * 64 + dc) = *(const float4*)(vR + dc);
        }
        int q = tid >> 4;
        #pragma unroll 4
        for (int pass = 0; pass < 8; pass++, q += 16) {
            const float* qR = g_qkv + base + (size_t)(qc * 128 + q) * (3 * ND);
            *(float4*)(Qs + q * 64 + dc) = *(const float4*)(qR + dc);
        }
    }
    __syncthreads();

    float* wb = Wb + wid * 1024;
    const int rot = 4 * (L & 15);

    for (int g4 = 0; g4 < 4; g4++) {
        const int q0 = wid * 16 + g4 * 4;
        const int sRow = qc * 128 + q0;

        float sc[4][8];
        #pragma unroll
        for (int qi = 0; qi < 4; qi++)
            #pragma unroll
            for (int j = 0; j < 8; j++) sc[qi][j] = 0.f;

        #pragma unroll
        for (int dd = 0; dd < 16; dd++) {
            const int d = dd * 4;
            float4 qv[4];
            #pragma unroll
            for (int qi = 0; qi < 4; qi++)
                qv[qi] = *(const float4*)(Qs + (q0 + qi) * 64 + d);
            const int p = (d + rot) & 63;
            #pragma unroll
            for (int j = 0; j < 8; j++) {
                float4 k4 = *(const float4*)(Ks + (L + 32 * j) * 64 + p);
                #pragma unroll
                for (int qi = 0; qi < 4; qi++)
                    sc[qi][j] += qv[qi].x * k4.x + qv[qi].y * k4.y +
                                 qv[qi].z * k4.z + qv[qi].w * k4.w;
            }
        }

        #pragma unroll
        for (int qi = 0; qi < 4; qi++) {
            const float* rrow = rel + (size_t)(sRow + qi) * NS;
            float m = -1e30f;
            #pragma unroll
            for (int j = 0; j < 8; j++) {
                float v = sc[qi][j] * 0.125f + rrow[L + 32 * j];
                sc[qi][j] = v;
                m = fmaxf(m, v);
            }
            #pragma unroll
            for (int off = 16; off; off >>= 1)
                m = fmaxf(m, __shfl_xor_sync(0xffffffffu, m, off));
            float ssum = 0.f;
            #pragma unroll
            for (int j = 0; j < 8; j++) { sc[qi][j] = expf(sc[qi][j] - m); ssum += sc[qi][j]; }
            #pragma unroll
            for (int off = 16; off; off >>= 1)
                ssum += __shfl_xor_sync(0xffffffffu, ssum, off);
            const float inv = 1.0f / ssum;
            #pragma unroll
            for (int j = 0; j < 8; j++) sc[qi][j] *= inv;
        }

        #pragma unroll
        for (int j = 0; j < 8; j++)
            *(float4*)(wb + (L + 32 * j) * 4) =
                make_float4(sc[0][j], sc[1][j], sc[2][j], sc[3][j]);
        __syncwarp();

        float2 acc[4];
        #pragma unroll
        for (int qi = 0; qi < 4; qi++) acc[qi] = make_float2(0.f, 0.f);
        #pragma unroll 4
        for (int t = 0; t < NS; t++) {
            float2 v2 = *(const float2*)(Vs + t * 64 + 2 * L);
            float4 w4 = *(const float4*)(wb + t * 4);
            acc[0].x += w4.x * v2.x; acc[0].y += w4.x * v2.y;
            acc[1].x += w4.y * v2.x; acc[1].y += w4.y * v2.y;
            acc[2].x += w4.z * v2.x; acc[2].y += w4.z * v2.y;
            acc[3].x += w4.w * v2.x; acc[3].y += w4.w * v2.y;
        }
        #pragma unroll
        for (int qi = 0; qi < 4; qi++)
            store_split2(s_o, ND, b * NS + sRow + qi, h * HD + 2 * L,
                         acc[qi].x, acc[qi].y);
        __syncwarp();
    }
}

// ---------------- GEMM common macros ----------------
#define MMA_BF16(d, a0,a1,a2,a3, b0,b1)                                         \
    asm volatile("mma.sync.aligned.m16n8k16.row.col.f32.bf16.bf16.f32 "         \
                 "{%0,%1,%2,%3}, {%4,%5,%6,%7}, {%8,%9}, {%0,%1,%2,%3};"        \
                 : "+f"(d[0]), "+f"(d[1]), "+f"(d[2]), "+f"(d[3])               \
                 : "r"(a0), "r"(a1), "r"(a2), "r"(a3), "r"(b0), "r"(b1))

#define MMA_FP16(d, a0,a1,a2,a3, b0,b1)                                         \
    asm volatile("mma.sync.aligned.m16n8k16.row.col.f32.f16.f16.f32 "           \
                 "{%0,%1,%2,%3}, {%4,%5,%6,%7}, {%8,%9}, {%0,%1,%2,%3};"        \
                 : "+f"(d[0]), "+f"(d[1]), "+f"(d[2]), "+f"(d[3])               \
                 : "r"(a0), "r"(a1), "r"(a2), "r"(a3), "r"(b0), "r"(b1))

#define LDSM4(r, addr)                                                          \
    asm volatile("ldmatrix.sync.aligned.m8n8.x4.shared.b16 {%0,%1,%2,%3}, [%4];"\
                 : "=r"((r)[0]), "=r"((r)[1]), "=r"((r)[2]), "=r"((r)[3])       \
                 : "r"(addr))

#define CP16(dst, src)                                                          \
    asm volatile("cp.async.cg.shared.global [%0], [%1], 16;" :: "r"(dst), "l"(src))
#define CP_COMMIT() asm volatile("cp.async.commit_group;" ::: "memory")
#define CP_WAIT2()  asm volatile("cp.async.wait_group 2;" ::: "memory")

__device__ __forceinline__ uint32_t tile_off(int m, int kc) {
    return (uint32_t)((m >> 6) * 4096 + (m & 63) * 32 +
                      ((kc ^ ((m >> 2) & 1)) << 4));
}
__device__ __forceinline__ uint32_t tile_off_h(int m, int kc) {
    return (uint32_t)((m >> 6) * 2048 + (m & 63) * 32 +
                      ((kc ^ ((m >> 2) & 1)) << 4));
}

// ---------------- split-bf16 GEMM (round-6 verified config) ----------------
// MINB: min CTAs/SM hint (2 for TM=64 -> caps regs at 128, spill-safe there).
template <int TM, int EPI, int MINB>
__global__ __launch_bounds__(256, MINB)
void gemm_split(const uint8_t* __restrict__ A, const uint8_t* __restrict__ W,
                const float* __restrict__ bias, const float* __restrict__ res,
                void* __restrict__ Cout, int M, int N, int K) {
    constexpr int ABLK  = TM / 64;
    constexpr int NREG  = ABLK + 2;
    constexpr int ST    = NREG * 4096;
    constexpr int AWOFF = ABLK * 4096;
    constexpr int MF    = TM / 32;
    constexpr int NSTG  = 4;

    extern __shared__ uint8_t smem[];
    const uint32_t sb = smem_u32(smem);

    const int tid = threadIdx.x;
    const int bm = blockIdx.x * TM;
    const int bn = blockIdx.y * 128;
    const int wid = tid >> 5, lane = tid & 31;
    const int g = lane >> 2, t4 = lane & 3;
    const int wm = (wid >> 2) * (TM / 2);
    const int wn = (wid & 3) * 32;

    const int S = K >> 4;

    const uint8_t* ps[NREG];
    {
        const int mt0 = blockIdx.x * ABLK;
        const int nt0 = blockIdx.y * 2;
        #pragma unroll
        for (int i = 0; i < ABLK; i++)
            ps[i] = A + (size_t)(mt0 + i) * S * 4096;
        ps[ABLK]     = W + (size_t)nt0 * S * 4096;
        ps[ABLK + 1] = W + (size_t)(nt0 + 1) * S * 4096;
    }

    const int sel = lane >> 3, ri = lane & 7;
    uint32_t aOffH[MF], bOffH[2];
    #pragma unroll
    for (int mf = 0; mf < MF; mf++) {
        const int m = wm + mf * 16 + (sel & 1) * 8 + ri;
        aOffH[mf] = tile_off(m, sel >> 1);
    }
    #pragma unroll
    for (int p = 0; p < 2; p++) {
        const int n = wn + p * 16 + (sel >> 1) * 8 + ri;
        bOffH[p] = AWOFF + tile_off(n, sel & 1);
    }

    float acc[MF][4][4];
    #pragma unroll
    for (int i = 0; i < MF; i++)
        #pragma unroll
        for (int j = 0; j < 4; j++)
            #pragma unroll
            for (int c = 0; c < 4; c++) acc[i][j][c] = 0.f;

    #pragma unroll
    for (int s = 0; s < NSTG - 1; s++) {
        const uint32_t dst = sb + s * ST + tid * 16;
        #pragma unroll
        for (int c = 0; c < NREG; c++)
            CP16(dst + c * 4096, ps[c] + tid * 16);
        #pragma unroll
        for (int c = 0; c < NREG; c++) ps[c] += 4096;
        CP_COMMIT();
    }

    for (int s = 0; s < S; s++) {
        CP_WAIT2();
        __syncthreads();

        const uint32_t stg = sb + (uint32_t)((s & 3) * ST);
        uint32_t aH[MF][4], aL[MF][4], bH[2][4], bL[2][4];
        #pragma unroll
        for (int mf = 0; mf < MF; mf++) {
            LDSM4(aH[mf], stg + aOffH[mf]);
            LDSM4(aL[mf], stg + aOffH[mf] + 2048);
        }
        #pragma unroll
        for (int p = 0; p < 2; p++) {
            LDSM4(bH[p], stg + bOffH[p]);
            LDSM4(bL[p], stg + bOffH[p] + 2048);
        }
        #pragma unroll
        for (int mf = 0; mf < MF; mf++)
            #pragma unroll
            for (int nf = 0; nf < 4; nf++) {
                const int p = nf >> 1, q = (nf & 1) * 2;
                MMA_BF16(acc[mf][nf], aH[mf][0], aH[mf][1], aH[mf][2], aH[mf][3],
                         bH[p][q], bH[p][q + 1]);
                MMA_BF16(acc[mf][nf], aH[mf][0], aH[mf][1], aH[mf][2], aH[mf][3],
                         bL[p][q], bL[p][q + 1]);
                MMA_BF16(acc[mf][nf], aL[mf][0], aL[mf][1], aL[mf][2], aL[mf][3],
                         bH[p][q], bH[p][q + 1]);
            }

        if (s + NSTG - 1 < S) {
            const uint32_t dst = sb + (uint32_t)(((s + NSTG - 1) & 3) * ST) + tid * 16;
            #pragma unroll
            for (int c = 0; c < NREG; c++)
                CP16(dst + c * 4096, ps[c] + tid * 16);
            #pragma unroll
            for (int c = 0; c < NREG; c++) ps[c] += 4096;
        }
        CP_COMMIT();
    }

    // ---- epilogue ----
    #pragma unroll
    for (int mf = 0; mf < MF; mf++) {
        const int r0 = bm + wm + mf * 16 + g;
        #pragma unroll
        for (int nf = 0; nf < 4; nf++) {
            const int c0 = bn + wn + nf * 8 + 2 * t4;
            const float2 bv = *(const float2*)(bias + c0);
            float v00 = acc[mf][nf][0] + bv.x;
            float v01 = acc[mf][nf][1] + bv.y;
            float v10 = acc[mf][nf][2] + bv.x;
            float v11 = acc[mf][nf][3] + bv.y;
            if (EPI == 2) {
                v00 = v00 * 0.5f * (1.0f + erff(v00 * 0.70710678118654752f));
                v01 = v01 * 0.5f * (1.0f + erff(v01 * 0.70710678118654752f));
                v10 = v10 * 0.5f * (1.0f + erff(v10 * 0.70710678118654752f));
                v11 = v11 * 0.5f * (1.0f + erff(v11 * 0.70710678118654752f));
                uint8_t* C = (uint8_t*)Cout;
                store_split2(C, N, r0,     c0, v00, v01);
                store_split2(C, N, r0 + 8, c0, v10, v11);
            } else {
                float* C = (float*)Cout;
                const size_t i0 = (size_t)r0 * N + c0;
                const size_t i1 = (size_t)(r0 + 8) * N + c0;
                if (EPI == 1) {
                    const float2 r0v = *(const float2*)(res + i0);
                    const float2 r1v = *(const float2*)(res + i1);
                    v00 += r0v.x; v01 += r0v.y; v10 += r1v.x; v11 += r1v.y;
                }
                *(float2*)(C + i0) = make_float2(v00, v01);
                *(float2*)(C + i1) = make_float2(v10, v11);
            }
        }
    }
}

// ---------------- fp16 single-term GEMM (terminal vocab projection) ----------
// TM=128 x 128, 8 KB/stage, 4 stages. minBlocks=2 -> <=128 regs, 2 CTAs/SM.
__global__ __launch_bounds__(256, 2)
void gemm_h(const uint8_t* __restrict__ A, const uint8_t* __restrict__ W,
            const float* __restrict__ bias, float* __restrict__ C,
            int M, int N, int K) {
    constexpr int ST   = 8192;
    constexpr int NSTG = 4;

    extern __shared__ uint8_t smem[];
    const uint32_t sb = smem_u32(smem);

    const int tid = threadIdx.x;
    const int bm = blockIdx.x * 128;
    const int bn = blockIdx.y * 128;
    const int wid = tid >> 5, lane = tid & 31;
    const int g = lane >> 2, t4 = lane & 3;
    const int wm = (wid >> 2) * 64;
    const int wn = (wid & 3) * 32;

    const int S = K >> 4;   // 32 stages

    const int o0 = tid * 16;          // [0, 4096): blocks 0-1 (A)
    const int o1 = 4096 + tid * 16;   // [4096, 8192): blocks 2-3 (W)
    const uint8_t* src0;
    const uint8_t* src1;
    {
        const int mt0 = blockIdx.x * 2;
        const int nt0 = blockIdx.y * 2;
        const uint8_t* blkp[4];
        blkp[0] = A + (size_t)(mt0 + 0) * S * 2048;
        blkp[1] = A + (size_t)(mt0 + 1) * S * 2048;
        blkp[2] = W + (size_t)(nt0 + 0) * S * 2048;
        blkp[3] = W + (size_t)(nt0 + 1) * S * 2048;
        src0 = blkp[o0 >> 11] + (o0 & 2047);
        src1 = blkp[o1 >> 11] + (o1 & 2047);
    }

    const int sel = lane >> 3, ri = lane & 7;
    uint32_t aOff[4], bOff[2];
    #pragma unroll
    for (int mf = 0; mf < 4; mf++) {
        const int m = wm + mf * 16 + (sel & 1) * 8 + ri;
        aOff[mf] = tile_off_h(m, sel >> 1);
    }
    #pragma unroll
    for (int p = 0; p < 2; p++) {
        const int n = wn + p * 16 + (sel >> 1) * 8 + ri;
        bOff[p] = 4096 + tile_off_h(n, sel & 1);
    }

    float acc[4][4][4];
    #pragma unroll
    for (int i = 0; i < 4; i++)
        #pragma unroll
        for (int j = 0; j < 4; j++)
            #pragma unroll
            for (int c = 0; c < 4; c++) acc[i][j][c] = 0.f;

    #pragma unroll
    for (int s = 0; s < NSTG - 1; s++) {
        const uint32_t dst = sb + s * ST;
        CP16(dst + o0, src0);
        CP16(dst + o1, src1);
        src0 += 2048; src1 += 2048;
        CP_COMMIT();
    }

    for (int s = 0; s < S; s++) {
        CP_WAIT2();
        __syncthreads();

        const uint32_t stg = sb + (uint32_t)((s & 3) * ST);
        uint32_t aF[4][4], bF[2][4];
        #pragma unroll
        for (int mf = 0; mf < 4; mf++) LDSM4(aF[mf], stg + aOff[mf]);
        #pragma unroll
        for (int p = 0; p < 2; p++)    LDSM4(bF[p], stg + bOff[p]);

        #pragma unroll
        for (int mf = 0; mf < 4; mf++)
            #pragma unroll
            for (int nf = 0; nf < 4; nf++) {
                const int p = nf >> 1, q = (nf & 1) * 2;
                MMA_FP16(acc[mf][nf], aF[mf][0], aF[mf][1], aF[mf][2], aF[mf][3],
                         bF[p][q], bF[p][q + 1]);
            }

        if (s + NSTG - 1 < S) {
            const uint32_t dst = sb + (uint32_t)(((s + NSTG - 1) & 3) * ST);
            CP16(dst + o0, src0);
            CP16(dst + o1, src1);
            src0 += 2048; src1 += 2048;
        }
        CP_COMMIT();
    }

    #pragma unroll
    for (int mf = 0; mf < 4; mf++) {
        const int r0 = bm + wm + mf * 16 + g;
        #pragma unroll
        for (int nf = 0; nf < 4; nf++) {
            const int c0 = bn + wn + nf * 8 + 2 * t4;
            const float2 bv = *(const float2*)(bias + c0);
            const size_t i0 = (size_t)r0 * N + c0;
            const size_t i1 = (size_t)(r0 + 8) * N + c0;
            *(float2*)(C + i0) = make_float2(acc[mf][nf][0] + bv.x, acc[mf][nf][1] + bv.y);
            *(float2*)(C + i1) = make_float2(acc[mf][nf][2] + bv.x, acc[mf][nf][3] + bv.y);
        }
    }
}

// ---------------- launch ----------------
extern "C" void kernel_launch(void* const* d_in, const int* in_sizes, int n_in,
                              void* d_out, int out_size) {
    const float* patches        = (const float*)d_in[0];
    const float* masked_token   = (const float*)d_in[3];
    const float* partial_params = (const float*)d_in[4];
    const float* emb_w          = (const float*)d_in[5];
    const float* emb_b          = (const float*)d_in[6];
    const float* ln1_g          = (const float*)d_in[7];
    const float* ln1_b          = (const float*)d_in[8];
    const float* in_proj_w      = (const float*)d_in[9];
    const float* in_proj_b      = (const float*)d_in[10];
    const float* out_proj_w     = (const float*)d_in[11];
    const float* out_proj_b     = (const float*)d_in[12];
    const float* rel_pos        = (const float*)d_in[13];
    const float* ln2_g          = (const float*)d_in[14];
    const float* ln2_b          = (const float*)d_in[15];
    const float* ffn_w1         = (const float*)d_in[16];
    const float* ffn_b1         = (const float*)d_in[17];
    const float* ffn_w2         = (const float*)d_in[18];
    const float* ffn_b2         = (const float*)d_in[19];
    const float* outp_w         = (const float*)d_in[20];
    const float* outp_b         = (const float*)d_in[21];
    float* out = (float*)d_out;

    float *x, *qkv;
    uint8_t *xn, *o, *h, *xf, *win, *wo, *w1, *w2, *wv;
    cudaGetSymbolAddress((void**)&x,   g_x);
    cudaGetSymbolAddress((void**)&qkv, g_qkv);
    cudaGetSymbolAddress((void**)&xn,  s_xn);
    cudaGetSymbolAddress((void**)&o,   s_o);
    cudaGetSymbolAddress((void**)&h,   s_h);
    cudaGetSymbolAddress((void**)&xf,  s_xf);
    cudaGetSymbolAddress((void**)&win, s_win);
    cudaGetSymbolAddress((void**)&wo,  s_wo);
    cudaGetSymbolAddress((void**)&w1,  s_w1);
    cudaGetSymbolAddress((void**)&w2,  s_w2);
    cudaGetSymbolAddress((void**)&wv,  s_wv);

    cudaFuncSetAttribute(attn_kernel, cudaFuncAttributeMaxDynamicSharedMemorySize, ATTN_SMEM);
    cudaFuncSetAttribute((const void*)gemm_split<64, 0, 2>, cudaFuncAttributeMaxDynamicSharedMemorySize, 49152);
    cudaFuncSetAttribute((const void*)gemm_split<64, 1, 2>, cudaFuncAttributeMaxDynamicSharedMemorySize, 49152);
    cudaFuncSetAttribute((const void*)gemm_split<128, 2, 1>, cudaFuncAttributeMaxDynamicSharedMemorySize, 65536);
    cudaFuncSetAttribute((const void*)gemm_h, cudaFuncAttributeMaxDynamicSharedMemorySize, 32768);

    // ---- convert all weights ----
    {
        int nc;
        nc = NL * 3 * ND * ND / 8;  convert_w<<<(nc + 255) / 256, 256>>>(in_proj_w,  win, ND, nc);
        nc = NL * ND * ND / 8;      convert_w<<<(nc + 255) / 256, 256>>>(out_proj_w, wo,  ND, nc);
        nc = NL * NF * ND / 8;      convert_w<<<(nc + 255) / 256, 256>>>(ffn_w1,     w1,  ND, nc);
        nc = NL * ND * NF / 8;      convert_w<<<(nc + 255) / 256, 256>>>(ffn_w2,     w2,  NF, nc);
        nc = (int)((size_t)NV * ND / 8);
        convert_w_h<<<(nc + 255) / 256, 256>>>(outp_w, wv, ND, nc);
    }

    tokenize_embed_kernel<<<NTOK, 128>>>(patches, masked_token, partial_params, emb_w, emb_b);

    for (int l = 0; l < NL; l++) {
        ln_kernel<<<NTOK, 256>>>(x, xn, ln1_g + l * ND, ln1_b + l * ND);

        gemm_split<64, 0, 2><<<dim3(NTOK / 64, 3 * ND / 128), 256, 49152>>>(
            xn, win + (size_t)l * 3 * ND * ND * 4, in_proj_b + l * 3 * ND,
            nullptr, qkv, NTOK, 3 * ND, ND);

        attn_kernel<<<NB * NH * 2, 256, ATTN_SMEM>>>(rel_pos + (size_t)l * NS * NS);

        gemm_split<64, 1, 2><<<dim3(NTOK / 64, ND / 128), 256, 49152>>>(
            o, wo + (size_t)l * ND * ND * 4, out_proj_b + l * ND,
            x, x, NTOK, ND, ND);

        ln_kernel<<<NTOK, 256>>>(x, xn, ln2_g + l * ND, ln2_b + l * ND);

        gemm_split<128, 2, 1><<<dim3(NTOK / 128, NF / 128), 256, 65536>>>(
            xn, w1 + (size_t)l * NF * ND * 4, ffn_b1 + l * NF,
            nullptr, h, NTOK, NF, ND);

        gemm_split<64, 1, 2><<<dim3(NTOK / 64, ND / 128), 256, 49152>>>(
            h, w2 + (size_t)l * ND * NF * 4, ffn_b2 + l * ND,
            x, x, NTOK, ND, NF);
    }

    convert_x_kernel<<<NTOK, 256>>>(x, xf);

    gemm_h<<<dim3(NTOK / 128, NV / 128), 256, 32768>>>(
        xf, wv, outp_b, out, NTOK, NV, ND);
}

// round 11
// speedup vs baseline: 1.4591x; 1.0481x over previous
#include <cuda_runtime.h>
#include <cuda_bf16.h>
#include <cuda_fp16.h>
#include <math.h>
#include <stdint.h>

// ---------------- problem constants ----------------
#define NB   8
#define NS   256
#define NP   16
#define ND   512
#define NH   8
#define HD   64
#define NL   6
#define NF   2048
#define NV   65536
#define NTOK (NB * NS)   // 2048

// ---------------- scratch (device globals; no allocation) ----------------
__device__ float g_x  [NTOK * ND];          // residual stream (fp32)
__device__ float g_qkv[NTOK * 3 * ND];      // qkv projection (fp32)

// split-bf16 tile buffers (hi|lo 2KB blocks of 64 rows x 16 k, swizzled)
__device__ uint8_t s_xn [NTOK * ND * 4];
__device__ uint8_t s_o  [NTOK * ND * 4];
__device__ uint8_t s_h  [NTOK * NF * 4];
__device__ uint8_t s_win[NL * 3 * ND * ND * 4];
__device__ uint8_t s_wo [NL * ND * ND * 4];
__device__ uint8_t s_w1 [NL * NF * ND * 4];
__device__ uint8_t s_w2 [(size_t)NL * ND * NF * 4];
// fp16 single tiles (2KB blocks of 64 rows x 16 k, swizzled) for vocab GEMM
__device__ uint8_t s_xf [NTOK * ND * 2];
__device__ uint8_t s_wv [(size_t)NV * ND * 2];

__device__ __forceinline__ uint32_t smem_u32(const void* p) {
    uint32_t a;
    asm("{ .reg .u64 t; cvta.to.shared.u64 t, %1; cvt.u32.u64 %0, t; }" : "=r"(a) : "l"(p));
    return a;
}

// ---------------- split helpers ----------------
__device__ __forceinline__ void split_pack(float a, float b, unsigned& hi, unsigned& lo) {
    __nv_bfloat16 ha = __float2bfloat16_rn(a);
    __nv_bfloat16 hb = __float2bfloat16_rn(b);
    float ra = a - __bfloat162float(ha);
    float rb = b - __bfloat162float(hb);
    __nv_bfloat162 h2 = __halves2bfloat162(ha, hb);
    __nv_bfloat162 l2 = __floats2bfloat162_rn(ra, rb);
    hi = *(unsigned*)&h2;
    lo = *(unsigned*)&l2;
}
__device__ __forceinline__ void pack8(float4 v0, float4 v1, uint4& hi, uint4& lo) {
    split_pack(v0.x, v0.y, hi.x, lo.x);
    split_pack(v0.z, v0.w, hi.y, lo.y);
    split_pack(v1.x, v1.y, hi.z, lo.z);
    split_pack(v1.z, v1.w, hi.w, lo.w);
}
__device__ __forceinline__ void store_split2(uint8_t* base, int K, int row, int col,
                                             float a, float b) {
    unsigned hi, lo;
    split_pack(a, b, hi, lo);
    size_t blk = (size_t)(row >> 6) * (K >> 4) + (col >> 4);
    uint32_t off = (uint32_t)((row & 63) * 32 +
                   ((((col >> 3) & 1) ^ ((row >> 2) & 1)) << 4) + (col & 7) * 2);
    *(unsigned*)(base + blk * 4096 + off) = hi;
    *(unsigned*)(base + blk * 4096 + 2048 + off) = lo;
}
// fp16 single-tile store of 2 adjacent elements
__device__ __forceinline__ void store_h2(uint8_t* base, int K, int row, int col,
                                         float a, float b) {
    __half2 h = __floats2half2_rn(a, b);
    size_t blk = (size_t)(row >> 6) * (K >> 4) + (col >> 4);
    uint32_t off = (uint32_t)((row & 63) * 32 +
                   ((((col >> 3) & 1) ^ ((row >> 2) & 1)) << 4) + (col & 7) * 2);
    *(__half2*)(base + blk * 2048 + off) = h;
}

// ---------------- weight conversion (fp32 [R,K] -> split tiles) ----------------
__global__ void convert_w(const float* __restrict__ src, uint8_t* __restrict__ dst,
                          int K, int nChunks) {
    int ct = blockIdx.x * 256 + threadIdx.x;
    if (ct >= nChunks) return;
    int within = ct & 127;
    int blk = ct >> 7;
    int r = within >> 1, kc = within & 1;
    int stages = K >> 4;
    int rt = blk / stages, s = blk - rt * stages;
    const float* p = src + (size_t)(rt * 64 + r) * K + s * 16 + kc * 8;
    float4 v0 = *(const float4*)p, v1 = *(const float4*)(p + 4);
    uint4 hi, lo;
    pack8(v0, v1, hi, lo);
    uint32_t off = (uint32_t)(r * 32 + ((kc ^ ((r >> 2) & 1)) << 4));
    *(uint4*)(dst + (size_t)blk * 4096 + off) = hi;
    *(uint4*)(dst + (size_t)blk * 4096 + 2048 + off) = lo;
}

// weight conversion (fp32 [R,K] -> fp16 single tiles)
__global__ void convert_w_h(const float* __restrict__ src, uint8_t* __restrict__ dst,
                            int K, int nChunks) {
    int ct = blockIdx.x * 256 + threadIdx.x;
    if (ct >= nChunks) return;
    int within = ct & 127;
    int blk = ct >> 7;
    int r = within >> 1, kc = within & 1;
    int stages = K >> 4;
    int rt = blk / stages, s = blk - rt * stages;
    const float* p = src + (size_t)(rt * 64 + r) * K + s * 16 + kc * 8;
    float4 v0 = *(const float4*)p, v1 = *(const float4*)(p + 4);
    __half2 h0 = __floats2half2_rn(v0.x, v0.y);
    __half2 h1 = __floats2half2_rn(v0.z, v0.w);
    __half2 h2 = __floats2half2_rn(v1.x, v1.y);
    __half2 h3 = __floats2half2_rn(v1.z, v1.w);
    uint4 hv;
    hv.x = *(unsigned*)&h0; hv.y = *(unsigned*)&h1;
    hv.z = *(unsigned*)&h2; hv.w = *(unsigned*)&h3;
    uint32_t off = (uint32_t)(r * 32 + ((kc ^ ((r >> 2) & 1)) << 4));
    *(uint4*)(dst + (size_t)blk * 2048 + off) = hv;
}

__global__ void convert_x_kernel(const float* __restrict__ src, uint8_t* __restrict__ dst) {
    const int row = blockIdx.x;
    float2 v = ((const float2*)(src + (size_t)row * ND))[threadIdx.x];
    store_h2(dst, ND, row, threadIdx.x * 2, v.x, v.y);
}

// ---------------- tokenize + embed ----------------
__global__ void tokenize_embed_kernel(const float* __restrict__ patches,
                                      const float* __restrict__ masked_token,
                                      const float* __restrict__ partial_params,
                                      const float* __restrict__ emb_w,
                                      const float* __restrict__ emb_b) {
    const int tok = blockIdx.x;
    const int tid = threadIdx.x;   // 128 threads
    __shared__ float proc[NP];

    if (tid == 0) {
        const float* f = patches + (size_t)tok * NP;
        bool anyMask = false, anyBin = false;
        int firstBin = -1;
        float fp[NP];
        #pragma unroll
        for (int p = 0; p < NP; p++) {
            float v = f[p];
            fp[p] = v;
            bool m = fabsf(v - 0.5f) < 0.1f;
            if (m) anyMask = true;
            else { anyBin = true; if (firstBin < 0) firstBin = p; }
        }
        if (!anyBin) {
            #pragma unroll
            for (int p = 0; p < NP; p++) proc[p] = masked_token[p];
        } else if (anyMask) {
            int ptok = firstBin * 2 + (int)rintf(fp[firstBin]);
            const float* pp = partial_params + ptok * NP;
            #pragma unroll
            for (int p = 0; p < NP; p++) proc[p] = pp[p];
        } else {
            #pragma unroll
            for (int p = 0; p < NP; p++) proc[p] = fp[p];
        }
    }
    __syncthreads();

    for (int d = tid; d < ND; d += blockDim.x) {
        const float* w = emb_w + d * NP;
        float s = emb_b[d];
        #pragma unroll
        for (int p = 0; p < NP; p++) s += proc[p] * w[p];
        g_x[(size_t)tok * ND + d] = s;
    }
}

// ---------------- layernorm (fp32 in -> split-bf16 tile out) ----------------
__global__ void ln_kernel(const float* __restrict__ in, uint8_t* __restrict__ out,
                          const float* __restrict__ gamma, const float* __restrict__ beta) {
    const int tok = blockIdx.x;
    const int tid = threadIdx.x;   // 256
    const float2 v = ((const float2*)(in + (size_t)tok * ND))[tid];

    float s  = v.x + v.y;
    float sq = v.x * v.x + v.y * v.y;
    #pragma unroll
    for (int off = 16; off; off >>= 1) {
        s  += __shfl_xor_sync(0xffffffffu, s,  off);
        sq += __shfl_xor_sync(0xffffffffu, sq, off);
    }
    __shared__ float rs[8], rq[8], stats[2];
    if ((tid & 31) == 0) { rs[tid >> 5] = s; rq[tid >> 5] = sq; }
    __syncthreads();
    if (tid == 0) {
        float S = 0.f, Q = 0.f;
        #pragma unroll
        for (int i = 0; i < 8; i++) { S += rs[i]; Q += rq[i]; }
        float mean = S * (1.0f / ND);
        float var  = Q * (1.0f / ND) - mean * mean;
        stats[0] = mean;
        stats[1] = rsqrtf(var + 1e-5f);
    }
    __syncthreads();
    const float mean = stats[0], inv = stats[1];
    float2 g2 = ((const float2*)gamma)[tid];
    float2 b2 = ((const float2*)beta)[tid];
    float ox = (v.x - mean) * inv * g2.x + b2.x;
    float oy = (v.y - mean) * inv * g2.y + b2.y;
    store_split2(out, ND, tok, tid * 2, ox, oy);
}

// ---------------- fused attention (smem K/V, 512 threads, split output) -----
// grid = B*H*2 = 128 blocks, 512 threads (16 warps). Each warp: 8 queries.
// smem: Ks 64K + Vs 64K + Qs 32K + Wb 64K = 224 KB.
#define ATTN_SMEM (224 * 1024)

__global__ __launch_bounds__(512) void attn_kernel(const float* __restrict__ rel) {
    extern __shared__ float sm[];
    float* Ks = sm;            // [256][64] rotated rows
    float* Vs = sm + 16384;    // [256][64]
    float* Qs = sm + 32768;    // [128][64]
    float* Wb = sm + 40960;    // [16 warps][256][4]

    const int idx = blockIdx.x;
    const int qc = idx & 1;
    const int h  = (idx >> 1) & (NH - 1);
    const int b  = idx >> 4;
    const int tid = threadIdx.x, wid = tid >> 5, L = tid & 31;

    const size_t base = (size_t)(b * NS) * (3 * ND) + h * HD;

    // ---- stage K (rotated), V, Q : 512 threads ----
    {
        const int dc = (tid & 15) * 4;
        int t = tid >> 4;   // 0..31
        #pragma unroll 4
        for (int pass = 0; pass < 8; pass++, t += 32) {
            const float* kR = g_qkv + base + ND + (size_t)t * (3 * ND);
            float4 kv = *(const float4*)(kR + dc);
            const int p = (dc + 4 * (t & 15)) & 63;
            *(float4*)(Ks + t * 64 + p) = kv;
            const float* vR = g_qkv + base + 2 * ND + (size_t)t * (3 * ND);
            *(float4*)(Vs + t * 64 + dc) = *(const float4*)(vR + dc);
        }
        int q = tid >> 4;
        #pragma unroll 4
        for (int pass = 0; pass < 4; pass++, q += 32) {
            const float* qR = g_qkv + base + (size_t)(qc * 128 + q) * (3 * ND);
            *(float4*)(Qs + q * 64 + dc) = *(const float4*)(qR + dc);
        }
    }
    __syncthreads();

    float* wb = Wb + wid * 1024;
    const int rot = 4 * (L & 15);

    for (int g4 = 0; g4 < 2; g4++) {
        const int q0 = wid * 8 + g4 * 4;       // local query base (0..124)
        const int sRow = qc * 128 + q0;

        float sc[4][8];
        #pragma unroll
        for (int qi = 0; qi < 4; qi++)
            #pragma unroll
            for (int j = 0; j < 8; j++) sc[qi][j] = 0.f;

        #pragma unroll
        for (int dd = 0; dd < 16; dd++) {
            const int d = dd * 4;
            float4 qv[4];
            #pragma unroll
            for (int qi = 0; qi < 4; qi++)
                qv[qi] = *(const float4*)(Qs + (q0 + qi) * 64 + d);
            const int p = (d + rot) & 63;
            #pragma unroll
            for (int j = 0; j < 8; j++) {
                float4 k4 = *(const float4*)(Ks + (L + 32 * j) * 64 + p);
                #pragma unroll
                for (int qi = 0; qi < 4; qi++)
                    sc[qi][j] += qv[qi].x * k4.x + qv[qi].y * k4.y +
                                 qv[qi].z * k4.z + qv[qi].w * k4.w;
            }
        }

        #pragma unroll
        for (int qi = 0; qi < 4; qi++) {
            const float* rrow = rel + (size_t)(sRow + qi) * NS;
            float m = -1e30f;
            #pragma unroll
            for (int j = 0; j < 8; j++) {
                float v = sc[qi][j] * 0.125f + rrow[L + 32 * j];
                sc[qi][j] = v;
                m = fmaxf(m, v);
            }
            #pragma unroll
            for (int off = 16; off; off >>= 1)
                m = fmaxf(m, __shfl_xor_sync(0xffffffffu, m, off));
            float ssum = 0.f;
            #pragma unroll
            for (int j = 0; j < 8; j++) { sc[qi][j] = expf(sc[qi][j] - m); ssum += sc[qi][j]; }
            #pragma unroll
            for (int off = 16; off; off >>= 1)
                ssum += __shfl_xor_sync(0xffffffffu, ssum, off);
            const float inv = 1.0f / ssum;
            #pragma unroll
            for (int j = 0; j < 8; j++) sc[qi][j] *= inv;
        }

        #pragma unroll
        for (int j = 0; j < 8; j++)
            *(float4*)(wb + (L + 32 * j) * 4) =
                make_float4(sc[0][j], sc[1][j], sc[2][j], sc[3][j]);
        __syncwarp();

        float2 acc[4];
        #pragma unroll
        for (int qi = 0; qi < 4; qi++) acc[qi] = make_float2(0.f, 0.f);
        #pragma unroll 4
        for (int t = 0; t < NS; t++) {
            float2 v2 = *(const float2*)(Vs + t * 64 + 2 * L);
            float4 w4 = *(const float4*)(wb + t * 4);
            acc[0].x += w4.x * v2.x; acc[0].y += w4.x * v2.y;
            acc[1].x += w4.y * v2.x; acc[1].y += w4.y * v2.y;
            acc[2].x += w4.z * v2.x; acc[2].y += w4.z * v2.y;
            acc[3].x += w4.w * v2.x; acc[3].y += w4.w * v2.y;
        }
        #pragma unroll
        for (int qi = 0; qi < 4; qi++)
            store_split2(s_o, ND, b * NS + sRow + qi, h * HD + 2 * L,
                         acc[qi].x, acc[qi].y);
        __syncwarp();
    }
}

// ---------------- GEMM common macros ----------------
#define MMA_BF16(d, a0,a1,a2,a3, b0,b1)                                         \
    asm volatile("mma.sync.aligned.m16n8k16.row.col.f32.bf16.bf16.f32 "         \
                 "{%0,%1,%2,%3}, {%4,%5,%6,%7}, {%8,%9}, {%0,%1,%2,%3};"        \
                 : "+f"(d[0]), "+f"(d[1]), "+f"(d[2]), "+f"(d[3])               \
                 : "r"(a0), "r"(a1), "r"(a2), "r"(a3), "r"(b0), "r"(b1))

#define MMA_FP16(d, a0,a1,a2,a3, b0,b1)                                         \
    asm volatile("mma.sync.aligned.m16n8k16.row.col.f32.f16.f16.f32 "           \
                 "{%0,%1,%2,%3}, {%4,%5,%6,%7}, {%8,%9}, {%0,%1,%2,%3};"        \
                 : "+f"(d[0]), "+f"(d[1]), "+f"(d[2]), "+f"(d[3])               \
                 : "r"(a0), "r"(a1), "r"(a2), "r"(a3), "r"(b0), "r"(b1))

#define LDSM4(r, addr)                                                          \
    asm volatile("ldmatrix.sync.aligned.m8n8.x4.shared.b16 {%0,%1,%2,%3}, [%4];"\
                 : "=r"((r)[0]), "=r"((r)[1]), "=r"((r)[2]), "=r"((r)[3])       \
                 : "r"(addr))

#define CP16(dst, src)                                                          \
    asm volatile("cp.async.cg.shared.global [%0], [%1], 16;" :: "r"(dst), "l"(src))
#define CP_COMMIT() asm volatile("cp.async.commit_group;" ::: "memory")
#define CP_WAIT2()  asm volatile("cp.async.wait_group 2;" ::: "memory")

__device__ __forceinline__ uint32_t tile_off(int m, int kc) {
    return (uint32_t)((m >> 6) * 4096 + (m & 63) * 32 +
                      ((kc ^ ((m >> 2) & 1)) << 4));
}
__device__ __forceinline__ uint32_t tile_off_h(int m, int kc) {
    return (uint32_t)((m >> 6) * 2048 + (m & 63) * 32 +
                      ((kc ^ ((m >> 2) & 1)) << 4));
}

// ---------------- split-bf16 GEMM (round-6 verified config) ----------------
template <int TM, int EPI, int MINB>
__global__ __launch_bounds__(256, MINB)
void gemm_split(const uint8_t* __restrict__ A, const uint8_t* __restrict__ W,
                const float* __restrict__ bias, const float* __restrict__ res,
                void* __restrict__ Cout, int M, int N, int K) {
    constexpr int ABLK  = TM / 64;
    constexpr int NREG  = ABLK + 2;
    constexpr int ST    = NREG * 4096;
    constexpr int AWOFF = ABLK * 4096;
    constexpr int MF    = TM / 32;
    constexpr int NSTG  = 4;

    extern __shared__ uint8_t smem[];
    const uint32_t sb = smem_u32(smem);

    const int tid = threadIdx.x;
    const int bm = blockIdx.x * TM;
    const int bn = blockIdx.y * 128;
    const int wid = tid >> 5, lane = tid & 31;
    const int g = lane >> 2, t4 = lane & 3;
    const int wm = (wid >> 2) * (TM / 2);
    const int wn = (wid & 3) * 32;

    const int S = K >> 4;

    const uint8_t* ps[NREG];
    {
        const int mt0 = blockIdx.x * ABLK;
        const int nt0 = blockIdx.y * 2;
        #pragma unroll
        for (int i = 0; i < ABLK; i++)
            ps[i] = A + (size_t)(mt0 + i) * S * 4096;
        ps[ABLK]     = W + (size_t)nt0 * S * 4096;
        ps[ABLK + 1] = W + (size_t)(nt0 + 1) * S * 4096;
    }

    const int sel = lane >> 3, ri = lane & 7;
    uint32_t aOffH[MF], bOffH[2];
    #pragma unroll
    for (int mf = 0; mf < MF; mf++) {
        const int m = wm + mf * 16 + (sel & 1) * 8 + ri;
        aOffH[mf] = tile_off(m, sel >> 1);
    }
    #pragma unroll
    for (int p = 0; p < 2; p++) {
        const int n = wn + p * 16 + (sel >> 1) * 8 + ri;
        bOffH[p] = AWOFF + tile_off(n, sel & 1);
    }

    float acc[MF][4][4];
    #pragma unroll
    for (int i = 0; i < MF; i++)
        #pragma unroll
        for (int j = 0; j < 4; j++)
            #pragma unroll
            for (int c = 0; c < 4; c++) acc[i][j][c] = 0.f;

    #pragma unroll
    for (int s = 0; s < NSTG - 1; s++) {
        const uint32_t dst = sb + s * ST + tid * 16;
        #pragma unroll
        for (int c = 0; c < NREG; c++)
            CP16(dst + c * 4096, ps[c] + tid * 16);
        #pragma unroll
        for (int c = 0; c < NREG; c++) ps[c] += 4096;
        CP_COMMIT();
    }

    for (int s = 0; s < S; s++) {
        CP_WAIT2();
        __syncthreads();

        const uint32_t stg = sb + (uint32_t)((s & 3) * ST);
        uint32_t aH[MF][4], aL[MF][4], bH[2][4], bL[2][4];
        #pragma unroll
        for (int mf = 0; mf < MF; mf++) {
            LDSM4(aH[mf], stg + aOffH[mf]);
            LDSM4(aL[mf], stg + aOffH[mf] + 2048);
        }
        #pragma unroll
        for (int p = 0; p < 2; p++) {
            LDSM4(bH[p], stg + bOffH[p]);
            LDSM4(bL[p], stg + bOffH[p] + 2048);
        }
        #pragma unroll
        for (int mf = 0; mf < MF; mf++)
            #pragma unroll
            for (int nf = 0; nf < 4; nf++) {
                const int p = nf >> 1, q = (nf & 1) * 2;
                MMA_BF16(acc[mf][nf], aH[mf][0], aH[mf][1], aH[mf][2], aH[mf][3],
                         bH[p][q], bH[p][q + 1]);
                MMA_BF16(acc[mf][nf], aH[mf][0], aH[mf][1], aH[mf][2], aH[mf][3],
                         bL[p][q], bL[p][q + 1]);
                MMA_BF16(acc[mf][nf], aL[mf][0], aL[mf][1], aL[mf][2], aL[mf][3],
                         bH[p][q], bH[p][q + 1]);
            }

        if (s + NSTG - 1 < S) {
            const uint32_t dst = sb + (uint32_t)(((s + NSTG - 1) & 3) * ST) + tid * 16;
            #pragma unroll
            for (int c = 0; c < NREG; c++)
                CP16(dst + c * 4096, ps[c] + tid * 16);
            #pragma unroll
            for (int c = 0; c < NREG; c++) ps[c] += 4096;
        }
        CP_COMMIT();
    }

    // ---- epilogue ----
    #pragma unroll
    for (int mf = 0; mf < MF; mf++) {
        const int r0 = bm + wm + mf * 16 + g;
        #pragma unroll
        for (int nf = 0; nf < 4; nf++) {
            const int c0 = bn + wn + nf * 8 + 2 * t4;
            const float2 bv = *(const float2*)(bias + c0);
            float v00 = acc[mf][nf][0] + bv.x;
            float v01 = acc[mf][nf][1] + bv.y;
            float v10 = acc[mf][nf][2] + bv.x;
            float v11 = acc[mf][nf][3] + bv.y;
            if (EPI == 2) {
                v00 = v00 * 0.5f * (1.0f + erff(v00 * 0.70710678118654752f));
                v01 = v01 * 0.5f * (1.0f + erff(v01 * 0.70710678118654752f));
                v10 = v10 * 0.5f * (1.0f + erff(v10 * 0.70710678118654752f));
                v11 = v11 * 0.5f * (1.0f + erff(v11 * 0.70710678118654752f));
                uint8_t* C = (uint8_t*)Cout;
                store_split2(C, N, r0,     c0, v00, v01);
                store_split2(C, N, r0 + 8, c0, v10, v11);
            } else {
                float* C = (float*)Cout;
                const size_t i0 = (size_t)r0 * N + c0;
                const size_t i1 = (size_t)(r0 + 8) * N + c0;
                if (EPI == 1) {
                    const float2 r0v = *(const float2*)(res + i0);
                    const float2 r1v = *(const float2*)(res + i1);
                    v00 += r0v.x; v01 += r0v.y; v10 += r1v.x; v11 += r1v.y;
                }
                *(float2*)(C + i0) = make_float2(v00, v01);
                *(float2*)(C + i1) = make_float2(v10, v11);
            }
        }
    }
}

// ---------------- fp16 single-term GEMM (terminal vocab projection) ----------
__global__ __launch_bounds__(256, 2)
void gemm_h(const uint8_t* __restrict__ A, const uint8_t* __restrict__ W,
            const float* __restrict__ bias, float* __restrict__ C,
            int M, int N, int K) {
    constexpr int ST   = 8192;
    constexpr int NSTG = 4;

    extern __shared__ uint8_t smem[];
    const uint32_t sb = smem_u32(smem);

    const int tid = threadIdx.x;
    const int bm = blockIdx.x * 128;
    const int bn = blockIdx.y * 128;
    const int wid = tid >> 5, lane = tid & 31;
    const int g = lane >> 2, t4 = lane & 3;
    const int wm = (wid >> 2) * 64;
    const int wn = (wid & 3) * 32;

    const int S = K >> 4;   // 32 stages

    const int o0 = tid * 16;
    const int o1 = 4096 + tid * 16;
    const uint8_t* src0;
    const uint8_t* src1;
    {
        const int mt0 = blockIdx.x * 2;
        const int nt0 = blockIdx.y * 2;
        const uint8_t* blkp[4];
        blkp[0] = A + (size_t)(mt0 + 0) * S * 2048;
        blkp[1] = A + (size_t)(mt0 + 1) * S * 2048;
        blkp[2] = W + (size_t)(nt0 + 0) * S * 2048;
        blkp[3] = W + (size_t)(nt0 + 1) * S * 2048;
        src0 = blkp[o0 >> 11] + (o0 & 2047);
        src1 = blkp[o1 >> 11] + (o1 & 2047);
    }

    const int sel = lane >> 3, ri = lane & 7;
    uint32_t aOff[4], bOff[2];
    #pragma unroll
    for (int mf = 0; mf < 4; mf++) {
        const int m = wm + mf * 16 + (sel & 1) * 8 + ri;
        aOff[mf] = tile_off_h(m, sel >> 1);
    }
    #pragma unroll
    for (int p = 0; p < 2; p++) {
        const int n = wn + p * 16 + (sel >> 1) * 8 + ri;
        bOff[p] = 4096 + tile_off_h(n, sel & 1);
    }

    float acc[4][4][4];
    #pragma unroll
    for (int i = 0; i < 4; i++)
        #pragma unroll
        for (int j = 0; j < 4; j++)
            #pragma unroll
            for (int c = 0; c < 4; c++) acc[i][j][c] = 0.f;

    #pragma unroll
    for (int s = 0; s < NSTG - 1; s++) {
        const uint32_t dst = sb + s * ST;
        CP16(dst + o0, src0);
        CP16(dst + o1, src1);
        src0 += 2048; src1 += 2048;
        CP_COMMIT();
    }

    for (int s = 0; s < S; s++) {
        CP_WAIT2();
        __syncthreads();

        const uint32_t stg = sb + (uint32_t)((s & 3) * ST);
        uint32_t aF[4][4], bF[2][4];
        #pragma unroll
        for (int mf = 0; mf < 4; mf++) LDSM4(aF[mf], stg + aOff[mf]);
        #pragma unroll
        for (int p = 0; p < 2; p++)    LDSM4(bF[p], stg + bOff[p]);

        #pragma unroll
        for (int mf = 0; mf < 4; mf++)
            #pragma unroll
            for (int nf = 0; nf < 4; nf++) {
                const int p = nf >> 1, q = (nf & 1) * 2;
                MMA_FP16(acc[mf][nf], aF[mf][0], aF[mf][1], aF[mf][2], aF[mf][3],
                         bF[p][q], bF[p][q + 1]);
            }

        if (s + NSTG - 1 < S) {
            const uint32_t dst = sb + (uint32_t)(((s + NSTG - 1) & 3) * ST);
            CP16(dst + o0, src0);
            CP16(dst + o1, src1);
            src0 += 2048; src1 += 2048;
        }
        CP_COMMIT();
    }

    #pragma unroll
    for (int mf = 0; mf < 4; mf++) {
        const int r0 = bm + wm + mf * 16 + g;
        #pragma unroll
        for (int nf = 0; nf < 4; nf++) {
            const int c0 = bn + wn + nf * 8 + 2 * t4;
            const float2 bv = *(const float2*)(bias + c0);
            const size_t i0 = (size_t)r0 * N + c0;
            const size_t i1 = (size_t)(r0 + 8) * N + c0;
            *(float2*)(C + i0) = make_float2(acc[mf][nf][0] + bv.x, acc[mf][nf][1] + bv.y);
            *(float2*)(C + i1) = make_float2(acc[mf][nf][2] + bv.x, acc[mf][nf][3] + bv.y);
        }
    }
}

// ---------------- launch ----------------
extern "C" void kernel_launch(void* const* d_in, const int* in_sizes, int n_in,
                              void* d_out, int out_size) {
    const float* patches        = (const float*)d_in[0];
    const float* masked_token   = (const float*)d_in[3];
    const float* partial_params = (const float*)d_in[4];
    const float* emb_w          = (const float*)d_in[5];
    const float* emb_b          = (const float*)d_in[6];
    const float* ln1_g          = (const float*)d_in[7];
    const float* ln1_b          = (const float*)d_in[8];
    const float* in_proj_w      = (const float*)d_in[9];
    const float* in_proj_b      = (const float*)d_in[10];
    const float* out_proj_w     = (const float*)d_in[11];
    const float* out_proj_b     = (const float*)d_in[12];
    const float* rel_pos        = (const float*)d_in[13];
    const float* ln2_g          = (const float*)d_in[14];
    const float* ln2_b          = (const float*)d_in[15];
    const float* ffn_w1         = (const float*)d_in[16];
    const float* ffn_b1         = (const float*)d_in[17];
    const float* ffn_w2         = (const float*)d_in[18];
    const float* ffn_b2         = (const float*)d_in[19];
    const float* outp_w         = (const float*)d_in[20];
    const float* outp_b         = (const float*)d_in[21];
    float* out = (float*)d_out;

    float *x, *qkv;
    uint8_t *xn, *o, *h, *xf, *win, *wo, *w1, *w2, *wv;
    cudaGetSymbolAddress((void**)&x,   g_x);
    cudaGetSymbolAddress((void**)&qkv, g_qkv);
    cudaGetSymbolAddress((void**)&xn,  s_xn);
    cudaGetSymbolAddress((void**)&o,   s_o);
    cudaGetSymbolAddress((void**)&h,   s_h);
    cudaGetSymbolAddress((void**)&xf,  s_xf);
    cudaGetSymbolAddress((void**)&win, s_win);
    cudaGetSymbolAddress((void**)&wo,  s_wo);
    cudaGetSymbolAddress((void**)&w1,  s_w1);
    cudaGetSymbolAddress((void**)&w2,  s_w2);
    cudaGetSymbolAddress((void**)&wv,  s_wv);

    cudaFuncSetAttribute(attn_kernel, cudaFuncAttributeMaxDynamicSharedMemorySize, ATTN_SMEM);
    cudaFuncSetAttribute((const void*)gemm_split<64, 0, 2>, cudaFuncAttributeMaxDynamicSharedMemorySize, 49152);
    cudaFuncSetAttribute((const void*)gemm_split<64, 1, 2>, cudaFuncAttributeMaxDynamicSharedMemorySize, 49152);
    cudaFuncSetAttribute((const void*)gemm_split<64, 2, 2>, cudaFuncAttributeMaxDynamicSharedMemorySize, 49152);
    cudaFuncSetAttribute((const void*)gemm_h, cudaFuncAttributeMaxDynamicSharedMemorySize, 32768);

    // ---- convert all weights ----
    {
        int nc;
        nc = NL * 3 * ND * ND / 8;  convert_w<<<(nc + 255) / 256, 256>>>(in_proj_w,  win, ND, nc);
        nc = NL * ND * ND / 8;      convert_w<<<(nc + 255) / 256, 256>>>(out_proj_w, wo,  ND, nc);
        nc = NL * NF * ND / 8;      convert_w<<<(nc + 255) / 256, 256>>>(ffn_w1,     w1,  ND, nc);
        nc = NL * ND * NF / 8;      convert_w<<<(nc + 255) / 256, 256>>>(ffn_w2,     w2,  NF, nc);
        nc = (int)((size_t)NV * ND / 8);
        convert_w_h<<<(nc + 255) / 256, 256>>>(outp_w, wv, ND, nc);
    }

    tokenize_embed_kernel<<<NTOK, 128>>>(patches, masked_token, partial_params, emb_w, emb_b);

    for (int l = 0; l < NL; l++) {
        ln_kernel<<<NTOK, 256>>>(x, xn, ln1_g + l * ND, ln1_b + l * ND);

        gemm_split<64, 0, 2><<<dim3(NTOK / 64, 3 * ND / 128), 256, 49152>>>(
            xn, win + (size_t)l * 3 * ND * ND * 4, in_proj_b + l * 3 * ND,
            nullptr, qkv, NTOK, 3 * ND, ND);

        attn_kernel<<<NB * NH * 2, 512, ATTN_SMEM>>>(rel_pos + (size_t)l * NS * NS);

        gemm_split<64, 1, 2><<<dim3(NTOK / 64, ND / 128), 256, 49152>>>(
            o, wo + (size_t)l * ND * ND * 4, out_proj_b + l * ND,
            x, x, NTOK, ND, ND);

        ln_kernel<<<NTOK, 256>>>(x, xn, ln2_g + l * ND, ln2_b + l * ND);

        gemm_split<64, 2, 2><<<dim3(NTOK / 64, NF / 128), 256, 49152>>>(
            xn, w1 + (size_t)l * NF * ND * 4, ffn_b1 + l * NF,
            nullptr, h, NTOK, NF, ND);

        gemm_split<64, 1, 2><<<dim3(NTOK / 64, ND / 128), 256, 49152>>>(
            h, w2 + (size_t)l * ND * NF * 4, ffn_b2 + l * ND,
            x, x, NTOK, ND, NF);
    }

    convert_x_kernel<<<NTOK, 256>>>(x, xf);

    gemm_h<<<dim3(NTOK / 128, NV / 128), 256, 32768>>>(
        xf, wv, outp_b, out, NTOK, NV, ND);
}

// round 12
// speedup vs baseline: 1.5997x; 1.0964x over previous
#include <cuda_runtime.h>
#include <cuda_bf16.h>
#include <cuda_fp16.h>
#include <math.h>
#include <stdint.h>

// ---------------- problem constants ----------------
#define NB   8
#define NS   256
#define NP   16
#define ND   512
#define NH   8
#define HD   64
#define NL   6
#define NF   2048
#define NV   65536
#define NTOK (NB * NS)   // 2048

// ---------------- scratch (device globals; no allocation) ----------------
__device__ float g_x  [NTOK * ND];          // residual stream (fp32)
__device__ float g_qkv[NTOK * 3 * ND];      // qkv projection (fp32)

// split-fp16 activation tiles (hi|lo 2KB blocks of 64 rows x 16 k, swizzled)
__device__ uint8_t s_xn [NTOK * ND * 4];
__device__ uint8_t s_o  [NTOK * ND * 4];
__device__ uint8_t s_h  [NTOK * NF * 4];
// fp16 single tiles (2KB blocks) for weights + vocab A
__device__ uint8_t s_win[NL * 3 * ND * ND * 2];
__device__ uint8_t s_wo [NL * ND * ND * 2];
__device__ uint8_t s_w1 [NL * NF * ND * 2];
__device__ uint8_t s_w2 [(size_t)NL * ND * NF * 2];
__device__ uint8_t s_xf [NTOK * ND * 2];
__device__ uint8_t s_wv [(size_t)NV * ND * 2];

__device__ __forceinline__ uint32_t smem_u32(const void* p) {
    uint32_t a;
    asm("{ .reg .u64 t; cvta.to.shared.u64 t, %1; cvt.u32.u64 %0, t; }" : "=r"(a) : "l"(p));
    return a;
}

// ---------------- split / store helpers ----------------
// split-fp16 store of 2 adjacent elements into hi|lo 4KB-block tile format
__device__ __forceinline__ void store_split2_f16(uint8_t* base, int K, int row, int col,
                                                 float a, float b) {
    __half ha = __float2half_rn(a);
    __half hb = __float2half_rn(b);
    __half2 hi = __halves2half2(ha, hb);
    __half2 lo = __floats2half2_rn(a - __half2float(ha), b - __half2float(hb));
    size_t blk = (size_t)(row >> 6) * (K >> 4) + (col >> 4);
    uint32_t off = (uint32_t)((row & 63) * 32 +
                   ((((col >> 3) & 1) ^ ((row >> 2) & 1)) << 4) + (col & 7) * 2);
    *(__half2*)(base + blk * 4096 + off) = hi;
    *(__half2*)(base + blk * 4096 + 2048 + off) = lo;
}
// fp16 single-tile store of 2 adjacent elements (2KB blocks)
__device__ __forceinline__ void store_h2(uint8_t* base, int K, int row, int col,
                                         float a, float b) {
    __half2 h = __floats2half2_rn(a, b);
    size_t blk = (size_t)(row >> 6) * (K >> 4) + (col >> 4);
    uint32_t off = (uint32_t)((row & 63) * 32 +
                   ((((col >> 3) & 1) ^ ((row >> 2) & 1)) << 4) + (col & 7) * 2);
    *(__half2*)(base + blk * 2048 + off) = h;
}

// ---------------- weight conversion (fp32 [R,K] -> fp16 single tiles) --------
__global__ void convert_w_h(const float* __restrict__ src, uint8_t* __restrict__ dst,
                            int K, int nChunks) {
    int ct = blockIdx.x * 256 + threadIdx.x;
    if (ct >= nChunks) return;
    int within = ct & 127;
    int blk = ct >> 7;
    int r = within >> 1, kc = within & 1;
    int stages = K >> 4;
    int rt = blk / stages, s = blk - rt * stages;
    const float* p = src + (size_t)(rt * 64 + r) * K + s * 16 + kc * 8;
    float4 v0 = *(const float4*)p, v1 = *(const float4*)(p + 4);
    __half2 h0 = __floats2half2_rn(v0.x, v0.y);
    __half2 h1 = __floats2half2_rn(v0.z, v0.w);
    __half2 h2 = __floats2half2_rn(v1.x, v1.y);
    __half2 h3 = __floats2half2_rn(v1.z, v1.w);
    uint4 hv;
    hv.x = *(unsigned*)&h0; hv.y = *(unsigned*)&h1;
    hv.z = *(unsigned*)&h2; hv.w = *(unsigned*)&h3;
    uint32_t off = (uint32_t)(r * 32 + ((kc ^ ((r >> 2) & 1)) << 4));
    *(uint4*)(dst + (size_t)blk * 2048 + off) = hv;
}

__global__ void convert_x_kernel(const float* __restrict__ src, uint8_t* __restrict__ dst) {
    const int row = blockIdx.x;
    float2 v = ((const float2*)(src + (size_t)row * ND))[threadIdx.x];
    store_h2(dst, ND, row, threadIdx.x * 2, v.x, v.y);
}

// ---------------- tokenize + embed ----------------
__global__ void tokenize_embed_kernel(const float* __restrict__ patches,
                                      const float* __restrict__ masked_token,
                                      const float* __restrict__ partial_params,
                                      const float* __restrict__ emb_w,
                                      const float* __restrict__ emb_b) {
    const int tok = blockIdx.x;
    const int tid = threadIdx.x;   // 128 threads
    __shared__ float proc[NP];

    if (tid == 0) {
        const float* f = patches + (size_t)tok * NP;
        bool anyMask = false, anyBin = false;
        int firstBin = -1;
        float fp[NP];
        #pragma unroll
        for (int p = 0; p < NP; p++) {
            float v = f[p];
            fp[p] = v;
            bool m = fabsf(v - 0.5f) < 0.1f;
            if (m) anyMask = true;
            else { anyBin = true; if (firstBin < 0) firstBin = p; }
        }
        if (!anyBin) {
            #pragma unroll
            for (int p = 0; p < NP; p++) proc[p] = masked_token[p];
        } else if (anyMask) {
            int ptok = firstBin * 2 + (int)rintf(fp[firstBin]);
            const float* pp = partial_params + ptok * NP;
            #pragma unroll
            for (int p = 0; p < NP; p++) proc[p] = pp[p];
        } else {
            #pragma unroll
            for (int p = 0; p < NP; p++) proc[p] = fp[p];
        }
    }
    __syncthreads();

    for (int d = tid; d < ND; d += blockDim.x) {
        const float* w = emb_w + d * NP;
        float s = emb_b[d];
        #pragma unroll
        for (int p = 0; p < NP; p++) s += proc[p] * w[p];
        g_x[(size_t)tok * ND + d] = s;
    }
}

// ---------------- layernorm (fp32 in -> split-fp16 tile out) ----------------
__global__ void ln_kernel(const float* __restrict__ in, uint8_t* __restrict__ out,
                          const float* __restrict__ gamma, const float* __restrict__ beta) {
    const int tok = blockIdx.x;
    const int tid = threadIdx.x;   // 256
    const float2 v = ((const float2*)(in + (size_t)tok * ND))[tid];

    float s  = v.x + v.y;
    float sq = v.x * v.x + v.y * v.y;
    #pragma unroll
    for (int off = 16; off; off >>= 1) {
        s  += __shfl_xor_sync(0xffffffffu, s,  off);
        sq += __shfl_xor_sync(0xffffffffu, sq, off);
    }
    __shared__ float rs[8], rq[8], stats[2];
    if ((tid & 31) == 0) { rs[tid >> 5] = s; rq[tid >> 5] = sq; }
    __syncthreads();
    if (tid == 0) {
        float S = 0.f, Q = 0.f;
        #pragma unroll
        for (int i = 0; i < 8; i++) { S += rs[i]; Q += rq[i]; }
        float mean = S * (1.0f / ND);
        float var  = Q * (1.0f / ND) - mean * mean;
        stats[0] = mean;
        stats[1] = rsqrtf(var + 1e-5f);
    }
    __syncthreads();
    const float mean = stats[0], inv = stats[1];
    float2 g2 = ((const float2*)gamma)[tid];
    float2 b2 = ((const float2*)beta)[tid];
    float ox = (v.x - mean) * inv * g2.x + b2.x;
    float oy = (v.y - mean) * inv * g2.y + b2.y;
    store_split2_f16(out, ND, tok, tid * 2, ox, oy);
}

// ---------------- fused attention (smem K/V, 512 threads, split out) --------
#define ATTN_SMEM (224 * 1024)

__global__ __launch_bounds__(512) void attn_kernel(const float* __restrict__ rel) {
    extern __shared__ float sm[];
    float* Ks = sm;            // [256][64] rotated rows
    float* Vs = sm + 16384;    // [256][64]
    float* Qs = sm + 32768;    // [128][64]
    float* Wb = sm + 40960;    // [16 warps][256][4]

    const int idx = blockIdx.x;
    const int qc = idx & 1;
    const int h  = (idx >> 1) & (NH - 1);
    const int b  = idx >> 4;
    const int tid = threadIdx.x, wid = tid >> 5, L = tid & 31;

    const size_t base = (size_t)(b * NS) * (3 * ND) + h * HD;

    {
        const int dc = (tid & 15) * 4;
        int t = tid >> 4;   // 0..31
        #pragma unroll 4
        for (int pass = 0; pass < 8; pass++, t += 32) {
            const float* kR = g_qkv + base + ND + (size_t)t * (3 * ND);
            float4 kv = *(const float4*)(kR + dc);
            const int p = (dc + 4 * (t & 15)) & 63;
            *(float4*)(Ks + t * 64 + p) = kv;
            const float* vR = g_qkv + base + 2 * ND + (size_t)t * (3 * ND);
            *(float4*)(Vs + t * 64 + dc) = *(const float4*)(vR + dc);
        }
        int q = tid >> 4;
        #pragma unroll 4
        for (int pass = 0; pass < 4; pass++, q += 32) {
            const float* qR = g_qkv + base + (size_t)(qc * 128 + q) * (3 * ND);
            *(float4*)(Qs + q * 64 + dc) = *(const float4*)(qR + dc);
        }
    }
    __syncthreads();

    float* wb = Wb + wid * 1024;
    const int rot = 4 * (L & 15);

    for (int g4 = 0; g4 < 2; g4++) {
        const int q0 = wid * 8 + g4 * 4;
        const int sRow = qc * 128 + q0;

        float sc[4][8];
        #pragma unroll
        for (int qi = 0; qi < 4; qi++)
            #pragma unroll
            for (int j = 0; j < 8; j++) sc[qi][j] = 0.f;

        #pragma unroll
        for (int dd = 0; dd < 16; dd++) {
            const int d = dd * 4;
            float4 qv[4];
            #pragma unroll
            for (int qi = 0; qi < 4; qi++)
                qv[qi] = *(const float4*)(Qs + (q0 + qi) * 64 + d);
            const int p = (d + rot) & 63;
            #pragma unroll
            for (int j = 0; j < 8; j++) {
                float4 k4 = *(const float4*)(Ks + (L + 32 * j) * 64 + p);
                #pragma unroll
                for (int qi = 0; qi < 4; qi++)
                    sc[qi][j] += qv[qi].x * k4.x + qv[qi].y * k4.y +
                                 qv[qi].z * k4.z + qv[qi].w * k4.w;
            }
        }

        #pragma unroll
        for (int qi = 0; qi < 4; qi++) {
            const float* rrow = rel + (size_t)(sRow + qi) * NS;
            float m = -1e30f;
            #pragma unroll
            for (int j = 0; j < 8; j++) {
                float v = sc[qi][j] * 0.125f + rrow[L + 32 * j];
                sc[qi][j] = v;
                m = fmaxf(m, v);
            }
            #pragma unroll
            for (int off = 16; off; off >>= 1)
                m = fmaxf(m, __shfl_xor_sync(0xffffffffu, m, off));
            float ssum = 0.f;
            #pragma unroll
            for (int j = 0; j < 8; j++) { sc[qi][j] = expf(sc[qi][j] - m); ssum += sc[qi][j]; }
            #pragma unroll
            for (int off = 16; off; off >>= 1)
                ssum += __shfl_xor_sync(0xffffffffu, ssum, off);
            const float inv = 1.0f / ssum;
            #pragma unroll
            for (int j = 0; j < 8; j++) sc[qi][j] *= inv;
        }

        #pragma unroll
        for (int j = 0; j < 8; j++)
            *(float4*)(wb + (L + 32 * j) * 4) =
                make_float4(sc[0][j], sc[1][j], sc[2][j], sc[3][j]);
        __syncwarp();

        float2 acc[4];
        #pragma unroll
        for (int qi = 0; qi < 4; qi++) acc[qi] = make_float2(0.f, 0.f);
        #pragma unroll 4
        for (int t = 0; t < NS; t++) {
            float2 v2 = *(const float2*)(Vs + t * 64 + 2 * L);
            float4 w4 = *(const float4*)(wb + t * 4);
            acc[0].x += w4.x * v2.x; acc[0].y += w4.x * v2.y;
            acc[1].x += w4.y * v2.x; acc[1].y += w4.y * v2.y;
            acc[2].x += w4.z * v2.x; acc[2].y += w4.z * v2.y;
            acc[3].x += w4.w * v2.x; acc[3].y += w4.w * v2.y;
        }
        #pragma unroll
        for (int qi = 0; qi < 4; qi++)
            store_split2_f16(s_o, ND, b * NS + sRow + qi, h * HD + 2 * L,
                             acc[qi].x, acc[qi].y);
        __syncwarp();
    }
}

// ---------------- GEMM common macros ----------------
#define MMA_FP16(d, a0,a1,a2,a3, b0,b1)                                         \
    asm volatile("mma.sync.aligned.m16n8k16.row.col.f32.f16.f16.f32 "           \
                 "{%0,%1,%2,%3}, {%4,%5,%6,%7}, {%8,%9}, {%0,%1,%2,%3};"        \
                 : "+f"(d[0]), "+f"(d[1]), "+f"(d[2]), "+f"(d[3])               \
                 : "r"(a0), "r"(a1), "r"(a2), "r"(a3), "r"(b0), "r"(b1))

#define LDSM4(r, addr)                                                          \
    asm volatile("ldmatrix.sync.aligned.m8n8.x4.shared.b16 {%0,%1,%2,%3}, [%4];"\
                 : "=r"((r)[0]), "=r"((r)[1]), "=r"((r)[2]), "=r"((r)[3])       \
                 : "r"(addr))

#define CP16(dst, src)                                                          \
    asm volatile("cp.async.cg.shared.global [%0], [%1], 16;" :: "r"(dst), "l"(src))
#define CP_COMMIT() asm volatile("cp.async.commit_group;" ::: "memory")
#define CP_WAIT2()  asm volatile("cp.async.wait_group 2;" ::: "memory")

__device__ __forceinline__ uint32_t tile_off(int m, int kc) {   // 4KB blocks
    return (uint32_t)((m >> 6) * 4096 + (m & 63) * 32 +
                      ((kc ^ ((m >> 2) & 1)) << 4));
}
__device__ __forceinline__ uint32_t tile_off_h(int m, int kc) { // 2KB blocks
    return (uint32_t)((m >> 6) * 2048 + (m & 63) * 32 +
                      ((kc ^ ((m >> 2) & 1)) << 4));
}

// ---------------- 2-term split-fp16 GEMM (layer GEMMs) ----------------------
// A in split-fp16 tiles (hi|lo, 4KB/block), W single fp16 (2KB/block).
// D = Ah*W + Al*W, fp32 accum. TM=64 x TN=128, 8KB/stage, 4 stages.
// EPI: 0 = fp32+bias, 1 = fp32+bias+res, 2 = gelu -> split-fp16 tiles.
template <int EPI>
__global__ __launch_bounds__(256, 2)
void gemm_2t(const uint8_t* __restrict__ A, const uint8_t* __restrict__ W,
             const float* __restrict__ bias, const float* __restrict__ res,
             void* __restrict__ Cout, int M, int N, int K) {
    constexpr int ST   = 8192;
    constexpr int NSTG = 4;

    extern __shared__ uint8_t smem[];
    const uint32_t sb = smem_u32(smem);

    const int tid = threadIdx.x;
    const int bm = blockIdx.x * 64;
    const int bn = blockIdx.y * 128;
    const int wid = tid >> 5, lane = tid & 31;
    const int g = lane >> 2, t4 = lane & 3;
    const int wm = (wid >> 2) * 32;
    const int wn = (wid & 3) * 32;

    const int S = K >> 4;

    // cp.async sources: A region [0,4096) (hi|lo block), W region [4096,8192)
    const int o0 = tid * 16;
    const int o1 = 4096 + tid * 16;
    const uint8_t* src0 = A + (size_t)blockIdx.x * S * 4096 + o0;
    const uint8_t* src1;
    {
        const int nt0 = blockIdx.y * 2;
        const int wsel = (o1 - 4096) >> 11;       // 0 or 1
        src1 = W + (size_t)(nt0 + wsel) * S * 2048 + ((o1 - 4096) & 2047);
    }

    const int sel = lane >> 3, ri = lane & 7;
    uint32_t aOffH[2], bOff[2];
    #pragma unroll
    for (int mf = 0; mf < 2; mf++) {
        const int m = wm + mf * 16 + (sel & 1) * 8 + ri;
        aOffH[mf] = tile_off(m, sel >> 1);
    }
    #pragma unroll
    for (int p = 0; p < 2; p++) {
        const int n = wn + p * 16 + (sel >> 1) * 8 + ri;
        bOff[p] = 4096 + tile_off_h(n, sel & 1);
    }

    float acc[2][4][4];
    #pragma unroll
    for (int i = 0; i < 2; i++)
        #pragma unroll
        for (int j = 0; j < 4; j++)
            #pragma unroll
            for (int c = 0; c < 4; c++) acc[i][j][c] = 0.f;

    #pragma unroll
    for (int s = 0; s < NSTG - 1; s++) {
        const uint32_t dst = sb + s * ST;
        CP16(dst + o0, src0);
        CP16(dst + o1, src1);
        src0 += 4096; src1 += 2048;
        CP_COMMIT();
    }

    for (int s = 0; s < S; s++) {
        CP_WAIT2();
        __syncthreads();

        const uint32_t stg = sb + (uint32_t)((s & 3) * ST);
        uint32_t aH[2][4], aL[2][4], bS[2][4];
        #pragma unroll
        for (int mf = 0; mf < 2; mf++) {
            LDSM4(aH[mf], stg + aOffH[mf]);
            LDSM4(aL[mf], stg + aOffH[mf] + 2048);
        }
        #pragma unroll
        for (int p = 0; p < 2; p++) LDSM4(bS[p], stg + bOff[p]);

        #pragma unroll
        for (int mf = 0; mf < 2; mf++)
            #pragma unroll
            for (int nf = 0; nf < 4; nf++) {
                const int p = nf >> 1, q = (nf & 1) * 2;
                MMA_FP16(acc[mf][nf], aH[mf][0], aH[mf][1], aH[mf][2], aH[mf][3],
                         bS[p][q], bS[p][q + 1]);
                MMA_FP16(acc[mf][nf], aL[mf][0], aL[mf][1], aL[mf][2], aL[mf][3],
                         bS[p][q], bS[p][q + 1]);
            }

        if (s + NSTG - 1 < S) {
            const uint32_t dst = sb + (uint32_t)(((s + NSTG - 1) & 3) * ST);
            CP16(dst + o0, src0);
            CP16(dst + o1, src1);
            src0 += 4096; src1 += 2048;
        }
        CP_COMMIT();
    }

    // ---- epilogue ----
    #pragma unroll
    for (int mf = 0; mf < 2; mf++) {
        const int r0 = bm + wm + mf * 16 + g;
        #pragma unroll
        for (int nf = 0; nf < 4; nf++) {
            const int c0 = bn + wn + nf * 8 + 2 * t4;
            const float2 bv = *(const float2*)(bias + c0);
            float v00 = acc[mf][nf][0] + bv.x;
            float v01 = acc[mf][nf][1] + bv.y;
            float v10 = acc[mf][nf][2] + bv.x;
            float v11 = acc[mf][nf][3] + bv.y;
            if (EPI == 2) {
                v00 = v00 * 0.5f * (1.0f + erff(v00 * 0.70710678118654752f));
                v01 = v01 * 0.5f * (1.0f + erff(v01 * 0.70710678118654752f));
                v10 = v10 * 0.5f * (1.0f + erff(v10 * 0.70710678118654752f));
                v11 = v11 * 0.5f * (1.0f + erff(v11 * 0.70710678118654752f));
                uint8_t* C = (uint8_t*)Cout;
                store_split2_f16(C, N, r0,     c0, v00, v01);
                store_split2_f16(C, N, r0 + 8, c0, v10, v11);
            } else {
                float* C = (float*)Cout;
                const size_t i0 = (size_t)r0 * N + c0;
                const size_t i1 = (size_t)(r0 + 8) * N + c0;
                if (EPI == 1) {
                    const float2 r0v = *(const float2*)(res + i0);
                    const float2 r1v = *(const float2*)(res + i1);
                    v00 += r0v.x; v01 += r0v.y; v10 += r1v.x; v11 += r1v.y;
                }
                *(float2*)(C + i0) = make_float2(v00, v01);
                *(float2*)(C + i1) = make_float2(v10, v11);
            }
        }
    }
}

// ---------------- fp16 single-term GEMM (terminal vocab projection) ----------
__global__ __launch_bounds__(256, 2)
void gemm_h(const uint8_t* __restrict__ A, const uint8_t* __restrict__ W,
            const float* __restrict__ bias, float* __restrict__ C,
            int M, int N, int K) {
    constexpr int ST   = 8192;
    constexpr int NSTG = 4;

    extern __shared__ uint8_t smem[];
    const uint32_t sb = smem_u32(smem);

    const int tid = threadIdx.x;
    const int bm = blockIdx.x * 128;
    const int bn = blockIdx.y * 128;
    const int wid = tid >> 5, lane = tid & 31;
    const int g = lane >> 2, t4 = lane & 3;
    const int wm = (wid >> 2) * 64;
    const int wn = (wid & 3) * 32;

    const int S = K >> 4;

    const int o0 = tid * 16;
    const int o1 = 4096 + tid * 16;
    const uint8_t* src0;
    const uint8_t* src1;
    {
        const int mt0 = blockIdx.x * 2;
        const int nt0 = blockIdx.y * 2;
        const uint8_t* blkp[4];
        blkp[0] = A + (size_t)(mt0 + 0) * S * 2048;
        blkp[1] = A + (size_t)(mt0 + 1) * S * 2048;
        blkp[2] = W + (size_t)(nt0 + 0) * S * 2048;
        blkp[3] = W + (size_t)(nt0 + 1) * S * 2048;
        src0 = blkp[o0 >> 11] + (o0 & 2047);
        src1 = blkp[o1 >> 11] + (o1 & 2047);
    }

    const int sel = lane >> 3, ri = lane & 7;
    uint32_t aOff[4], bOff[2];
    #pragma unroll
    for (int mf = 0; mf < 4; mf++) {
        const int m = wm + mf * 16 + (sel & 1) * 8 + ri;
        aOff[mf] = tile_off_h(m, sel >> 1);
    }
    #pragma unroll
    for (int p = 0; p < 2; p++) {
        const int n = wn + p * 16 + (sel >> 1) * 8 + ri;
        bOff[p] = 4096 + tile_off_h(n, sel & 1);
    }

    float acc[4][4][4];
    #pragma unroll
    for (int i = 0; i < 4; i++)
        #pragma unroll
        for (int j = 0; j < 4; j++)
            #pragma unroll
            for (int c = 0; c < 4; c++) acc[i][j][c] = 0.f;

    #pragma unroll
    for (int s = 0; s < NSTG - 1; s++) {
        const uint32_t dst = sb + s * ST;
        CP16(dst + o0, src0);
        CP16(dst + o1, src1);
        src0 += 2048; src1 += 2048;
        CP_COMMIT();
    }

    for (int s = 0; s < S; s++) {
        CP_WAIT2();
        __syncthreads();

        const uint32_t stg = sb + (uint32_t)((s & 3) * ST);
        uint32_t aF[4][4], bF[2][4];
        #pragma unroll
        for (int mf = 0; mf < 4; mf++) LDSM4(aF[mf], stg + aOff[mf]);
        #pragma unroll
        for (int p = 0; p < 2; p++)    LDSM4(bF[p], stg + bOff[p]);

        #pragma unroll
        for (int mf = 0; mf < 4; mf++)
            #pragma unroll
            for (int nf = 0; nf < 4; nf++) {
                const int p = nf >> 1, q = (nf & 1) * 2;
                MMA_FP16(acc[mf][nf], aF[mf][0], aF[mf][1], aF[mf][2], aF[mf][3],
                         bF[p][q], bF[p][q + 1]);
            }

        if (s + NSTG - 1 < S) {
            const uint32_t dst = sb + (uint32_t)(((s + NSTG - 1) & 3) * ST);
            CP16(dst + o0, src0);
            CP16(dst + o1, src1);
            src0 += 2048; src1 += 2048;
        }
        CP_COMMIT();
    }

    #pragma unroll
    for (int mf = 0; mf < 4; mf++) {
        const int r0 = bm + wm + mf * 16 + g;
        #pragma unroll
        for (int nf = 0; nf < 4; nf++) {
            const int c0 = bn + wn + nf * 8 + 2 * t4;
            const float2 bv = *(const float2*)(bias + c0);
            const size_t i0 = (size_t)r0 * N + c0;
            const size_t i1 = (size_t)(r0 + 8) * N + c0;
            *(float2*)(C + i0) = make_float2(acc[mf][nf][0] + bv.x, acc[mf][nf][1] + bv.y);
            *(float2*)(C + i1) = make_float2(acc[mf][nf][2] + bv.x, acc[mf][nf][3] + bv.y);
        }
    }
}

// ---------------- launch ----------------
extern "C" void kernel_launch(void* const* d_in, const int* in_sizes, int n_in,
                              void* d_out, int out_size) {
    const float* patches        = (const float*)d_in[0];
    const float* masked_token   = (const float*)d_in[3];
    const float* partial_params = (const float*)d_in[4];
    const float* emb_w          = (const float*)d_in[5];
    const float* emb_b          = (const float*)d_in[6];
    const float* ln1_g          = (const float*)d_in[7];
    const float* ln1_b          = (const float*)d_in[8];
    const float* in_proj_w      = (const float*)d_in[9];
    const float* in_proj_b      = (const float*)d_in[10];
    const float* out_proj_w     = (const float*)d_in[11];
    const float* out_proj_b     = (const float*)d_in[12];
    const float* rel_pos        = (const float*)d_in[13];
    const float* ln2_g          = (const float*)d_in[14];
    const float* ln2_b          = (const float*)d_in[15];
    const float* ffn_w1         = (const float*)d_in[16];
    const float* ffn_b1         = (const float*)d_in[17];
    const float* ffn_w2         = (const float*)d_in[18];
    const float* ffn_b2         = (const float*)d_in[19];
    const float* outp_w         = (const float*)d_in[20];
    const float* outp_b         = (const float*)d_in[21];
    float* out = (float*)d_out;

    float *x, *qkv;
    uint8_t *xn, *o, *h, *xf, *win, *wo, *w1, *w2, *wv;
    cudaGetSymbolAddress((void**)&x,   g_x);
    cudaGetSymbolAddress((void**)&qkv, g_qkv);
    cudaGetSymbolAddress((void**)&xn,  s_xn);
    cudaGetSymbolAddress((void**)&o,   s_o);
    cudaGetSymbolAddress((void**)&h,   s_h);
    cudaGetSymbolAddress((void**)&xf,  s_xf);
    cudaGetSymbolAddress((void**)&win, s_win);
    cudaGetSymbolAddress((void**)&wo,  s_wo);
    cudaGetSymbolAddress((void**)&w1,  s_w1);
    cudaGetSymbolAddress((void**)&w2,  s_w2);
    cudaGetSymbolAddress((void**)&wv,  s_wv);

    cudaFuncSetAttribute(attn_kernel, cudaFuncAttributeMaxDynamicSharedMemorySize, ATTN_SMEM);
    cudaFuncSetAttribute((const void*)gemm_2t<0>, cudaFuncAttributeMaxDynamicSharedMemorySize, 32768);
    cudaFuncSetAttribute((const void*)gemm_2t<1>, cudaFuncAttributeMaxDynamicSharedMemorySize, 32768);
    cudaFuncSetAttribute((const void*)gemm_2t<2>, cudaFuncAttributeMaxDynamicSharedMemorySize, 32768);
    cudaFuncSetAttribute((const void*)gemm_h, cudaFuncAttributeMaxDynamicSharedMemorySize, 32768);

    // ---- convert all weights to fp16 single tiles ----
    {
        int nc;
        nc = NL * 3 * ND * ND / 8;  convert_w_h<<<(nc + 255) / 256, 256>>>(in_proj_w,  win, ND, nc);
        nc = NL * ND * ND / 8;      convert_w_h<<<(nc + 255) / 256, 256>>>(out_proj_w, wo,  ND, nc);
        nc = NL * NF * ND / 8;      convert_w_h<<<(nc + 255) / 256, 256>>>(ffn_w1,     w1,  ND, nc);
        nc = NL * ND * NF / 8;      convert_w_h<<<(nc + 255) / 256, 256>>>(ffn_w2,     w2,  NF, nc);
        nc = (int)((size_t)NV * ND / 8);
        convert_w_h<<<(nc + 255) / 256, 256>>>(outp_w, wv, ND, nc);
    }

    tokenize_embed_kernel<<<NTOK, 128>>>(patches, masked_token, partial_params, emb_w, emb_b);

    for (int l = 0; l < NL; l++) {
        ln_kernel<<<NTOK, 256>>>(x, xn, ln1_g + l * ND, ln1_b + l * ND);

        gemm_2t<0><<<dim3(NTOK / 64, 3 * ND / 128), 256, 32768>>>(
            xn, win + (size_t)l * 3 * ND * ND * 2, in_proj_b + l * 3 * ND,
            nullptr, qkv, NTOK, 3 * ND, ND);

        attn_kernel<<<NB * NH * 2, 512, ATTN_SMEM>>>(rel_pos + (size_t)l * NS * NS);

        gemm_2t<1><<<dim3(NTOK / 64, ND / 128), 256, 32768>>>(
            o, wo + (size_t)l * ND * ND * 2, out_proj_b + l * ND,
            x, x, NTOK, ND, ND);

        ln_kernel<<<NTOK, 256>>>(x, xn, ln2_g + l * ND, ln2_b + l * ND);

        gemm_2t<2><<<dim3(NTOK / 64, NF / 128), 256, 32768>>>(
            xn, w1 + (size_t)l * NF * ND * 2, ffn_b1 + l * NF,
            nullptr, h, NTOK, NF, ND);

        gemm_2t<1><<<dim3(NTOK / 64, ND / 128), 256, 32768>>>(
            h, w2 + (size_t)l * ND * NF * 2, ffn_b2 + l * ND,
            x, x, NTOK, ND, NF);
    }

    convert_x_kernel<<<NTOK, 256>>>(x, xf);

    gemm_h<<<dim3(NTOK / 128, NV / 128), 256, 32768>>>(
        xf, wv, outp_b, out, NTOK, NV, ND);
}

// round 13
// speedup vs baseline: 1.6476x; 1.0299x over previous
#include <cuda_runtime.h>
#include <cuda_bf16.h>
#include <cuda_fp16.h>
#include <math.h>
#include <stdint.h>

// ---------------- problem constants ----------------
#define NB   8
#define NS   256
#define NP   16
#define ND   512
#define NH   8
#define HD   64
#define NL   6
#define NF   2048
#define NV   65536
#define NTOK (NB * NS)   // 2048

// ---------------- scratch (device globals; no allocation) ----------------
__device__ float g_x  [NTOK * ND];          // residual stream (fp32)
__device__ float g_qkv[NTOK * 3 * ND];      // qkv projection (fp32)

// split-fp16 activation tiles (hi|lo 2KB halves of 4KB blocks, swizzled)
__device__ uint8_t s_xn [NTOK * ND * 4];
__device__ uint8_t s_o  [NTOK * ND * 4];
__device__ uint8_t s_h  [NTOK * NF * 4];
// fp16 single tiles (2KB blocks) for weights + vocab A
__device__ uint8_t s_win[NL * 3 * ND * ND * 2];
__device__ uint8_t s_wo [NL * ND * ND * 2];
__device__ uint8_t s_w1 [NL * NF * ND * 2];
__device__ uint8_t s_w2 [(size_t)NL * ND * NF * 2];
__device__ uint8_t s_xf [NTOK * ND * 2];
__device__ uint8_t s_wv [(size_t)NV * ND * 2];

__device__ __forceinline__ uint32_t smem_u32(const void* p) {
    uint32_t a;
    asm("{ .reg .u64 t; cvta.to.shared.u64 t, %1; cvt.u32.u64 %0, t; }" : "=r"(a) : "l"(p));
    return a;
}

// ---------------- split / store helpers ----------------
__device__ __forceinline__ void store_split2_f16(uint8_t* base, int K, int row, int col,
                                                 float a, float b) {
    __half ha = __float2half_rn(a);
    __half hb = __float2half_rn(b);
    __half2 hi = __halves2half2(ha, hb);
    __half2 lo = __floats2half2_rn(a - __half2float(ha), b - __half2float(hb));
    size_t blk = (size_t)(row >> 6) * (K >> 4) + (col >> 4);
    uint32_t off = (uint32_t)((row & 63) * 32 +
                   ((((col >> 3) & 1) ^ ((row >> 2) & 1)) << 4) + (col & 7) * 2);
    *(__half2*)(base + blk * 4096 + off) = hi;
    *(__half2*)(base + blk * 4096 + 2048 + off) = lo;
}
__device__ __forceinline__ void store_h2(uint8_t* base, int K, int row, int col,
                                         float a, float b) {
    __half2 h = __floats2half2_rn(a, b);
    size_t blk = (size_t)(row >> 6) * (K >> 4) + (col >> 4);
    uint32_t off = (uint32_t)((row & 63) * 32 +
                   ((((col >> 3) & 1) ^ ((row >> 2) & 1)) << 4) + (col & 7) * 2);
    *(__half2*)(base + blk * 2048 + off) = h;
}

// ---------------- weight conversion (fp32 [R,K] -> fp16 single tiles) --------
__global__ void convert_w_h(const float* __restrict__ src, uint8_t* __restrict__ dst,
                            int K, int nChunks) {
    int ct = blockIdx.x * 256 + threadIdx.x;
    if (ct >= nChunks) return;
    int within = ct & 127;
    int blk = ct >> 7;
    int r = within >> 1, kc = within & 1;
    int stages = K >> 4;
    int rt = blk / stages, s = blk - rt * stages;
    const float* p = src + (size_t)(rt * 64 + r) * K + s * 16 + kc * 8;
    float4 v0 = *(const float4*)p, v1 = *(const float4*)(p + 4);
    __half2 h0 = __floats2half2_rn(v0.x, v0.y);
    __half2 h1 = __floats2half2_rn(v0.z, v0.w);
    __half2 h2 = __floats2half2_rn(v1.x, v1.y);
    __half2 h3 = __floats2half2_rn(v1.z, v1.w);
    uint4 hv;
    hv.x = *(unsigned*)&h0; hv.y = *(unsigned*)&h1;
    hv.z = *(unsigned*)&h2; hv.w = *(unsigned*)&h3;
    uint32_t off = (uint32_t)(r * 32 + ((kc ^ ((r >> 2) & 1)) << 4));
    *(uint4*)(dst + (size_t)blk * 2048 + off) = hv;
}

// ---------------- tokenize + embed ----------------
__global__ void tokenize_embed_kernel(const float* __restrict__ patches,
                                      const float* __restrict__ masked_token,
                                      const float* __restrict__ partial_params,
                                      const float* __restrict__ emb_w,
                                      const float* __restrict__ emb_b) {
    const int tok = blockIdx.x;
    const int tid = threadIdx.x;   // 128 threads
    __shared__ float proc[NP];

    if (tid == 0) {
        const float* f = patches + (size_t)tok * NP;
        bool anyMask = false, anyBin = false;
        int firstBin = -1;
        float fp[NP];
        #pragma unroll
        for (int p = 0; p < NP; p++) {
            float v = f[p];
            fp[p] = v;
            bool m = fabsf(v - 0.5f) < 0.1f;
            if (m) anyMask = true;
            else { anyBin = true; if (firstBin < 0) firstBin = p; }
        }
        if (!anyBin) {
            #pragma unroll
            for (int p = 0; p < NP; p++) proc[p] = masked_token[p];
        } else if (anyMask) {
            int ptok = firstBin * 2 + (int)rintf(fp[firstBin]);
            const float* pp = partial_params + ptok * NP;
            #pragma unroll
            for (int p = 0; p < NP; p++) proc[p] = pp[p];
        } else {
            #pragma unroll
            for (int p = 0; p < NP; p++) proc[p] = fp[p];
        }
    }
    __syncthreads();

    for (int d = tid; d < ND; d += blockDim.x) {
        const float* w = emb_w + d * NP;
        float s = emb_b[d];
        #pragma unroll
        for (int p = 0; p < NP; p++) s += proc[p] * w[p];
        g_x[(size_t)tok * ND + d] = s;
    }
}

// ---------------- layernorm (fp32 in -> split-fp16 tile out) ----------------
__global__ void ln_kernel(const float* __restrict__ in, uint8_t* __restrict__ out,
                          const float* __restrict__ gamma, const float* __restrict__ beta) {
    const int tok = blockIdx.x;
    const int tid = threadIdx.x;   // 256
    const float2 v = ((const float2*)(in + (size_t)tok * ND))[tid];

    float s  = v.x + v.y;
    float sq = v.x * v.x + v.y * v.y;
    #pragma unroll
    for (int off = 16; off; off >>= 1) {
        s  += __shfl_xor_sync(0xffffffffu, s,  off);
        sq += __shfl_xor_sync(0xffffffffu, sq, off);
    }
    __shared__ float rs[8], rq[8], stats[2];
    if ((tid & 31) == 0) { rs[tid >> 5] = s; rq[tid >> 5] = sq; }
    __syncthreads();
    if (tid == 0) {
        float S = 0.f, Q = 0.f;
        #pragma unroll
        for (int i = 0; i < 8; i++) { S += rs[i]; Q += rq[i]; }
        float mean = S * (1.0f / ND);
        float var  = Q * (1.0f / ND) - mean * mean;
        stats[0] = mean;
        stats[1] = rsqrtf(var + 1e-5f);
    }
    __syncthreads();
    const float mean = stats[0], inv = stats[1];
    float2 g2 = ((const float2*)gamma)[tid];
    float2 b2 = ((const float2*)beta)[tid];
    float ox = (v.x - mean) * inv * g2.x + b2.x;
    float oy = (v.y - mean) * inv * g2.y + b2.y;
    store_split2_f16(out, ND, tok, tid * 2, ox, oy);
}

// ---------------- fused attention (smem K/V, 512 threads, split out) --------
#define ATTN_SMEM (224 * 1024)

__global__ __launch_bounds__(512) void attn_kernel(const float* __restrict__ rel) {
    extern __shared__ float sm[];
    float* Ks = sm;            // [256][64] rotated rows
    float* Vs = sm + 16384;    // [256][64]
    float* Qs = sm + 32768;    // [128][64]
    float* Wb = sm + 40960;    // [16 warps][256][4]

    const int idx = blockIdx.x;
    const int qc = idx & 1;
    const int h  = (idx >> 1) & (NH - 1);
    const int b  = idx >> 4;
    const int tid = threadIdx.x, wid = tid >> 5, L = tid & 31;

    const size_t base = (size_t)(b * NS) * (3 * ND) + h * HD;

    {
        const int dc = (tid & 15) * 4;
        int t = tid >> 4;   // 0..31
        #pragma unroll 4
        for (int pass = 0; pass < 8; pass++, t += 32) {
            const float* kR = g_qkv + base + ND + (size_t)t * (3 * ND);
            float4 kv = *(const float4*)(kR + dc);
            const int p = (dc + 4 * (t & 15)) & 63;
            *(float4*)(Ks + t * 64 + p) = kv;
            const float* vR = g_qkv + base + 2 * ND + (size_t)t * (3 * ND);
            *(float4*)(Vs + t * 64 + dc) = *(const float4*)(vR + dc);
        }
        int q = tid >> 4;
        #pragma unroll 4
        for (int pass = 0; pass < 4; pass++, q += 32) {
            const float* qR = g_qkv + base + (size_t)(qc * 128 + q) * (3 * ND);
            *(float4*)(Qs + q * 64 + dc) = *(const float4*)(qR + dc);
        }
    }
    __syncthreads();

    float* wb = Wb + wid * 1024;
    const int rot = 4 * (L & 15);

    for (int g4 = 0; g4 < 2; g4++) {
        const int q0 = wid * 8 + g4 * 4;
        const int sRow = qc * 128 + q0;

        float sc[4][8];
        #pragma unroll
        for (int qi = 0; qi < 4; qi++)
            #pragma unroll
            for (int j = 0; j < 8; j++) sc[qi][j] = 0.f;

        #pragma unroll
        for (int dd = 0; dd < 16; dd++) {
            const int d = dd * 4;
            float4 qv[4];
            #pragma unroll
            for (int qi = 0; qi < 4; qi++)
                qv[qi] = *(const float4*)(Qs + (q0 + qi) * 64 + d);
            const int p = (d + rot) & 63;
            #pragma unroll
            for (int j = 0; j < 8; j++) {
                float4 k4 = *(const float4*)(Ks + (L + 32 * j) * 64 + p);
                #pragma unroll
                for (int qi = 0; qi < 4; qi++)
                    sc[qi][j] += qv[qi].x * k4.x + qv[qi].y * k4.y +
                                 qv[qi].z * k4.z + qv[qi].w * k4.w;
            }
        }

        #pragma unroll
        for (int qi = 0; qi < 4; qi++) {
            const float* rrow = rel + (size_t)(sRow + qi) * NS;
            float m = -1e30f;
            #pragma unroll
            for (int j = 0; j < 8; j++) {
                float v = sc[qi][j] * 0.125f + rrow[L + 32 * j];
                sc[qi][j] = v;
                m = fmaxf(m, v);
            }
            #pragma unroll
            for (int off = 16; off; off >>= 1)
                m = fmaxf(m, __shfl_xor_sync(0xffffffffu, m, off));
            float ssum = 0.f;
            #pragma unroll
            for (int j = 0; j < 8; j++) { sc[qi][j] = expf(sc[qi][j] - m); ssum += sc[qi][j]; }
            #pragma unroll
            for (int off = 16; off; off >>= 1)
                ssum += __shfl_xor_sync(0xffffffffu, ssum, off);
            const float inv = 1.0f / ssum;
            #pragma unroll
            for (int j = 0; j < 8; j++) sc[qi][j] *= inv;
        }

        #pragma unroll
        for (int j = 0; j < 8; j++)
            *(float4*)(wb + (L + 32 * j) * 4) =
                make_float4(sc[0][j], sc[1][j], sc[2][j], sc[3][j]);
        __syncwarp();

        float2 acc[4];
        #pragma unroll
        for (int qi = 0; qi < 4; qi++) acc[qi] = make_float2(0.f, 0.f);
        #pragma unroll 4
        for (int t = 0; t < NS; t++) {
            float2 v2 = *(const float2*)(Vs + t * 64 + 2 * L);
            float4 w4 = *(const float4*)(wb + t * 4);
            acc[0].x += w4.x * v2.x; acc[0].y += w4.x * v2.y;
            acc[1].x += w4.y * v2.x; acc[1].y += w4.y * v2.y;
            acc[2].x += w4.z * v2.x; acc[2].y += w4.z * v2.y;
            acc[3].x += w4.w * v2.x; acc[3].y += w4.w * v2.y;
        }
        #pragma unroll
        for (int qi = 0; qi < 4; qi++)
            store_split2_f16(s_o, ND, b * NS + sRow + qi, h * HD + 2 * L,
                             acc[qi].x, acc[qi].y);
        __syncwarp();
    }
}

// ---------------- GEMM common macros ----------------
#define MMA_FP16(d, a0,a1,a2,a3, b0,b1)                                         \
    asm volatile("mma.sync.aligned.m16n8k16.row.col.f32.f16.f16.f32 "           \
                 "{%0,%1,%2,%3}, {%4,%5,%6,%7}, {%8,%9}, {%0,%1,%2,%3};"        \
                 : "+f"(d[0]), "+f"(d[1]), "+f"(d[2]), "+f"(d[3])               \
                 : "r"(a0), "r"(a1), "r"(a2), "r"(a3), "r"(b0), "r"(b1))

#define LDSM4(r, addr)                                                          \
    asm volatile("ldmatrix.sync.aligned.m8n8.x4.shared.b16 {%0,%1,%2,%3}, [%4];"\
                 : "=r"((r)[0]), "=r"((r)[1]), "=r"((r)[2]), "=r"((r)[3])       \
                 : "r"(addr))

#define CP16(dst, src)                                                          \
    asm volatile("cp.async.cg.shared.global [%0], [%1], 16;" :: "r"(dst), "l"(src))
#define CP_COMMIT() asm volatile("cp.async.commit_group;" ::: "memory")
#define CP_WAIT2()  asm volatile("cp.async.wait_group 2;" ::: "memory")

__device__ __forceinline__ uint32_t tile_off(int m, int kc) {   // 4KB blocks
    return (uint32_t)((m >> 6) * 4096 + (m & 63) * 32 +
                      ((kc ^ ((m >> 2) & 1)) << 4));
}
__device__ __forceinline__ uint32_t tile_off_h(int m, int kc) { // 2KB blocks
    return (uint32_t)((m >> 6) * 2048 + (m & 63) * 32 +
                      ((kc ^ ((m >> 2) & 1)) << 4));
}

// ---------------- 2-term split-fp16 GEMM (layer GEMMs) ----------------------
// A in split-fp16 tiles (hi|lo, 4KB/block), W single fp16 (2KB/block).
// D = Ah*W + Al*W, fp32 accum. TM=64 x TN=128, 8KB/stage, 4 stages.
// EPI: 0 = fp32+bias, 1 = fp32+bias+res, 2 = gelu -> split-fp16 tiles,
//      3 = bias+res -> fp16 single tile only (fused convert_x).
template <int EPI>
__global__ __launch_bounds__(256, 2)
void gemm_2t(const uint8_t* __restrict__ A, const uint8_t* __restrict__ W,
             const float* __restrict__ bias, const float* __restrict__ res,
             void* __restrict__ Cout, int M, int N, int K) {
    constexpr int ST   = 8192;
    constexpr int NSTG = 4;

    extern __shared__ uint8_t smem[];
    const uint32_t sb = smem_u32(smem);

    const int tid = threadIdx.x;
    const int bm = blockIdx.x * 64;
    const int bn = blockIdx.y * 128;
    const int wid = tid >> 5, lane = tid & 31;
    const int g = lane >> 2, t4 = lane & 3;
    const int wm = (wid >> 2) * 32;
    const int wn = (wid & 3) * 32;

    const int S = K >> 4;

    const int o0 = tid * 16;
    const int o1 = 4096 + tid * 16;
    const uint8_t* src0 = A + (size_t)blockIdx.x * S * 4096 + o0;
    const uint8_t* src1;
    {
        const int nt0 = blockIdx.y * 2;
        const int wsel = (o1 - 4096) >> 11;
        src1 = W + (size_t)(nt0 + wsel) * S * 2048 + ((o1 - 4096) & 2047);
    }

    const int sel = lane >> 3, ri = lane & 7;
    uint32_t aOffH[2], bOff[2];
    #pragma unroll
    for (int mf = 0; mf < 2; mf++) {
        const int m = wm + mf * 16 + (sel & 1) * 8 + ri;
        aOffH[mf] = tile_off(m, sel >> 1);
    }
    #pragma unroll
    for (int p = 0; p < 2; p++) {
        const int n = wn + p * 16 + (sel >> 1) * 8 + ri;
        bOff[p] = 4096 + tile_off_h(n, sel & 1);
    }

    float acc[2][4][4];
    #pragma unroll
    for (int i = 0; i < 2; i++)
        #pragma unroll
        for (int j = 0; j < 4; j++)
            #pragma unroll
            for (int c = 0; c < 4; c++) acc[i][j][c] = 0.f;

    #pragma unroll
    for (int s = 0; s < NSTG - 1; s++) {
        const uint32_t dst = sb + s * ST;
        CP16(dst + o0, src0);
        CP16(dst + o1, src1);
        src0 += 4096; src1 += 2048;
        CP_COMMIT();
    }

    for (int s = 0; s < S; s++) {
        CP_WAIT2();
        __syncthreads();

        const uint32_t stg = sb + (uint32_t)((s & 3) * ST);
        uint32_t aH[2][4], aL[2][4], bS[2][4];
        #pragma unroll
        for (int mf = 0; mf < 2; mf++) {
            LDSM4(aH[mf], stg + aOffH[mf]);
            LDSM4(aL[mf], stg + aOffH[mf] + 2048);
        }
        #pragma unroll
        for (int p = 0; p < 2; p++) LDSM4(bS[p], stg + bOff[p]);

        #pragma unroll
        for (int mf = 0; mf < 2; mf++)
            #pragma unroll
            for (int nf = 0; nf < 4; nf++) {
                const int p = nf >> 1, q = (nf & 1) * 2;
                MMA_FP16(acc[mf][nf], aH[mf][0], aH[mf][1], aH[mf][2], aH[mf][3],
                         bS[p][q], bS[p][q + 1]);
                MMA_FP16(acc[mf][nf], aL[mf][0], aL[mf][1], aL[mf][2], aL[mf][3],
                         bS[p][q], bS[p][q + 1]);
            }

        if (s + NSTG - 1 < S) {
            const uint32_t dst = sb + (uint32_t)(((s + NSTG - 1) & 3) * ST);
            CP16(dst + o0, src0);
            CP16(dst + o1, src1);
            src0 += 4096; src1 += 2048;
        }
        CP_COMMIT();
    }

    // ---- epilogue ----
    #pragma unroll
    for (int mf = 0; mf < 2; mf++) {
        const int r0 = bm + wm + mf * 16 + g;
        #pragma unroll
        for (int nf = 0; nf < 4; nf++) {
            const int c0 = bn + wn + nf * 8 + 2 * t4;
            const float2 bv = *(const float2*)(bias + c0);
            float v00 = acc[mf][nf][0] + bv.x;
            float v01 = acc[mf][nf][1] + bv.y;
            float v10 = acc[mf][nf][2] + bv.x;
            float v11 = acc[mf][nf][3] + bv.y;
            if (EPI == 2) {
                v00 = v00 * 0.5f * (1.0f + erff(v00 * 0.70710678118654752f));
                v01 = v01 * 0.5f * (1.0f + erff(v01 * 0.70710678118654752f));
                v10 = v10 * 0.5f * (1.0f + erff(v10 * 0.70710678118654752f));
                v11 = v11 * 0.5f * (1.0f + erff(v11 * 0.70710678118654752f));
                uint8_t* C = (uint8_t*)Cout;
                store_split2_f16(C, N, r0,     c0, v00, v01);
                store_split2_f16(C, N, r0 + 8, c0, v10, v11);
            } else if (EPI == 3) {
                const size_t i0 = (size_t)r0 * N + c0;
                const size_t i1 = (size_t)(r0 + 8) * N + c0;
                const float2 r0v = *(const float2*)(res + i0);
                const float2 r1v = *(const float2*)(res + i1);
                v00 += r0v.x; v01 += r0v.y; v10 += r1v.x; v11 += r1v.y;
                uint8_t* C = (uint8_t*)Cout;
                store_h2(C, N, r0,     c0, v00, v01);
                store_h2(C, N, r0 + 8, c0, v10, v11);
            } else {
                float* C = (float*)Cout;
                const size_t i0 = (size_t)r0 * N + c0;
                const size_t i1 = (size_t)(r0 + 8) * N + c0;
                if (EPI == 1) {
                    const float2 r0v = *(const float2*)(res + i0);
                    const float2 r1v = *(const float2*)(res + i1);
                    v00 += r0v.x; v01 += r0v.y; v10 += r1v.x; v11 += r1v.y;
                }
                *(float2*)(C + i0) = make_float2(v00, v01);
                *(float2*)(C + i1) = make_float2(v10, v11);
            }
        }
    }
}

// ---------------- fp16 single-term GEMM (vocab), 2 k-chunks/stage ------------
// TM=128 x 128, 16 KB/stage (2 chunks of 8 KB), 4 stages = 64 KB, 2 CTAs/SM.
__global__ __launch_bounds__(256, 2)
void gemm_h(const uint8_t* __restrict__ A, const uint8_t* __restrict__ W,
            const float* __restrict__ bias, float* __restrict__ C,
            int M, int N, int K) {
    constexpr int ST   = 16384;
    constexpr int NSTG = 4;

    extern __shared__ uint8_t smem[];
    const uint32_t sb = smem_u32(smem);

    const int tid = threadIdx.x;
    const int bm = blockIdx.x * 128;
    const int bn = blockIdx.y * 128;
    const int wid = tid >> 5, lane = tid & 31;
    const int g = lane >> 2, t4 = lane & 3;
    const int wm = (wid >> 2) * 64;
    const int wn = (wid & 3) * 32;

    const int S = K >> 4;        // 32 k-chunks
    const int SP = S >> 1;       // 16 pipeline stages

    const int o0 = tid * 16;            // within 8KB chunk-half: blocks 0-1 (A)
    const int o1 = 4096 + tid * 16;     // blocks 2-3 (W)
    const uint8_t* src0;
    const uint8_t* src1;
    {
        const int mt0 = blockIdx.x * 2;
        const int nt0 = blockIdx.y * 2;
        const uint8_t* blkp[4];
        blkp[0] = A + (size_t)(mt0 + 0) * S * 2048;
        blkp[1] = A + (size_t)(mt0 + 1) * S * 2048;
        blkp[2] = W + (size_t)(nt0 + 0) * S * 2048;
        blkp[3] = W + (size_t)(nt0 + 1) * S * 2048;
        src0 = blkp[o0 >> 11] + (o0 & 2047);
        src1 = blkp[o1 >> 11] + (o1 & 2047);
    }

    const int sel = lane >> 3, ri = lane & 7;
    uint32_t aOff[4], bOff[2];
    #pragma unroll
    for (int mf = 0; mf < 4; mf++) {
        const int m = wm + mf * 16 + (sel & 1) * 8 + ri;
        aOff[mf] = tile_off_h(m, sel >> 1);
    }
    #pragma unroll
    for (int p = 0; p < 2; p++) {
        const int n = wn + p * 16 + (sel >> 1) * 8 + ri;
        bOff[p] = 4096 + tile_off_h(n, sel & 1);
    }

    float acc[4][4][4];
    #pragma unroll
    for (int i = 0; i < 4; i++)
        #pragma unroll
        for (int j = 0; j < 4; j++)
            #pragma unroll
            for (int c = 0; c < 4; c++) acc[i][j][c] = 0.f;

    // prologue: 3 stages, each stage = 2 chunks (4 cp.async/thread)
    #pragma unroll
    for (int s = 0; s < NSTG - 1; s++) {
        const uint32_t dst = sb + s * ST;
        CP16(dst + o0, src0);
        CP16(dst + o1, src1);
        CP16(dst + 8192 + o0, src0 + 2048);
        CP16(dst + 8192 + o1, src1 + 2048);
        src0 += 4096; src1 += 4096;
        CP_COMMIT();
    }

    for (int s = 0; s < SP; s++) {
        CP_WAIT2();
        __syncthreads();

        const uint32_t stg = sb + (uint32_t)((s & 3) * ST);
        #pragma unroll
        for (int j = 0; j < 2; j++) {
            const uint32_t cofs = stg + j * 8192;
            uint32_t aF[4][4], bF[2][4];
            #pragma unroll
            for (int mf = 0; mf < 4; mf++) LDSM4(aF[mf], cofs + aOff[mf]);
            #pragma unroll
            for (int p = 0; p < 2; p++)    LDSM4(bF[p], cofs + bOff[p]);

            #pragma unroll
            for (int mf = 0; mf < 4; mf++)
                #pragma unroll
                for (int nf = 0; nf < 4; nf++) {
                    const int p = nf >> 1, q = (nf & 1) * 2;
                    MMA_FP16(acc[mf][nf], aF[mf][0], aF[mf][1], aF[mf][2], aF[mf][3],
                             bF[p][q], bF[p][q + 1]);
                }
        }

        if (s + NSTG - 1 < SP) {
            const uint32_t dst = sb + (uint32_t)(((s + NSTG - 1) & 3) * ST);
            CP16(dst + o0, src0);
            CP16(dst + o1, src1);
            CP16(dst + 8192 + o0, src0 + 2048);
            CP16(dst + 8192 + o1, src1 + 2048);
            src0 += 4096; src1 += 4096;
        }
        CP_COMMIT();
    }

    #pragma unroll
    for (int mf = 0; mf < 4; mf++) {
        const int r0 = bm + wm + mf * 16 + g;
        #pragma unroll
        for (int nf = 0; nf < 4; nf++) {
            const int c0 = bn + wn + nf * 8 + 2 * t4;
            const float2 bv = *(const float2*)(bias + c0);
            const size_t i0 = (size_t)r0 * N + c0;
            const size_t i1 = (size_t)(r0 + 8) * N + c0;
            *(float2*)(C + i0) = make_float2(acc[mf][nf][0] + bv.x, acc[mf][nf][1] + bv.y);
            *(float2*)(C + i1) = make_float2(acc[mf][nf][2] + bv.x, acc[mf][nf][3] + bv.y);
        }
    }
}

// ---------------- launch ----------------
extern "C" void kernel_launch(void* const* d_in, const int* in_sizes, int n_in,
                              void* d_out, int out_size) {
    const float* patches        = (const float*)d_in[0];
    const float* masked_token   = (const float*)d_in[3];
    const float* partial_params = (const float*)d_in[4];
    const float* emb_w          = (const float*)d_in[5];
    const float* emb_b          = (const float*)d_in[6];
    const float* ln1_g          = (const float*)d_in[7];
    const float* ln1_b          = (const float*)d_in[8];
    const float* in_proj_w      = (const float*)d_in[9];
    const float* in_proj_b      = (const float*)d_in[10];
    const float* out_proj_w     = (const float*)d_in[11];
    const float* out_proj_b     = (const float*)d_in[12];
    const float* rel_pos        = (const float*)d_in[13];
    const float* ln2_g          = (const float*)d_in[14];
    const float* ln2_b           = (const float*)d_in[15];
    const float* ffn_w1         = (const float*)d_in[16];
    const float* ffn_b1         = (const float*)d_in[17];
    const float* ffn_w2         = (const float*)d_in[18];
    const float* ffn_b2         = (const float*)d_in[19];
    const float* outp_w         = (const float*)d_in[20];
    const float* outp_b         = (const float*)d_in[21];
    float* out = (float*)d_out;

    float *x, *qkv;
    uint8_t *xn, *o, *h, *xf, *win, *wo, *w1, *w2, *wv;
    cudaGetSymbolAddress((void**)&x,   g_x);
    cudaGetSymbolAddress((void**)&qkv, g_qkv);
    cudaGetSymbolAddress((void**)&xn,  s_xn);
    cudaGetSymbolAddress((void**)&o,   s_o);
    cudaGetSymbolAddress((void**)&h,   s_h);
    cudaGetSymbolAddress((void**)&xf,  s_xf);
    cudaGetSymbolAddress((void**)&win, s_win);
    cudaGetSymbolAddress((void**)&wo,  s_wo);
    cudaGetSymbolAddress((void**)&w1,  s_w1);
    cudaGetSymbolAddress((void**)&w2,  s_w2);
    cudaGetSymbolAddress((void**)&wv,  s_wv);

    cudaFuncSetAttribute(attn_kernel, cudaFuncAttributeMaxDynamicSharedMemorySize, ATTN_SMEM);
    cudaFuncSetAttribute((const void*)gemm_2t<0>, cudaFuncAttributeMaxDynamicSharedMemorySize, 32768);
    cudaFuncSetAttribute((const void*)gemm_2t<1>, cudaFuncAttributeMaxDynamicSharedMemorySize, 32768);
    cudaFuncSetAttribute((const void*)gemm_2t<2>, cudaFuncAttributeMaxDynamicSharedMemorySize, 32768);
    cudaFuncSetAttribute((const void*)gemm_2t<3>, cudaFuncAttributeMaxDynamicSharedMemorySize, 32768);
    cudaFuncSetAttribute((const void*)gemm_h, cudaFuncAttributeMaxDynamicSharedMemorySize, 65536);

    // ---- convert all weights to fp16 single tiles ----
    {
        int nc;
        nc = NL * 3 * ND * ND / 8;  convert_w_h<<<(nc + 255) / 256, 256>>>(in_proj_w,  win, ND, nc);
        nc = NL * ND * ND / 8;      convert_w_h<<<(nc + 255) / 256, 256>>>(out_proj_w, wo,  ND, nc);
        nc = NL * NF * ND / 8;      convert_w_h<<<(nc + 255) / 256, 256>>>(ffn_w1,     w1,  ND, nc);
        nc = NL * ND * NF / 8;      convert_w_h<<<(nc + 255) / 256, 256>>>(ffn_w2,     w2,  NF, nc);
        nc = (int)((size_t)NV * ND / 8);
        convert_w_h<<<(nc + 255) / 256, 256>>>(outp_w, wv, ND, nc);
    }

    tokenize_embed_kernel<<<NTOK, 128>>>(patches, masked_token, partial_params, emb_w, emb_b);

    for (int l = 0; l < NL; l++) {
        ln_kernel<<<NTOK, 256>>>(x, xn, ln1_g + l * ND, ln1_b + l * ND);

        gemm_2t<0><<<dim3(NTOK / 64, 3 * ND / 128), 256, 32768>>>(
            xn, win + (size_t)l * 3 * ND * ND * 2, in_proj_b + l * 3 * ND,
            nullptr, qkv, NTOK, 3 * ND, ND);

        attn_kernel<<<NB * NH * 2, 512, ATTN_SMEM>>>(rel_pos + (size_t)l * NS * NS);

        gemm_2t<1><<<dim3(NTOK / 64, ND / 128), 256, 32768>>>(
            o, wo + (size_t)l * ND * ND * 2, out_proj_b + l * ND,
            x, x, NTOK, ND, ND);

        ln_kernel<<<NTOK, 256>>>(x, xn, ln2_g + l * ND, ln2_b + l * ND);

        gemm_2t<2><<<dim3(NTOK / 64, NF / 128), 256, 32768>>>(
            xn, w1 + (size_t)l * NF * ND * 2, ffn_b1 + l * NF,
            nullptr, h, NTOK, NF, ND);

        if (l < NL - 1) {
            gemm_2t<1><<<dim3(NTOK / 64, ND / 128), 256, 32768>>>(
                h, w2 + (size_t)l * ND * NF * 2, ffn_b2 + l * ND,
                x, x, NTOK, ND, NF);
        } else {
            // last layer: fuse residual + fp16 conversion for vocab input
            gemm_2t<3><<<dim3(NTOK / 64, ND / 128), 256, 32768>>>(
                h, w2 + (size_t)l * ND * NF * 2, ffn_b2 + l * ND,
                x, xf, NTOK, ND, NF);
        }
    }

    gemm_h<<<dim3(NTOK / 128, NV / 128), 256, 65536>>>(
        xf, wv, outp_b, out, NTOK, NV, ND);
}

// round 14
// speedup vs baseline: 1.8373x; 1.1151x over previous
#include <cuda_runtime.h>
#include <cuda_bf16.h>
#include <cuda_fp16.h>
#include <math.h>
#include <stdint.h>

// ---------------- problem constants ----------------
#define NB   8
#define NS   256
#define NP   16
#define ND   512
#define NH   8
#define HD   64
#define NL   6
#define NF   2048
#define NV   65536
#define NTOK (NB * NS)   // 2048

// ---------------- scratch (device globals; no allocation) ----------------
__device__ float g_x  [NTOK * ND];          // residual stream (fp32)
__device__ float g_qkv[NTOK * 3 * ND];      // qkv projection (fp32)

// split-fp16 activation tiles (hi|lo 2KB halves of 4KB blocks, swizzled)
__device__ uint8_t s_xn [NTOK * ND * 4];
__device__ uint8_t s_o  [NTOK * ND * 4];
__device__ uint8_t s_h  [NTOK * NF * 4];
// fp16 single tiles (2KB blocks) for weights + vocab A
__device__ uint8_t s_win[NL * 3 * ND * ND * 2];
__device__ uint8_t s_wo [NL * ND * ND * 2];
__device__ uint8_t s_w1 [NL * NF * ND * 2];
__device__ uint8_t s_w2 [(size_t)NL * ND * NF * 2];
__device__ uint8_t s_xf [NTOK * ND * 2];
__device__ uint8_t s_wv [(size_t)NV * ND * 2];

__device__ __forceinline__ uint32_t smem_u32(const void* p) {
    uint32_t a;
    asm("{ .reg .u64 t; cvta.to.shared.u64 t, %1; cvt.u32.u64 %0, t; }" : "=r"(a) : "l"(p));
    return a;
}

// ---------------- split / store helpers ----------------
__device__ __forceinline__ void store_split2_f16(uint8_t* base, int K, int row, int col,
                                                 float a, float b) {
    __half ha = __float2half_rn(a);
    __half hb = __float2half_rn(b);
    __half2 hi = __halves2half2(ha, hb);
    __half2 lo = __floats2half2_rn(a - __half2float(ha), b - __half2float(hb));
    size_t blk = (size_t)(row >> 6) * (K >> 4) + (col >> 4);
    uint32_t off = (uint32_t)((row & 63) * 32 +
                   ((((col >> 3) & 1) ^ ((row >> 2) & 1)) << 4) + (col & 7) * 2);
    *(__half2*)(base + blk * 4096 + off) = hi;
    *(__half2*)(base + blk * 4096 + 2048 + off) = lo;
}
__device__ __forceinline__ void store_h2(uint8_t* base, int K, int row, int col,
                                         float a, float b) {
    __half2 h = __floats2half2_rn(a, b);
    size_t blk = (size_t)(row >> 6) * (K >> 4) + (col >> 4);
    uint32_t off = (uint32_t)((row & 63) * 32 +
                   ((((col >> 3) & 1) ^ ((row >> 2) & 1)) << 4) + (col & 7) * 2);
    *(__half2*)(base + blk * 2048 + off) = h;
}

// ---------------- weight conversion (fp32 [R,K] -> fp16 single tiles) --------
__global__ void convert_w_h(const float* __restrict__ src, uint8_t* __restrict__ dst,
                            int K, int nChunks) {
    int ct = blockIdx.x * 256 + threadIdx.x;
    if (ct >= nChunks) return;
    int within = ct & 127;
    int blk = ct >> 7;
    int r = within >> 1, kc = within & 1;
    int stages = K >> 4;
    int rt = blk / stages, s = blk - rt * stages;
    const float* p = src + (size_t)(rt * 64 + r) * K + s * 16 + kc * 8;
    float4 v0 = *(const float4*)p, v1 = *(const float4*)(p + 4);
    __half2 h0 = __floats2half2_rn(v0.x, v0.y);
    __half2 h1 = __floats2half2_rn(v0.z, v0.w);
    __half2 h2 = __floats2half2_rn(v1.x, v1.y);
    __half2 h3 = __floats2half2_rn(v1.z, v1.w);
    uint4 hv;
    hv.x = *(unsigned*)&h0; hv.y = *(unsigned*)&h1;
    hv.z = *(unsigned*)&h2; hv.w = *(unsigned*)&h3;
    uint32_t off = (uint32_t)(r * 32 + ((kc ^ ((r >> 2) & 1)) << 4));
    *(uint4*)(dst + (size_t)blk * 2048 + off) = hv;
}

// ---------------- tokenize + embed ----------------
__global__ void tokenize_embed_kernel(const float* __restrict__ patches,
                                      const float* __restrict__ masked_token,
                                      const float* __restrict__ partial_params,
                                      const float* __restrict__ emb_w,
                                      const float* __restrict__ emb_b) {
    const int tok = blockIdx.x;
    const int tid = threadIdx.x;   // 128 threads
    __shared__ float proc[NP];

    if (tid == 0) {
        const float* f = patches + (size_t)tok * NP;
        bool anyMask = false, anyBin = false;
        int firstBin = -1;
        float fp[NP];
        #pragma unroll
        for (int p = 0; p < NP; p++) {
            float v = f[p];
            fp[p] = v;
            bool m = fabsf(v - 0.5f) < 0.1f;
            if (m) anyMask = true;
            else { anyBin = true; if (firstBin < 0) firstBin = p; }
        }
        if (!anyBin) {
            #pragma unroll
            for (int p = 0; p < NP; p++) proc[p] = masked_token[p];
        } else if (anyMask) {
            int ptok = firstBin * 2 + (int)rintf(fp[firstBin]);
            const float* pp = partial_params + ptok * NP;
            #pragma unroll
            for (int p = 0; p < NP; p++) proc[p] = pp[p];
        } else {
            #pragma unroll
            for (int p = 0; p < NP; p++) proc[p] = fp[p];
        }
    }
    __syncthreads();

    for (int d = tid; d < ND; d += blockDim.x) {
        const float* w = emb_w + d * NP;
        float s = emb_b[d];
        #pragma unroll
        for (int p = 0; p < NP; p++) s += proc[p] * w[p];
        g_x[(size_t)tok * ND + d] = s;
    }
}

// ---------------- layernorm (fp32 in -> split-fp16 tile out) ----------------
__global__ void ln_kernel(const float* __restrict__ in, uint8_t* __restrict__ out,
                          const float* __restrict__ gamma, const float* __restrict__ beta) {
    const int tok = blockIdx.x;
    const int tid = threadIdx.x;   // 256
    const float2 v = ((const float2*)(in + (size_t)tok * ND))[tid];

    float s  = v.x + v.y;
    float sq = v.x * v.x + v.y * v.y;
    #pragma unroll
    for (int off = 16; off; off >>= 1) {
        s  += __shfl_xor_sync(0xffffffffu, s,  off);
        sq += __shfl_xor_sync(0xffffffffu, sq, off);
    }
    __shared__ float rs[8], rq[8], stats[2];
    if ((tid & 31) == 0) { rs[tid >> 5] = s; rq[tid >> 5] = sq; }
    __syncthreads();
    if (tid == 0) {
        float S = 0.f, Q = 0.f;
        #pragma unroll
        for (int i = 0; i < 8; i++) { S += rs[i]; Q += rq[i]; }
        float mean = S * (1.0f / ND);
        float var  = Q * (1.0f / ND) - mean * mean;
        stats[0] = mean;
        stats[1] = rsqrtf(var + 1e-5f);
    }
    __syncthreads();
    const float mean = stats[0], inv = stats[1];
    float2 g2 = ((const float2*)gamma)[tid];
    float2 b2 = ((const float2*)beta)[tid];
    float ox = (v.x - mean) * inv * g2.x + b2.x;
    float oy = (v.y - mean) * inv * g2.y + b2.y;
    store_split2_f16(out, ND, tok, tid * 2, ox, oy);
}

// ---------------- fused attention (smem K/V, 512 threads, split out) --------
#define ATTN_SMEM (224 * 1024)

__global__ __launch_bounds__(512) void attn_kernel(const float* __restrict__ rel) {
    extern __shared__ float sm[];
    float* Ks = sm;            // [256][64] rotated rows
    float* Vs = sm + 16384;    // [256][64]
    float* Qs = sm + 32768;    // [128][64]
    float* Wb = sm + 40960;    // [16 warps][256][4]

    const int idx = blockIdx.x;
    const int qc = idx & 1;
    const int h  = (idx >> 1) & (NH - 1);
    const int b  = idx >> 4;
    const int tid = threadIdx.x, wid = tid >> 5, L = tid & 31;

    const size_t base = (size_t)(b * NS) * (3 * ND) + h * HD;

    {
        const int dc = (tid & 15) * 4;
        int t = tid >> 4;   // 0..31
        #pragma unroll 4
        for (int pass = 0; pass < 8; pass++, t += 32) {
            const float* kR = g_qkv + base + ND + (size_t)t * (3 * ND);
            float4 kv = *(const float4*)(kR + dc);
            const int p = (dc + 4 * (t & 15)) & 63;
            *(float4*)(Ks + t * 64 + p) = kv;
            const float* vR = g_qkv + base + 2 * ND + (size_t)t * (3 * ND);
            *(float4*)(Vs + t * 64 + dc) = *(const float4*)(vR + dc);
        }
        int q = tid >> 4;
        #pragma unroll 4
        for (int pass = 0; pass < 4; pass++, q += 32) {
            const float* qR = g_qkv + base + (size_t)(qc * 128 + q) * (3 * ND);
            *(float4*)(Qs + q * 64 + dc) = *(const float4*)(qR + dc);
        }
    }
    __syncthreads();

    float* wb = Wb + wid * 1024;
    const int rot = 4 * (L & 15);

    for (int g4 = 0; g4 < 2; g4++) {
        const int q0 = wid * 8 + g4 * 4;
        const int sRow = qc * 128 + q0;

        float sc[4][8];
        #pragma unroll
        for (int qi = 0; qi < 4; qi++)
            #pragma unroll
            for (int j = 0; j < 8; j++) sc[qi][j] = 0.f;

        #pragma unroll
        for (int dd = 0; dd < 16; dd++) {
            const int d = dd * 4;
            float4 qv[4];
            #pragma unroll
            for (int qi = 0; qi < 4; qi++)
                qv[qi] = *(const float4*)(Qs + (q0 + qi) * 64 + d);
            const int p = (d + rot) & 63;
            #pragma unroll
            for (int j = 0; j < 8; j++) {
                float4 k4 = *(const float4*)(Ks + (L + 32 * j) * 64 + p);
                #pragma unroll
                for (int qi = 0; qi < 4; qi++)
                    sc[qi][j] += qv[qi].x * k4.x + qv[qi].y * k4.y +
                                 qv[qi].z * k4.z + qv[qi].w * k4.w;
            }
        }

        #pragma unroll
        for (int qi = 0; qi < 4; qi++) {
            const float* rrow = rel + (size_t)(sRow + qi) * NS;
            float m = -1e30f;
            #pragma unroll
            for (int j = 0; j < 8; j++) {
                float v = sc[qi][j] * 0.125f + rrow[L + 32 * j];
                sc[qi][j] = v;
                m = fmaxf(m, v);
            }
            #pragma unroll
            for (int off = 16; off; off >>= 1)
                m = fmaxf(m, __shfl_xor_sync(0xffffffffu, m, off));
            float ssum = 0.f;
            #pragma unroll
            for (int j = 0; j < 8; j++) { sc[qi][j] = expf(sc[qi][j] - m); ssum += sc[qi][j]; }
            #pragma unroll
            for (int off = 16; off; off >>= 1)
                ssum += __shfl_xor_sync(0xffffffffu, ssum, off);
            const float inv = 1.0f / ssum;
            #pragma unroll
            for (int j = 0; j < 8; j++) sc[qi][j] *= inv;
        }

        #pragma unroll
        for (int j = 0; j < 8; j++)
            *(float4*)(wb + (L + 32 * j) * 4) =
                make_float4(sc[0][j], sc[1][j], sc[2][j], sc[3][j]);
        __syncwarp();

        float2 acc[4];
        #pragma unroll
        for (int qi = 0; qi < 4; qi++) acc[qi] = make_float2(0.f, 0.f);
        #pragma unroll 4
        for (int t = 0; t < NS; t++) {
            float2 v2 = *(const float2*)(Vs + t * 64 + 2 * L);
            float4 w4 = *(const float4*)(wb + t * 4);
            acc[0].x += w4.x * v2.x; acc[0].y += w4.x * v2.y;
            acc[1].x += w4.y * v2.x; acc[1].y += w4.y * v2.y;
            acc[2].x += w4.z * v2.x; acc[2].y += w4.z * v2.y;
            acc[3].x += w4.w * v2.x; acc[3].y += w4.w * v2.y;
        }
        #pragma unroll
        for (int qi = 0; qi < 4; qi++)
            store_split2_f16(s_o, ND, b * NS + sRow + qi, h * HD + 2 * L,
                             acc[qi].x, acc[qi].y);
        __syncwarp();
    }
}

// ---------------- GEMM common macros ----------------
#define MMA_FP16(d, a0,a1,a2,a3, b0,b1)                                         \
    asm volatile("mma.sync.aligned.m16n8k16.row.col.f32.f16.f16.f32 "           \
                 "{%0,%1,%2,%3}, {%4,%5,%6,%7}, {%8,%9}, {%0,%1,%2,%3};"        \
                 : "+f"(d[0]), "+f"(d[1]), "+f"(d[2]), "+f"(d[3])               \
                 : "r"(a0), "r"(a1), "r"(a2), "r"(a3), "r"(b0), "r"(b1))

#define LDSM4(r, addr)                                                          \
    asm volatile("ldmatrix.sync.aligned.m8n8.x4.shared.b16 {%0,%1,%2,%3}, [%4];"\
                 : "=r"((r)[0]), "=r"((r)[1]), "=r"((r)[2]), "=r"((r)[3])       \
                 : "r"(addr))

#define CP16(dst, src)                                                          \
    asm volatile("cp.async.cg.shared.global [%0], [%1], 16;" :: "r"(dst), "l"(src))
#define CP_COMMIT() asm volatile("cp.async.commit_group;" ::: "memory")
#define CP_WAIT2()  asm volatile("cp.async.wait_group 2;" ::: "memory")

__device__ __forceinline__ uint32_t tile_off(int m, int kc) {   // 4KB blocks
    return (uint32_t)((m >> 6) * 4096 + (m & 63) * 32 +
                      ((kc ^ ((m >> 2) & 1)) << 4));
}
__device__ __forceinline__ uint32_t tile_off_h(int m, int kc) { // 2KB blocks
    return (uint32_t)((m >> 6) * 2048 + (m & 63) * 32 +
                      ((kc ^ ((m >> 2) & 1)) << 4));
}

// ---------------- 2-term split-fp16 GEMM (layer GEMMs), 2 k-chunks/stage ----
// A in split-fp16 tiles (hi|lo, 4KB/block), W single fp16 (2KB/block).
// D = Ah*W + Al*W, fp32 accum. TM=64 x TN=128.
// Stage = 2 k16 chunks = 16 KB ([A 4K | W 4K] x2), 4 stages = 64 KB, 2 CTAs/SM.
// EPI: 0 = fp32+bias, 1 = fp32+bias+res, 2 = gelu -> split-fp16 tiles,
//      3 = bias+res -> fp16 single tile only (fused convert_x).
template <int EPI>
__global__ __launch_bounds__(256, 2)
void gemm_2t(const uint8_t* __restrict__ A, const uint8_t* __restrict__ W,
             const float* __restrict__ bias, const float* __restrict__ res,
             void* __restrict__ Cout, int M, int N, int K) {
    constexpr int CH   = 8192;    // bytes per k16 chunk in smem
    constexpr int ST   = 2 * CH;  // stage = 2 chunks
    constexpr int NSTG = 4;

    extern __shared__ uint8_t smem[];
    const uint32_t sb = smem_u32(smem);

    const int tid = threadIdx.x;
    const int bm = blockIdx.x * 64;
    const int bn = blockIdx.y * 128;
    const int wid = tid >> 5, lane = tid & 31;
    const int g = lane >> 2, t4 = lane & 3;
    const int wm = (wid >> 2) * 32;
    const int wn = (wid & 3) * 32;

    const int S  = K >> 4;   // k16 chunks
    const int SP = S >> 1;   // pipeline stages

    const int o0 = tid * 16;            // A region [0,4096)
    const int o1 = 4096 + tid * 16;     // W region [4096,8192)
    const uint8_t* src0 = A + (size_t)blockIdx.x * S * 4096 + o0;
    const uint8_t* src1;
    {
        const int nt0 = blockIdx.y * 2;
        const int wsel = (o1 - 4096) >> 11;
        src1 = W + (size_t)(nt0 + wsel) * S * 2048 + ((o1 - 4096) & 2047);
    }

    const int sel = lane >> 3, ri = lane & 7;
    uint32_t aOffH[2], bOff[2];
    #pragma unroll
    for (int mf = 0; mf < 2; mf++) {
        const int m = wm + mf * 16 + (sel & 1) * 8 + ri;
        aOffH[mf] = tile_off(m, sel >> 1);
    }
    #pragma unroll
    for (int p = 0; p < 2; p++) {
        const int n = wn + p * 16 + (sel >> 1) * 8 + ri;
        bOff[p] = 4096 + tile_off_h(n, sel & 1);
    }

    float acc[2][4][4];
    #pragma unroll
    for (int i = 0; i < 2; i++)
        #pragma unroll
        for (int j = 0; j < 4; j++)
            #pragma unroll
            for (int c = 0; c < 4; c++) acc[i][j][c] = 0.f;

    // prologue: 3 stages x 2 chunks
    #pragma unroll
    for (int s = 0; s < NSTG - 1; s++) {
        const uint32_t dst = sb + s * ST;
        CP16(dst + o0, src0);
        CP16(dst + o1, src1);
        CP16(dst + CH + o0, src0 + 4096);
        CP16(dst + CH + o1, src1 + 2048);
        src0 += 8192; src1 += 4096;
        CP_COMMIT();
    }

    for (int s = 0; s < SP; s++) {
        CP_WAIT2();
        __syncthreads();

        const uint32_t stg = sb + (uint32_t)((s & 3) * ST);
        #pragma unroll
        for (int j = 0; j < 2; j++) {
            const uint32_t cofs = stg + j * CH;
            uint32_t aH[2][4], aL[2][4], bS[2][4];
            #pragma unroll
            for (int mf = 0; mf < 2; mf++) {
                LDSM4(aH[mf], cofs + aOffH[mf]);
                LDSM4(aL[mf], cofs + aOffH[mf] + 2048);
            }
            #pragma unroll
            for (int p = 0; p < 2; p++) LDSM4(bS[p], cofs + bOff[p]);

            #pragma unroll
            for (int mf = 0; mf < 2; mf++)
                #pragma unroll
                for (int nf = 0; nf < 4; nf++) {
                    const int p = nf >> 1, q = (nf & 1) * 2;
                    MMA_FP16(acc[mf][nf], aH[mf][0], aH[mf][1], aH[mf][2], aH[mf][3],
                             bS[p][q], bS[p][q + 1]);
                    MMA_FP16(acc[mf][nf], aL[mf][0], aL[mf][1], aL[mf][2], aL[mf][3],
                             bS[p][q], bS[p][q + 1]);
                }
        }

        if (s + NSTG - 1 < SP) {
            const uint32_t dst = sb + (uint32_t)(((s + NSTG - 1) & 3) * ST);
            CP16(dst + o0, src0);
            CP16(dst + o1, src1);
            CP16(dst + CH + o0, src0 + 4096);
            CP16(dst + CH + o1, src1 + 2048);
            src0 += 8192; src1 += 4096;
        }
        CP_COMMIT();
    }

    // ---- epilogue ----
    #pragma unroll
    for (int mf = 0; mf < 2; mf++) {
        const int r0 = bm + wm + mf * 16 + g;
        #pragma unroll
        for (int nf = 0; nf < 4; nf++) {
            const int c0 = bn + wn + nf * 8 + 2 * t4;
            const float2 bv = *(const float2*)(bias + c0);
            float v00 = acc[mf][nf][0] + bv.x;
            float v01 = acc[mf][nf][1] + bv.y;
            float v10 = acc[mf][nf][2] + bv.x;
            float v11 = acc[mf][nf][3] + bv.y;
            if (EPI == 2) {
                v00 = v00 * 0.5f * (1.0f + erff(v00 * 0.70710678118654752f));
                v01 = v01 * 0.5f * (1.0f + erff(v01 * 0.70710678118654752f));
                v10 = v10 * 0.5f * (1.0f + erff(v10 * 0.70710678118654752f));
                v11 = v11 * 0.5f * (1.0f + erff(v11 * 0.70710678118654752f));
                uint8_t* C = (uint8_t*)Cout;
                store_split2_f16(C, N, r0,     c0, v00, v01);
                store_split2_f16(C, N, r0 + 8, c0, v10, v11);
            } else if (EPI == 3) {
                const size_t i0 = (size_t)r0 * N + c0;
                const size_t i1 = (size_t)(r0 + 8) * N + c0;
                const float2 r0v = *(const float2*)(res + i0);
                const float2 r1v = *(const float2*)(res + i1);
                v00 += r0v.x; v01 += r0v.y; v10 += r1v.x; v11 += r1v.y;
                uint8_t* C = (uint8_t*)Cout;
                store_h2(C, N, r0,     c0, v00, v01);
                store_h2(C, N, r0 + 8, c0, v10, v11);
            } else {
                float* C = (float*)Cout;
                const size_t i0 = (size_t)r0 * N + c0;
                const size_t i1 = (size_t)(r0 + 8) * N + c0;
                if (EPI == 1) {
                    const float2 r0v = *(const float2*)(res + i0);
                    const float2 r1v = *(const float2*)(res + i1);
                    v00 += r0v.x; v01 += r0v.y; v10 += r1v.x; v11 += r1v.y;
                }
                *(float2*)(C + i0) = make_float2(v00, v01);
                *(float2*)(C + i1) = make_float2(v10, v11);
            }
        }
    }
}

// ---------------- fp16 single-term GEMM (vocab), 2 k-chunks/stage ------------
__global__ __launch_bounds__(256, 2)
void gemm_h(const uint8_t* __restrict__ A, const uint8_t* __restrict__ W,
            const float* __restrict__ bias, float* __restrict__ C,
            int M, int N, int K) {
    constexpr int ST   = 16384;
    constexpr int NSTG = 4;

    extern __shared__ uint8_t smem[];
    const uint32_t sb = smem_u32(smem);

    const int tid = threadIdx.x;
    const int bm = blockIdx.x * 128;
    const int bn = blockIdx.y * 128;
    const int wid = tid >> 5, lane = tid & 31;
    const int g = lane >> 2, t4 = lane & 3;
    const int wm = (wid >> 2) * 64;
    const int wn = (wid & 3) * 32;

    const int S = K >> 4;
    const int SP = S >> 1;

    const int o0 = tid * 16;
    const int o1 = 4096 + tid * 16;
    const uint8_t* src0;
    const uint8_t* src1;
    {
        const int mt0 = blockIdx.x * 2;
        const int nt0 = blockIdx.y * 2;
        const uint8_t* blkp[4];
        blkp[0] = A + (size_t)(mt0 + 0) * S * 2048;
        blkp[1] = A + (size_t)(mt0 + 1) * S * 2048;
        blkp[2] = W + (size_t)(nt0 + 0) * S * 2048;
        blkp[3] = W + (size_t)(nt0 + 1) * S * 2048;
        src0 = blkp[o0 >> 11] + (o0 & 2047);
        src1 = blkp[o1 >> 11] + (o1 & 2047);
    }

    const int sel = lane >> 3, ri = lane & 7;
    uint32_t aOff[4], bOff[2];
    #pragma unroll
    for (int mf = 0; mf < 4; mf++) {
        const int m = wm + mf * 16 + (sel & 1) * 8 + ri;
        aOff[mf] = tile_off_h(m, sel >> 1);
    }
    #pragma unroll
    for (int p = 0; p < 2; p++) {
        const int n = wn + p * 16 + (sel >> 1) * 8 + ri;
        bOff[p] = 4096 + tile_off_h(n, sel & 1);
    }

    float acc[4][4][4];
    #pragma unroll
    for (int i = 0; i < 4; i++)
        #pragma unroll
        for (int j = 0; j < 4; j++)
            #pragma unroll
            for (int c = 0; c < 4; c++) acc[i][j][c] = 0.f;

    #pragma unroll
    for (int s = 0; s < NSTG - 1; s++) {
        const uint32_t dst = sb + s * ST;
        CP16(dst + o0, src0);
        CP16(dst + o1, src1);
        CP16(dst + 8192 + o0, src0 + 2048);
        CP16(dst + 8192 + o1, src1 + 2048);
        src0 += 4096; src1 += 4096;
        CP_COMMIT();
    }

    for (int s = 0; s < SP; s++) {
        CP_WAIT2();
        __syncthreads();

        const uint32_t stg = sb + (uint32_t)((s & 3) * ST);
        #pragma unroll
        for (int j = 0; j < 2; j++) {
            const uint32_t cofs = stg + j * 8192;
            uint32_t aF[4][4], bF[2][4];
            #pragma unroll
            for (int mf = 0; mf < 4; mf++) LDSM4(aF[mf], cofs + aOff[mf]);
            #pragma unroll
            for (int p = 0; p < 2; p++)    LDSM4(bF[p], cofs + bOff[p]);

            #pragma unroll
            for (int mf = 0; mf < 4; mf++)
                #pragma unroll
                for (int nf = 0; nf < 4; nf++) {
                    const int p = nf >> 1, q = (nf & 1) * 2;
                    MMA_FP16(acc[mf][nf], aF[mf][0], aF[mf][1], aF[mf][2], aF[mf][3],
                             bF[p][q], bF[p][q + 1]);
                }
        }

        if (s + NSTG - 1 < SP) {
            const uint32_t dst = sb + (uint32_t)(((s + NSTG - 1) & 3) * ST);
            CP16(dst + o0, src0);
            CP16(dst + o1, src1);
            CP16(dst + 8192 + o0, src0 + 2048);
            CP16(dst + 8192 + o1, src1 + 2048);
            src0 += 4096; src1 += 4096;
        }
        CP_COMMIT();
    }

    #pragma unroll
    for (int mf = 0; mf < 4; mf++) {
        const int r0 = bm + wm + mf * 16 + g;
        #pragma unroll
        for (int nf = 0; nf < 4; nf++) {
            const int c0 = bn + wn + nf * 8 + 2 * t4;
            const float2 bv = *(const float2*)(bias + c0);
            const size_t i0 = (size_t)r0 * N + c0;
            const size_t i1 = (size_t)(r0 + 8) * N + c0;
            *(float2*)(C + i0) = make_float2(acc[mf][nf][0] + bv.x, acc[mf][nf][1] + bv.y);
            *(float2*)(C + i1) = make_float2(acc[mf][nf][2] + bv.x, acc[mf][nf][3] + bv.y);
        }
    }
}

// ---------------- launch ----------------
extern "C" void kernel_launch(void* const* d_in, const int* in_sizes, int n_in,
                              void* d_out, int out_size) {
    const float* patches        = (const float*)d_in[0];
    const float* masked_token   = (const float*)d_in[3];
    const float* partial_params = (const float*)d_in[4];
    const float* emb_w          = (const float*)d_in[5];
    const float* emb_b          = (const float*)d_in[6];
    const float* ln1_g          = (const float*)d_in[7];
    const float* ln1_b          = (const float*)d_in[8];
    const float* in_proj_w      = (const float*)d_in[9];
    const float* in_proj_b      = (const float*)d_in[10];
    const float* out_proj_w     = (const float*)d_in[11];
    const float* out_proj_b     = (const float*)d_in[12];
    const float* rel_pos        = (const float*)d_in[13];
    const float* ln2_g          = (const float*)d_in[14];
    const float* ln2_b          = (const float*)d_in[15];
    const float* ffn_w1         = (const float*)d_in[16];
    const float* ffn_b1         = (const float*)d_in[17];
    const float* ffn_w2         = (const float*)d_in[18];
    const float* ffn_b2         = (const float*)d_in[19];
    const float* outp_w         = (const float*)d_in[20];
    const float* outp_b         = (const float*)d_in[21];
    float* out = (float*)d_out;

    float *x, *qkv;
    uint8_t *xn, *o, *h, *xf, *win, *wo, *w1, *w2, *wv;
    cudaGetSymbolAddress((void**)&x,   g_x);
    cudaGetSymbolAddress((void**)&qkv, g_qkv);
    cudaGetSymbolAddress((void**)&xn,  s_xn);
    cudaGetSymbolAddress((void**)&o,   s_o);
    cudaGetSymbolAddress((void**)&h,   s_h);
    cudaGetSymbolAddress((void**)&xf,  s_xf);
    cudaGetSymbolAddress((void**)&win, s_win);
    cudaGetSymbolAddress((void**)&wo,  s_wo);
    cudaGetSymbolAddress((void**)&w1,  s_w1);
    cudaGetSymbolAddress((void**)&w2,  s_w2);
    cudaGetSymbolAddress((void**)&wv,  s_wv);

    cudaFuncSetAttribute(attn_kernel, cudaFuncAttributeMaxDynamicSharedMemorySize, ATTN_SMEM);
    cudaFuncSetAttribute((const void*)gemm_2t<0>, cudaFuncAttributeMaxDynamicSharedMemorySize, 65536);
    cudaFuncSetAttribute((const void*)gemm_2t<1>, cudaFuncAttributeMaxDynamicSharedMemorySize, 65536);
    cudaFuncSetAttribute((const void*)gemm_2t<2>, cudaFuncAttributeMaxDynamicSharedMemorySize, 65536);
    cudaFuncSetAttribute((const void*)gemm_2t<3>, cudaFuncAttributeMaxDynamicSharedMemorySize, 65536);
    cudaFuncSetAttribute((const void*)gemm_h, cudaFuncAttributeMaxDynamicSharedMemorySize, 65536);

    // ---- convert all weights to fp16 single tiles ----
    {
        int nc;
        nc = NL * 3 * ND * ND / 8;  convert_w_h<<<(nc + 255) / 256, 256>>>(in_proj_w,  win, ND, nc);
        nc = NL * ND * ND / 8;      convert_w_h<<<(nc + 255) / 256, 256>>>(out_proj_w, wo,  ND, nc);
        nc = NL * NF * ND / 8;      convert_w_h<<<(nc + 255) / 256, 256>>>(ffn_w1,     w1,  ND, nc);
        nc = NL * ND * NF / 8;      convert_w_h<<<(nc + 255) / 256, 256>>>(ffn_w2,     w2,  NF, nc);
        nc = (int)((size_t)NV * ND / 8);
        convert_w_h<<<(nc + 255) / 256, 256>>>(outp_w, wv, ND, nc);
    }

    tokenize_embed_kernel<<<NTOK, 128>>>(patches, masked_token, partial_params, emb_w, emb_b);

    for (int l = 0; l < NL; l++) {
        ln_kernel<<<NTOK, 256>>>(x, xn, ln1_g + l * ND, ln1_b + l * ND);

        gemm_2t<0><<<dim3(NTOK / 64, 3 * ND / 128), 256, 65536>>>(
            xn, win + (size_t)l * 3 * ND * ND * 2, in_proj_b + l * 3 * ND,
            nullptr, qkv, NTOK, 3 * ND, ND);

        attn_kernel<<<NB * NH * 2, 512, ATTN_SMEM>>>(rel_pos + (size_t)l * NS * NS);

        gemm_2t<1><<<dim3(NTOK / 64, ND / 128), 256, 65536>>>(
            o, wo + (size_t)l * ND * ND * 2, out_proj_b + l * ND,
            x, x, NTOK, ND, ND);

        ln_kernel<<<NTOK, 256>>>(x, xn, ln2_g + l * ND, ln2_b + l * ND);

        gemm_2t<2><<<dim3(NTOK / 64, NF / 128), 256, 65536>>>(
            xn, w1 + (size_t)l * NF * ND * 2, ffn_b1 + l * NF,
            nullptr, h, NTOK, NF, ND);

        if (l < NL - 1) {
            gemm_2t<1><<<dim3(NTOK / 64, ND / 128), 256, 65536>>>(
                h, w2 + (size_t)l * ND * NF * 2, ffn_b2 + l * ND,
                x, x, NTOK, ND, NF);
        } else {
            gemm_2t<3><<<dim3(NTOK / 64, ND / 128), 256, 65536>>>(
                h, w2 + (size_t)l * ND * NF * 2, ffn_b2 + l * ND,
                x, xf, NTOK, ND, NF);
        }
    }

    gemm_h<<<dim3(NTOK / 128, NV / 128), 256, 65536>>>(
        xf, wv, outp_b, out, NTOK, NV, ND);
}